// round 4
// baseline (speedup 1.0000x reference)
#include <cuda_runtime.h>

#define CH 192
#define NB 8
#define HW 16384
#define KSPLIT 8
#define KCHUNK (HW / KSPLIT)
#define EPSN 1e-12f

// ---------------- scratch (static device memory; no allocations) ----------------
__device__ float g_Wq[CH*CH], g_Wk[CH*CH], g_Wv[CH*CH], g_Wp2[CH*CH], g_bp2[CH];
__device__ float g_Spart[NB*KSPLIT*CH*CH];
__device__ float g_S[NB*CH*CH], g_T1[NB*CH*CH], g_T2[NB*CH*CH];
__device__ float g_G[NB*CH*CH], g_attn[NB*CH*CH], g_A1[NB*CH*CH], g_A2[NB*CH*CH];
__device__ float g_nk2[NB*CH], g_nq2[NB*CH];

// ---------------- generic tiny 192x192 GEMM: C[b] = A (x) B ----------------
// aBatched/bBatched: operand has per-batch stride CH*CH. transB: C = A * B^T.
__global__ void gemm192(const float* __restrict__ A, const float* __restrict__ Bm,
                        float* __restrict__ Cm, int aBatched, int bBatched, int transB) {
    __shared__ float As[16][17], Bs[16][17];
    int b = blockIdx.y;
    const float* Ab = A  + (aBatched ? b*CH*CH : 0);
    const float* Bb = Bm + (bBatched ? b*CH*CH : 0);
    float* Cb = Cm + b*CH*CH;
    int tile = blockIdx.x;           // 0..143 (12x12 tiles of 16)
    int i0 = (tile / 12) * 16;
    int j0 = (tile % 12) * 16;
    int tx = threadIdx.x, ty = threadIdx.y;
    float acc = 0.f;
    if (transB) {
        for (int kk = 0; kk < CH; kk += 16) {
            As[ty][tx] = Ab[(i0+ty)*CH + kk + tx];
            Bs[ty][tx] = Bb[(j0+ty)*CH + kk + tx];
            __syncthreads();
            #pragma unroll
            for (int k = 0; k < 16; ++k) acc += As[ty][k] * Bs[tx][k];
            __syncthreads();
        }
    } else {
        for (int kk = 0; kk < CH; kk += 16) {
            As[ty][tx] = Ab[(i0+ty)*CH + kk + tx];
            Bs[ty][tx] = Bb[(kk+ty)*CH + j0 + tx];
            __syncthreads();
            #pragma unroll
            for (int k = 0; k < 16; ++k) acc += As[ty][k] * Bs[k][tx];
            __syncthreads();
        }
    }
    Cb[(i0+ty)*CH + j0 + tx] = acc;
}

// bp2[f] = sum_o w_out[f][o] * b_proj[o]
__global__ void bias_combine(const float* __restrict__ w_out, const float* __restrict__ b_proj) {
    int f = threadIdx.x;
    if (f < CH) {
        float s = 0.f;
        for (int o = 0; o < CH; ++o) s += w_out[f*CH+o] * b_proj[o];
        g_bp2[f] = s;
    }
}

// ---------------- S = X X^T (per batch), split-K partials (deterministic) ----------------
__global__ __launch_bounds__(256) void xxt_partial(const float* __restrict__ xin) {
    __shared__ float As[16][68], Bs[16][68];
    int bz = blockIdx.z;
    int b = bz / KSPLIT, p = bz % KSPLIT;
    const float* Xb = xin + (size_t)b * CH * HW;
    int i0 = blockIdx.x * 64, j0 = blockIdx.y * 64;
    int tid = threadIdx.x;
    int tx = tid & 15, ty = tid >> 4;
    int lr = tid >> 2;             // 0..63
    int lk = (tid & 3) * 4;        // 0,4,8,12
    int kstart = p * KCHUNK;
    float acc[4][4] = {};
    for (int kt = 0; kt < KCHUNK; kt += 16) {
        int kb = kstart + kt;
        float4 av = *(const float4*)&Xb[(size_t)(i0+lr)*HW + kb + lk];
        float4 bv = *(const float4*)&Xb[(size_t)(j0+lr)*HW + kb + lk];
        __syncthreads();
        As[lk+0][lr]=av.x; As[lk+1][lr]=av.y; As[lk+2][lr]=av.z; As[lk+3][lr]=av.w;
        Bs[lk+0][lr]=bv.x; Bs[lk+1][lr]=bv.y; Bs[lk+2][lr]=bv.z; Bs[lk+3][lr]=bv.w;
        __syncthreads();
        #pragma unroll
        for (int k = 0; k < 16; ++k) {
            float4 a4 = *(const float4*)&As[k][ty*4];
            float4 b4 = *(const float4*)&Bs[k][tx*4];
            float aa[4] = {a4.x,a4.y,a4.z,a4.w};
            float bb[4] = {b4.x,b4.y,b4.z,b4.w};
            #pragma unroll
            for (int ii = 0; ii < 4; ++ii)
                #pragma unroll
                for (int jj = 0; jj < 4; ++jj)
                    acc[ii][jj] += aa[ii]*bb[jj];
        }
    }
    float* outp = g_Spart + (size_t)(b*KSPLIT + p)*CH*CH;
    #pragma unroll
    for (int ii = 0; ii < 4; ++ii) {
        float4 o = {acc[ii][0], acc[ii][1], acc[ii][2], acc[ii][3]};
        *(float4*)&outp[(i0+ty*4+ii)*CH + j0 + tx*4] = o;
    }
}

__global__ void s_reduce() {
    int idx = blockIdx.x*256 + threadIdx.x;   // over NB*CH*CH = 294912
    if (idx < NB*CH*CH) {
        int b = idx / (CH*CH), e = idx % (CH*CH);
        float s = 0.f;
        #pragma unroll
        for (int p = 0; p < KSPLIT; ++p)
            s += g_Spart[(size_t)(b*KSPLIT+p)*CH*CH + e];
        g_S[idx] = s;
    }
}

// nq2[b][j] = diag(Wq' T1)_j ; nk2[b][i] = diag(Wk' T2)_i
__global__ void diag_norms() {
    int b = blockIdx.x, which = blockIdx.y;
    int j = threadIdx.x;
    if (j >= CH) return;
    const float* W = which ? g_Wk : g_Wq;
    const float* T = (which ? g_T2 : g_T1) + (size_t)b*CH*CH;
    float s = 0.f;
    for (int m = 0; m < CH; ++m) s += W[j*CH+m] * T[m*CH+j];
    (which ? g_nk2 : g_nq2)[b*CH+j] = s;
}

// attn[i][j] = softmax_j( G[i][j] / (max(||k_i||,eps)*max(||q_j||,eps)) )
__global__ void softmax_rows() {
    int b = blockIdx.y, i = blockIdx.x;
    int j = threadIdx.x;                  // 192 threads, 6 full warps
    const float* Grow = g_G + ((size_t)b*CH + i)*CH;
    float dk = fmaxf(sqrtf(g_nk2[b*CH+i]), EPSN);
    float dq = fmaxf(sqrtf(g_nq2[b*CH+j]), EPSN);
    float L = Grow[j] / (dk*dq);
    __shared__ float redm[6], reds[6];
    float m = L;
    #pragma unroll
    for (int o = 16; o > 0; o >>= 1) m = fmaxf(m, __shfl_xor_sync(0xffffffffu, m, o));
    if ((j & 31) == 0) redm[j>>5] = m;
    __syncthreads();
    float mx = fmaxf(fmaxf(fmaxf(redm[0],redm[1]),fmaxf(redm[2],redm[3])),fmaxf(redm[4],redm[5]));
    float e = expf(L - mx);
    float s = e;
    #pragma unroll
    for (int o = 16; o > 0; o >>= 1) s += __shfl_xor_sync(0xffffffffu, s, o);
    if ((j & 31) == 0) reds[j>>5] = s;
    __syncthreads();
    float sum = reds[0]+reds[1]+reds[2]+reds[3]+reds[4]+reds[5];
    g_attn[((size_t)b*CH + i)*CH + j] = e / sum;
}

// ---------------- out[b] = A2[b] @ X[b] + bp2 ----------------
__global__ __launch_bounds__(256) void final_gemm(const float* __restrict__ xin,
                                                  float* __restrict__ out) {
    __shared__ float As[16][68], Bs[16][68];
    int b = blockIdx.z;
    int m0 = blockIdx.x * 64;      // 3 tiles
    int n0 = blockIdx.y * 64;      // 256 tiles
    const float* Ab = g_A2 + (size_t)b*CH*CH;
    const float* Xb = xin + (size_t)b*CH*HW;
    int tid = threadIdx.x;
    int tx = tid & 15, ty = tid >> 4;
    int alr = tid >> 2, alk = (tid & 3)*4;
    int bkr = tid >> 4, bnq = (tid & 15)*4;
    float acc[4][4] = {};
    for (int k0 = 0; k0 < CH; k0 += 16) {
        float4 av = *(const float4*)&Ab[(m0+alr)*CH + k0 + alk];
        float4 bv = *(const float4*)&Xb[(size_t)(k0+bkr)*HW + n0 + bnq];
        __syncthreads();
        As[alk+0][alr]=av.x; As[alk+1][alr]=av.y; As[alk+2][alr]=av.z; As[alk+3][alr]=av.w;
        *(float4*)&Bs[bkr][bnq] = bv;
        __syncthreads();
        #pragma unroll
        for (int k = 0; k < 16; ++k) {
            float4 a4 = *(const float4*)&As[k][ty*4];
            float4 b4 = *(const float4*)&Bs[k][tx*4];
            float aa[4] = {a4.x,a4.y,a4.z,a4.w};
            float bb[4] = {b4.x,b4.y,b4.z,b4.w};
            #pragma unroll
            for (int ii = 0; ii < 4; ++ii)
                #pragma unroll
                for (int jj = 0; jj < 4; ++jj)
                    acc[ii][jj] += aa[ii]*bb[jj];
        }
    }
    #pragma unroll
    for (int ii = 0; ii < 4; ++ii) {
        int m = m0 + ty*4 + ii;
        float bias = g_bp2[m];
        float4 o = {acc[ii][0]+bias, acc[ii][1]+bias, acc[ii][2]+bias, acc[ii][3]+bias};
        *(float4*)&out[((size_t)b*CH + m)*HW + n0 + tx*4] = o;
    }
}

// ---------------- launch ----------------
extern "C" void kernel_launch(void* const* d_in, const int* in_sizes, int n_in,
                              void* d_out, int out_size) {
    const float* x_in   = (const float*)d_in[0];
    const float* w_split= (const float*)d_in[1];
    const float* w_q    = (const float*)d_in[2];
    const float* w_k    = (const float*)d_in[3];
    const float* w_v    = (const float*)d_in[4];
    const float* w_proj = (const float*)d_in[5];
    const float* b_proj = (const float*)d_in[6];
    const float* w_out  = (const float*)d_in[7];
    float* out = (float*)d_out;

    float *pWq, *pWk, *pWv, *pWp2, *pS, *pT1, *pT2, *pG, *pAttn, *pA1, *pA2;
    cudaGetSymbolAddress((void**)&pWq,  g_Wq);
    cudaGetSymbolAddress((void**)&pWk,  g_Wk);
    cudaGetSymbolAddress((void**)&pWv,  g_Wv);
    cudaGetSymbolAddress((void**)&pWp2, g_Wp2);
    cudaGetSymbolAddress((void**)&pS,   g_S);
    cudaGetSymbolAddress((void**)&pT1,  g_T1);
    cudaGetSymbolAddress((void**)&pT2,  g_T2);
    cudaGetSymbolAddress((void**)&pG,   g_G);
    cudaGetSymbolAddress((void**)&pAttn,g_attn);
    cudaGetSymbolAddress((void**)&pA1,  g_A1);
    cudaGetSymbolAddress((void**)&pA2,  g_A2);

    dim3 tb(16, 16);

    // combined channel maps (tiny)
    gemm192<<<dim3(144,1), tb>>>(w_q,  w_split, pWq,  0,0,0);
    gemm192<<<dim3(144,1), tb>>>(w_k,  w_split, pWk,  0,0,0);
    gemm192<<<dim3(144,1), tb>>>(w_v,  w_split, pWv,  0,0,0);
    gemm192<<<dim3(144,1), tb>>>(w_out,w_proj,  pWp2, 0,0,0);
    bias_combine<<<1, 192>>>(w_out, b_proj);

    // S = X X^T per batch (big GEMM #1)
    xxt_partial<<<dim3(3,3,NB*KSPLIT), 256>>>(x_in);
    s_reduce<<<(NB*CH*CH)/256, 256>>>();

    // Gram + norms in channel space
    gemm192<<<dim3(144,NB), tb>>>(pS,  pWq, pT1, 1,0,1);   // T1 = S Wq'^T
    gemm192<<<dim3(144,NB), tb>>>(pS,  pWk, pT2, 1,0,1);   // T2 = S Wk'^T
    diag_norms<<<dim3(NB,2), 192>>>();
    gemm192<<<dim3(144,NB), tb>>>(pWk, pT1, pG,  0,1,0);   // G = Wk' T1

    softmax_rows<<<dim3(CH,NB), 192>>>();

    gemm192<<<dim3(144,NB), tb>>>(pWp2, pAttn, pA1, 0,1,0); // A1 = Wp2 attn
    gemm192<<<dim3(144,NB), tb>>>(pA1,  pWv,   pA2, 1,0,0); // A2 = A1 Wv'

    // out = A2 X + bp2 (big GEMM #2)
    final_gemm<<<dim3(3,256,NB), 256>>>(x_in, out);
}

// round 5
// speedup vs baseline: 1.0888x; 1.0888x over previous
#include <cuda_runtime.h>

#define CH 192
#define NB 8
#define HW 16384
#define KSPLIT 8
#define KCHUNK (HW / KSPLIT)
#define EPSN 1e-12f

// ---------------- packed f32x2 helpers (FFMA2) ----------------
__device__ __forceinline__ unsigned long long pack2(float lo, float hi) {
    unsigned long long r;
    asm("mov.b64 %0, {%1, %2};" : "=l"(r) : "f"(lo), "f"(hi));
    return r;
}
__device__ __forceinline__ void unpack2(unsigned long long v, float& lo, float& hi) {
    asm("mov.b64 {%0, %1}, %2;" : "=f"(lo), "=f"(hi) : "l"(v));
}
__device__ __forceinline__ void fma2(unsigned long long& d, unsigned long long a, unsigned long long b) {
    asm("fma.rn.f32x2 %0, %1, %2, %0;" : "+l"(d) : "l"(a), "l"(b));
}

// ---------------- scratch (static device memory; no allocations) ----------------
__device__ float g_Wq[CH*CH], g_Wk[CH*CH], g_Wv[CH*CH], g_Wp2[CH*CH], g_bp2[CH];
__device__ float g_Spart[NB*KSPLIT*CH*CH];
__device__ float g_S[NB*CH*CH], g_T1[NB*CH*CH], g_T2[NB*CH*CH];
__device__ float g_G[NB*CH*CH], g_attn[NB*CH*CH], g_A1[NB*CH*CH], g_A2[NB*CH*CH];
__device__ float g_nk2[NB*CH], g_nq2[NB*CH];

// ---------------- small 192x192 GEMM core: 32x32 tile, 2x2/thread, FFMA2 ----------------
__device__ __forceinline__ void gemm_tile32(const float* __restrict__ Ab,
                                            const float* __restrict__ Bb,
                                            float* __restrict__ Cb,
                                            int transB, int i0, int j0) {
    __shared__ float As[16][34], Bs[16][34];
    int t = threadIdx.x;                  // 256 threads
    int tx = t & 15, ty = t >> 4;
    int li = t & 31, lkq = t >> 5;        // A (and transB B) load mapping
    int lkb = t >> 4, lj2 = (t & 15) * 2; // non-trans B load mapping

    unsigned long long acc0 = 0ull, acc1 = 0ull;

    for (int kk = 0; kk < CH; kk += 16) {
        float2 av = *(const float2*)&Ab[(i0 + li) * CH + kk + lkq * 2];
        float2 bv;
        if (transB) bv = *(const float2*)&Bb[(j0 + li) * CH + kk + lkq * 2];
        else        bv = *(const float2*)&Bb[(kk + lkb) * CH + j0 + lj2];
        __syncthreads();
        As[lkq*2 + 0][li] = av.x;
        As[lkq*2 + 1][li] = av.y;
        if (transB) { Bs[lkq*2 + 0][li] = bv.x; Bs[lkq*2 + 1][li] = bv.y; }
        else        { *(float2*)&Bs[lkb][lj2] = bv; }
        __syncthreads();
        #pragma unroll
        for (int k = 0; k < 16; ++k) {
            float2 a2 = *(const float2*)&As[k][ty * 2];
            unsigned long long b2 = *(const unsigned long long*)&Bs[k][tx * 2];
            fma2(acc0, pack2(a2.x, a2.x), b2);
            fma2(acc1, pack2(a2.y, a2.y), b2);
        }
    }
    float o00, o01, o10, o11;
    unpack2(acc0, o00, o01);
    unpack2(acc1, o10, o11);
    *(float2*)&Cb[(i0 + ty*2 + 0) * CH + j0 + tx*2] = make_float2(o00, o01);
    *(float2*)&Cb[(i0 + ty*2 + 1) * CH + j0 + tx*2] = make_float2(o10, o11);
}

// 4 independent weight-combine GEMMs in one launch (grid.z selects op)
__global__ __launch_bounds__(256) void prep_weights(const float* __restrict__ wq,
                                                    const float* __restrict__ wk,
                                                    const float* __restrict__ wv,
                                                    const float* __restrict__ wout,
                                                    const float* __restrict__ wsplit,
                                                    const float* __restrict__ wproj) {
    const float *A, *B; float* C;
    switch (blockIdx.z) {
        case 0:  A = wq;   B = wsplit; C = g_Wq;  break;
        case 1:  A = wk;   B = wsplit; C = g_Wk;  break;
        case 2:  A = wv;   B = wsplit; C = g_Wv;  break;
        default: A = wout; B = wproj;  C = g_Wp2; break;
    }
    gemm_tile32(A, B, C, 0, blockIdx.x * 32, blockIdx.y * 32);
}

// generic batched 192x192 GEMM
__global__ __launch_bounds__(256) void gemm192v2(const float* __restrict__ A,
                                                 const float* __restrict__ Bm,
                                                 float* __restrict__ Cm,
                                                 int aBatched, int bBatched, int transB) {
    int b = blockIdx.z;
    gemm_tile32(A + (aBatched ? b*CH*CH : 0),
                Bm + (bBatched ? b*CH*CH : 0),
                Cm + b*CH*CH, transB,
                blockIdx.x * 32, blockIdx.y * 32);
}

// bp2[f] = sum_o w_out[f][o] * b_proj[o]
__global__ void bias_combine(const float* __restrict__ w_out, const float* __restrict__ b_proj) {
    int f = threadIdx.x;
    if (f < CH) {
        float s = 0.f;
        for (int o = 0; o < CH; ++o) s += w_out[f*CH+o] * b_proj[o];
        g_bp2[f] = s;
    }
}

// ---------------- S = X X^T (per batch), split-K partials, FFMA2 inner loop ----------------
__global__ __launch_bounds__(256) void xxt_partial(const float* __restrict__ xin) {
    __shared__ float As[16][68], Bs[16][68];
    int bz = blockIdx.z;
    int b = bz / KSPLIT, p = bz % KSPLIT;
    const float* Xb = xin + (size_t)b * CH * HW;
    int i0 = blockIdx.x * 64, j0 = blockIdx.y * 64;
    int tid = threadIdx.x;
    int tx = tid & 15, ty = tid >> 4;
    int lr = tid >> 2;             // 0..63
    int lk = (tid & 3) * 4;        // 0,4,8,12
    int kstart = p * KCHUNK;
    unsigned long long acc01[4] = {0ull,0ull,0ull,0ull};
    unsigned long long acc23[4] = {0ull,0ull,0ull,0ull};
    for (int kt = 0; kt < KCHUNK; kt += 16) {
        int kb = kstart + kt;
        float4 av = *(const float4*)&Xb[(size_t)(i0+lr)*HW + kb + lk];
        float4 bv = *(const float4*)&Xb[(size_t)(j0+lr)*HW + kb + lk];
        __syncthreads();
        As[lk+0][lr]=av.x; As[lk+1][lr]=av.y; As[lk+2][lr]=av.z; As[lk+3][lr]=av.w;
        Bs[lk+0][lr]=bv.x; Bs[lk+1][lr]=bv.y; Bs[lk+2][lr]=bv.z; Bs[lk+3][lr]=bv.w;
        __syncthreads();
        #pragma unroll
        for (int k = 0; k < 16; ++k) {
            float4 a4 = *(const float4*)&As[k][ty*4];
            ulonglong2 bb = *(const ulonglong2*)&Bs[k][tx*4];
            fma2(acc01[0], pack2(a4.x, a4.x), bb.x);
            fma2(acc23[0], pack2(a4.x, a4.x), bb.y);
            fma2(acc01[1], pack2(a4.y, a4.y), bb.x);
            fma2(acc23[1], pack2(a4.y, a4.y), bb.y);
            fma2(acc01[2], pack2(a4.z, a4.z), bb.x);
            fma2(acc23[2], pack2(a4.z, a4.z), bb.y);
            fma2(acc01[3], pack2(a4.w, a4.w), bb.x);
            fma2(acc23[3], pack2(a4.w, a4.w), bb.y);
        }
    }
    float* outp = g_Spart + (size_t)(b*KSPLIT + p)*CH*CH;
    #pragma unroll
    for (int ii = 0; ii < 4; ++ii) {
        float4 o;
        unpack2(acc01[ii], o.x, o.y);
        unpack2(acc23[ii], o.z, o.w);
        *(float4*)&outp[(i0+ty*4+ii)*CH + j0 + tx*4] = o;
    }
}

__global__ void s_reduce() {
    int idx = blockIdx.x*256 + threadIdx.x;   // over NB*CH*CH = 294912
    if (idx < NB*CH*CH) {
        int b = idx / (CH*CH), e = idx % (CH*CH);
        float s = 0.f;
        #pragma unroll
        for (int p = 0; p < KSPLIT; ++p)
            s += g_Spart[(size_t)(b*KSPLIT+p)*CH*CH + e];
        g_S[idx] = s;
    }
}

// nq2[b][j] = diag(Wq' T1)_j ; nk2[b][i] = diag(Wk' T2)_i
__global__ void diag_norms() {
    int b = blockIdx.x, which = blockIdx.y;
    int j = threadIdx.x;
    if (j >= CH) return;
    const float* W = which ? g_Wk : g_Wq;
    const float* T = (which ? g_T2 : g_T1) + (size_t)b*CH*CH;
    float s = 0.f;
    for (int m = 0; m < CH; ++m) s += W[j*CH+m] * T[m*CH+j];
    (which ? g_nk2 : g_nq2)[b*CH+j] = s;
}

// attn[i][j] = softmax_j( G[i][j] / (max(||k_i||,eps)*max(||q_j||,eps)) )
__global__ void softmax_rows() {
    int b = blockIdx.y, i = blockIdx.x;
    int j = threadIdx.x;                  // 192 threads, 6 full warps
    const float* Grow = g_G + ((size_t)b*CH + i)*CH;
    float dk = fmaxf(sqrtf(g_nk2[b*CH+i]), EPSN);
    float dq = fmaxf(sqrtf(g_nq2[b*CH+j]), EPSN);
    float L = Grow[j] / (dk*dq);
    __shared__ float redm[6], reds[6];
    float m = L;
    #pragma unroll
    for (int o = 16; o > 0; o >>= 1) m = fmaxf(m, __shfl_xor_sync(0xffffffffu, m, o));
    if ((j & 31) == 0) redm[j>>5] = m;
    __syncthreads();
    float mx = fmaxf(fmaxf(fmaxf(redm[0],redm[1]),fmaxf(redm[2],redm[3])),fmaxf(redm[4],redm[5]));
    float e = expf(L - mx);
    float s = e;
    #pragma unroll
    for (int o = 16; o > 0; o >>= 1) s += __shfl_xor_sync(0xffffffffu, s, o);
    if ((j & 31) == 0) reds[j>>5] = s;
    __syncthreads();
    float sum = reds[0]+reds[1]+reds[2]+reds[3]+reds[4]+reds[5];
    g_attn[((size_t)b*CH + i)*CH + j] = e / sum;
}

// ---------------- out[b] = A2[b] @ X[b] + bp2, FFMA2 inner loop ----------------
__global__ __launch_bounds__(256) void final_gemm(const float* __restrict__ xin,
                                                  float* __restrict__ out) {
    __shared__ float As[16][68], Bs[16][68];
    int b = blockIdx.z;
    int m0 = blockIdx.x * 64;      // 3 tiles
    int n0 = blockIdx.y * 64;      // 256 tiles
    const float* Ab = g_A2 + (size_t)b*CH*CH;
    const float* Xb = xin + (size_t)b*CH*HW;
    int tid = threadIdx.x;
    int tx = tid & 15, ty = tid >> 4;
    int alr = tid >> 2, alk = (tid & 3)*4;
    int bkr = tid >> 4, bnq = (tid & 15)*4;
    unsigned long long acc01[4] = {0ull,0ull,0ull,0ull};
    unsigned long long acc23[4] = {0ull,0ull,0ull,0ull};
    for (int k0 = 0; k0 < CH; k0 += 16) {
        float4 av = *(const float4*)&Ab[(m0+alr)*CH + k0 + alk];
        float4 bv = *(const float4*)&Xb[(size_t)(k0+bkr)*HW + n0 + bnq];
        __syncthreads();
        As[alk+0][alr]=av.x; As[alk+1][alr]=av.y; As[alk+2][alr]=av.z; As[alk+3][alr]=av.w;
        *(float4*)&Bs[bkr][bnq] = bv;
        __syncthreads();
        #pragma unroll
        for (int k = 0; k < 16; ++k) {
            float4 a4 = *(const float4*)&As[k][ty*4];
            ulonglong2 bb = *(const ulonglong2*)&Bs[k][tx*4];
            fma2(acc01[0], pack2(a4.x, a4.x), bb.x);
            fma2(acc23[0], pack2(a4.x, a4.x), bb.y);
            fma2(acc01[1], pack2(a4.y, a4.y), bb.x);
            fma2(acc23[1], pack2(a4.y, a4.y), bb.y);
            fma2(acc01[2], pack2(a4.z, a4.z), bb.x);
            fma2(acc23[2], pack2(a4.z, a4.z), bb.y);
            fma2(acc01[3], pack2(a4.w, a4.w), bb.x);
            fma2(acc23[3], pack2(a4.w, a4.w), bb.y);
        }
    }
    #pragma unroll
    for (int ii = 0; ii < 4; ++ii) {
        int m = m0 + ty*4 + ii;
        float bias = g_bp2[m];
        float4 o;
        unpack2(acc01[ii], o.x, o.y);
        unpack2(acc23[ii], o.z, o.w);
        o.x += bias; o.y += bias; o.z += bias; o.w += bias;
        *(float4*)&out[((size_t)b*CH + m)*HW + n0 + tx*4] = o;
    }
}

// ---------------- launch ----------------
extern "C" void kernel_launch(void* const* d_in, const int* in_sizes, int n_in,
                              void* d_out, int out_size) {
    const float* x_in   = (const float*)d_in[0];
    const float* w_split= (const float*)d_in[1];
    const float* w_q    = (const float*)d_in[2];
    const float* w_k    = (const float*)d_in[3];
    const float* w_v    = (const float*)d_in[4];
    const float* w_proj = (const float*)d_in[5];
    const float* b_proj = (const float*)d_in[6];
    const float* w_out  = (const float*)d_in[7];
    float* out = (float*)d_out;

    float *pWq, *pWk, *pWv, *pWp2, *pS, *pT1, *pT2, *pG, *pAttn, *pA1, *pA2;
    cudaGetSymbolAddress((void**)&pWq,  g_Wq);
    cudaGetSymbolAddress((void**)&pWk,  g_Wk);
    cudaGetSymbolAddress((void**)&pWv,  g_Wv);
    cudaGetSymbolAddress((void**)&pWp2, g_Wp2);
    cudaGetSymbolAddress((void**)&pS,   g_S);
    cudaGetSymbolAddress((void**)&pT1,  g_T1);
    cudaGetSymbolAddress((void**)&pT2,  g_T2);
    cudaGetSymbolAddress((void**)&pG,   g_G);
    cudaGetSymbolAddress((void**)&pAttn,g_attn);
    cudaGetSymbolAddress((void**)&pA1,  g_A1);
    cudaGetSymbolAddress((void**)&pA2,  g_A2);

    // combined channel maps (tiny) — 4 GEMMs in one launch
    prep_weights<<<dim3(6,6,4), 256>>>(w_q, w_k, w_v, w_out, w_split, w_proj);
    bias_combine<<<1, 192>>>(w_out, b_proj);

    // S = X X^T per batch (big GEMM #1)
    xxt_partial<<<dim3(3,3,NB*KSPLIT), 256>>>(x_in);
    s_reduce<<<(NB*CH*CH)/256, 256>>>();

    // Gram + norms in channel space
    gemm192v2<<<dim3(6,6,NB), 256>>>(pS,  pWq, pT1, 1,0,1);   // T1 = S Wq'^T
    gemm192v2<<<dim3(6,6,NB), 256>>>(pS,  pWk, pT2, 1,0,1);   // T2 = S Wk'^T
    diag_norms<<<dim3(NB,2), 192>>>();
    gemm192v2<<<dim3(6,6,NB), 256>>>(pWk, pT1, pG,  0,1,0);   // G = Wk' T1

    softmax_rows<<<dim3(CH,NB), 192>>>();

    gemm192v2<<<dim3(6,6,NB), 256>>>(pWp2, pAttn, pA1, 0,1,0); // A1 = Wp2 attn
    gemm192v2<<<dim3(6,6,NB), 256>>>(pA1,  pWv,   pA2, 1,0,0); // A2 = A1 Wv'

    // out = A2 X + bp2 (big GEMM #2)
    final_gemm<<<dim3(3,256,NB), 256>>>(x_in, out);
}

// round 8
// speedup vs baseline: 2.1232x; 1.9501x over previous
#include <cuda_runtime.h>
#include <cuda_bf16.h>
#include <cstdint>

#define CH 192
#define NB 8
#define HW 16384
#define KSPLIT1 16
#define EPSN 1e-12f

// ---------------- mma.sync / ldmatrix helpers (sm_80+ baseline PTX) ----------------
__device__ __forceinline__ uint32_t smem_u32(const void* p) {
    uint32_t a;
    asm("{ .reg .u64 t; cvta.to.shared.u64 t, %1; cvt.u32.u64 %0, t; }" : "=r"(a) : "l"(p));
    return a;
}
__device__ __forceinline__ void hmma(float* d, const uint32_t* a, const uint32_t* b) {
    asm volatile("mma.sync.aligned.m16n8k16.row.col.f32.bf16.bf16.f32 "
        "{%0,%1,%2,%3}, {%4,%5,%6,%7}, {%8,%9}, {%0,%1,%2,%3};"
        : "+f"(d[0]), "+f"(d[1]), "+f"(d[2]), "+f"(d[3])
        : "r"(a[0]), "r"(a[1]), "r"(a[2]), "r"(a[3]), "r"(b[0]), "r"(b[1]));
}
__device__ __forceinline__ void ldsm4(uint32_t* r, uint32_t a) {
    asm volatile("ldmatrix.sync.aligned.m8n8.x4.shared.b16 {%0,%1,%2,%3}, [%4];"
        : "=r"(r[0]), "=r"(r[1]), "=r"(r[2]), "=r"(r[3]) : "r"(a));
}
__device__ __forceinline__ void ldsm4t(uint32_t* r, uint32_t a) {
    asm volatile("ldmatrix.sync.aligned.m8n8.x4.trans.shared.b16 {%0,%1,%2,%3}, [%4];"
        : "=r"(r[0]), "=r"(r[1]), "=r"(r[2]), "=r"(r[3]) : "r"(a));
}
// fp32 pair -> bf16 hi pair + bf16 lo pair (packed b32 each)
__device__ __forceinline__ void split2(float x, float y, uint32_t& h, uint32_t& l) {
    __nv_bfloat162 hb = __floats2bfloat162_rn(x, y);
    float2 hf = __bfloat1622float2(hb);
    __nv_bfloat162 lb = __floats2bfloat162_rn(x - hf.x, y - hf.y);
    h = *reinterpret_cast<uint32_t*>(&hb);
    l = *reinterpret_cast<uint32_t*>(&lb);
}

// ---------------- packed f32x2 helpers (small GEMMs) ----------------
__device__ __forceinline__ unsigned long long pack2(float lo, float hi) {
    unsigned long long r;
    asm("mov.b64 %0, {%1, %2};" : "=l"(r) : "f"(lo), "f"(hi));
    return r;
}
__device__ __forceinline__ void unpack2(unsigned long long v, float& lo, float& hi) {
    asm("mov.b64 {%0, %1}, %2;" : "=f"(lo), "=f"(hi) : "l"(v));
}
__device__ __forceinline__ void fma2(unsigned long long& d, unsigned long long a, unsigned long long b) {
    asm("fma.rn.f32x2 %0, %1, %2, %0;" : "+l"(d) : "l"(a), "l"(b));
}

// ---------------- scratch ----------------
__device__ float g_Wq[CH*CH], g_Wk[CH*CH], g_Wv[CH*CH], g_Wp2[CH*CH], g_bp2[CH];
__device__ float g_Spart[NB*KSPLIT1*CH*CH];
__device__ float g_S[NB*CH*CH], g_T1[NB*CH*CH], g_T2[NB*CH*CH];
__device__ float g_G[NB*CH*CH], g_attn[NB*CH*CH], g_A1[NB*CH*CH], g_A2[NB*CH*CH];
__device__ float g_nk2[NB*CH], g_nq2[NB*CH];

// ============ GEMM1: S[b] = X X^T (split-K) via mma.sync bf16 hi/lo split ============
// grid (KSPLIT1, NB), 256 thr, dyn smem 98304 (2 stages x [XH 192x64 | XL 192x64] bf16)
__global__ __launch_bounds__(256) void xxt_mma(const float* __restrict__ xin) {
    extern __shared__ char smem[];
    const int tid = threadIdx.x, wid = tid >> 5, lane = tid & 31;
    const int split = blockIdx.x, b = blockIdx.y;
    const float* Xb = xin + (size_t)b * CH * HW;
    const int kbase = split * (HW / KSPLIT1);
    const uint32_t sb = smem_u32(smem);
    const int m0 = (wid >> 2) * 96, n0 = (wid & 3) * 48;

    float d[6][6][4];
    #pragma unroll
    for (int i = 0; i < 6; ++i)
        #pragma unroll
        for (int j = 0; j < 6; ++j)
            #pragma unroll
            for (int q = 0; q < 4; ++q) d[i][j][q] = 0.f;

    auto stage_load = [&](int buf, int kb) {
        char* XH = smem + buf * 49152;
        char* XL = XH + 24576;
        #pragma unroll
        for (int u = tid; u < 3072; u += 256) {
            int r = u >> 4, k4 = (u & 15) << 2;
            float4 v = *(const float4*)&Xb[(size_t)r * HW + kb + k4];
            uint32_t h0, l0, h1, l1;
            split2(v.x, v.y, h0, l0);
            split2(v.z, v.w, h1, l1);
            int sw = r * 128 + (((u & 15) << 3) ^ ((r & 7) << 4));
            *(uint2*)(XH + sw) = make_uint2(h0, h1);
            *(uint2*)(XL + sw) = make_uint2(l0, l1);
        }
    };

    const int xorv = (lane & 7) << 4;
    const int mat = lane >> 3;
    const int halfA = (lane >> 4) << 4;
    const int halfB = (mat & 1) << 4;
    const int rA15 = lane & 15;
    const int rB = ((mat >> 1) << 3) + (lane & 7);

    auto stage_compute = [&](int buf) {
        uint32_t baseH = sb + buf * 49152;
        uint32_t baseL = baseH + 24576;
        #pragma unroll 1
        for (int kk = 0; kk < 4; ++kk) {
            int colA = ((kk << 5) + halfA) ^ xorv;
            int colB = ((kk << 5) + halfB) ^ xorv;
            uint32_t ah[6][4], bh[3][4];
            #pragma unroll
            for (int i = 0; i < 6; ++i)
                ldsm4(ah[i], baseH + (m0 + 16*i + rA15) * 128 + colA);
            #pragma unroll
            for (int jj = 0; jj < 3; ++jj)
                ldsm4(bh[jj], baseH + (n0 + jj*16 + rB) * 128 + colB);
            #pragma unroll
            for (int i = 0; i < 6; ++i)
                #pragma unroll
                for (int jj = 0; jj < 3; ++jj) {
                    hmma(d[i][2*jj],     ah[i], &bh[jj][0]);
                    hmma(d[i][2*jj + 1], ah[i], &bh[jj][2]);
                }
            uint32_t bl[3][4];
            #pragma unroll
            for (int jj = 0; jj < 3; ++jj)
                ldsm4(bl[jj], baseL + (n0 + jj*16 + rB) * 128 + colB);
            #pragma unroll
            for (int i = 0; i < 6; ++i)
                #pragma unroll
                for (int jj = 0; jj < 3; ++jj) {
                    hmma(d[i][2*jj],     ah[i], &bl[jj][0]);
                    hmma(d[i][2*jj + 1], ah[i], &bl[jj][2]);
                }
            uint32_t al[6][4];
            #pragma unroll
            for (int i = 0; i < 6; ++i)
                ldsm4(al[i], baseL + (m0 + 16*i + rA15) * 128 + colA);
            #pragma unroll
            for (int i = 0; i < 6; ++i)
                #pragma unroll
                for (int jj = 0; jj < 3; ++jj) {
                    hmma(d[i][2*jj],     al[i], &bh[jj][0]);
                    hmma(d[i][2*jj + 1], al[i], &bh[jj][2]);
                }
        }
    };

    stage_load(0, kbase);
    __syncthreads();
    for (int c = 0; c < 16; ++c) {
        if (c < 15) stage_load((c + 1) & 1, kbase + (c + 1) * 64);
        stage_compute(c & 1);
        __syncthreads();
    }

    float* Sp = g_Spart + (size_t)(b * KSPLIT1 + split) * CH * CH;
    int lr = lane >> 2, lc2 = (lane & 3) * 2;
    #pragma unroll
    for (int mi = 0; mi < 6; ++mi)
        #pragma unroll
        for (int nj = 0; nj < 6; ++nj) {
            int r = m0 + 16*mi + lr, cc = n0 + 8*nj + lc2;
            *(float2*)&Sp[r * CH + cc]       = make_float2(d[mi][nj][0], d[mi][nj][1]);
            *(float2*)&Sp[(r + 8) * CH + cc] = make_float2(d[mi][nj][2], d[mi][nj][3]);
        }
}

__global__ void s_reduce() {
    int idx = blockIdx.x * 256 + threadIdx.x;
    if (idx < NB*CH*CH) {
        int b = idx / (CH*CH), e = idx % (CH*CH);
        float s = 0.f;
        #pragma unroll
        for (int p = 0; p < KSPLIT1; ++p)
            s += g_Spart[(size_t)(b*KSPLIT1 + p)*CH*CH + e];
        g_S[idx] = s;
    }
}

// ============ GEMM2: out[b] = A2 X + bp2 via mma.sync (out-ch x pixels) ============
// grid (HW/128, NB), 256 thr, dyn smem 163840
// stage: A2H 192x64 (24576) | A2L (24576) | XH 64x128 (16384) | XL (16384) = 81920
__global__ __launch_bounds__(256) void out_mma(const float* __restrict__ xin,
                                               float* __restrict__ out) {
    extern __shared__ char smem[];
    const int tid = threadIdx.x, wid = tid >> 5, lane = tid & 31;
    const int p0 = blockIdx.x * 128, b = blockIdx.y;
    const float* Xb = xin + (size_t)b * CH * HW;
    const float* A2b = g_A2 + (size_t)b * CH * CH;
    const uint32_t sb = smem_u32(smem);
    const int m0 = (wid >> 1) * 48, n0p = (wid & 1) * 64;

    float d[3][8][4];
    #pragma unroll
    for (int i = 0; i < 3; ++i)
        #pragma unroll
        for (int j = 0; j < 8; ++j)
            #pragma unroll
            for (int q = 0; q < 4; ++q) d[i][j][q] = 0.f;

    auto stage_load = [&](int buf, int c0) {
        char* base = smem + buf * 81920;
        char* A2H = base;
        char* A2L = base + 24576;
        char* XH  = base + 49152;
        char* XL  = base + 65536;
        #pragma unroll
        for (int u = tid; u < 3072; u += 256) {   // A2: 192 co x 64 c
            int r = u >> 4, c4 = (u & 15) << 2;
            float4 v = *(const float4*)&A2b[r * CH + c0 + c4];
            uint32_t h0, l0, h1, l1;
            split2(v.x, v.y, h0, l0);
            split2(v.z, v.w, h1, l1);
            int sw = r * 128 + (((u & 15) << 3) ^ ((r & 7) << 4));
            *(uint2*)(A2H + sw) = make_uint2(h0, h1);
            *(uint2*)(A2L + sw) = make_uint2(l0, l1);
        }
        #pragma unroll
        for (int u = tid; u < 2048; u += 256) {   // X: 64 c x 128 p
            int r = u >> 5, p4 = (u & 31) << 2;
            float4 v = *(const float4*)&Xb[(size_t)(c0 + r) * HW + p0 + p4];
            uint32_t h0, l0, h1, l1;
            split2(v.x, v.y, h0, l0);
            split2(v.z, v.w, h1, l1);
            int sw = r * 256 + (((u & 31) << 3) ^ ((r & 7) << 4));
            *(uint2*)(XH + sw) = make_uint2(h0, h1);
            *(uint2*)(XL + sw) = make_uint2(l0, l1);
        }
    };

    const int xorv = (lane & 7) << 4;
    const int mat = lane >> 3;
    const int halfA = (lane >> 4) << 4;
    const int rA15 = lane & 15;
    const int rbX = ((mat & 1) << 3) + (lane & 7);     // X k-row within k16
    const int cbX = (n0p + ((mat >> 1) << 3)) * 2;     // X n-col bytes (+ jj*32)

    auto stage_compute = [&](int buf) {
        uint32_t baseAH = sb + buf * 81920;
        uint32_t baseAL = baseAH + 24576;
        uint32_t baseXH = baseAH + 49152;
        uint32_t baseXL = baseAH + 65536;
        #pragma unroll 1
        for (int kk = 0; kk < 4; ++kk) {
            int colA = ((kk << 5) + halfA) ^ xorv;
            int xrow = (kk * 16 + rbX) * 256;
            uint32_t ah[3][4], bt[4][4];
            #pragma unroll
            for (int mi = 0; mi < 3; ++mi)
                ldsm4(ah[mi], baseAH + (m0 + 16*mi + rA15) * 128 + colA);
            #pragma unroll
            for (int jj = 0; jj < 4; ++jj)
                ldsm4t(bt[jj], baseXH + xrow + ((cbX + jj*32) ^ xorv));
            #pragma unroll
            for (int mi = 0; mi < 3; ++mi)
                #pragma unroll
                for (int jj = 0; jj < 4; ++jj) {
                    hmma(d[mi][2*jj],     ah[mi], &bt[jj][0]);
                    hmma(d[mi][2*jj + 1], ah[mi], &bt[jj][2]);
                }
            uint32_t btl[4][4];
            #pragma unroll
            for (int jj = 0; jj < 4; ++jj)
                ldsm4t(btl[jj], baseXL + xrow + ((cbX + jj*32) ^ xorv));
            #pragma unroll
            for (int mi = 0; mi < 3; ++mi)
                #pragma unroll
                for (int jj = 0; jj < 4; ++jj) {
                    hmma(d[mi][2*jj],     ah[mi], &btl[jj][0]);
                    hmma(d[mi][2*jj + 1], ah[mi], &btl[jj][2]);
                }
            uint32_t al[3][4];
            #pragma unroll
            for (int mi = 0; mi < 3; ++mi)
                ldsm4(al[mi], baseAL + (m0 + 16*mi + rA15) * 128 + colA);
            #pragma unroll
            for (int mi = 0; mi < 3; ++mi)
                #pragma unroll
                for (int jj = 0; jj < 4; ++jj) {
                    hmma(d[mi][2*jj],     al[mi], &bt[jj][0]);
                    hmma(d[mi][2*jj + 1], al[mi], &bt[jj][2]);
                }
        }
    };

    stage_load(0, 0);
    __syncthreads();
    for (int c = 0; c < 3; ++c) {
        if (c < 2) stage_load((c + 1) & 1, (c + 1) * 64);
        stage_compute(c & 1);
        __syncthreads();
    }

    // stage output through smem (reuse buffers) for coalesced stores
    float* so = (float*)smem;   // 192 x 132 floats = 101376 B
    int lr = lane >> 2, lc2 = (lane & 3) * 2;
    #pragma unroll
    for (int mi = 0; mi < 3; ++mi)
        #pragma unroll
        for (int nj = 0; nj < 8; ++nj) {
            int r = m0 + 16*mi + lr, cc = n0p + 8*nj + lc2;
            *(float2*)&so[r * 132 + cc]       = make_float2(d[mi][nj][0], d[mi][nj][1]);
            *(float2*)&so[(r + 8) * 132 + cc] = make_float2(d[mi][nj][2], d[mi][nj][3]);
        }
    __syncthreads();
    #pragma unroll
    for (int u = tid; u < 6144; u += 256) {
        int co = u >> 5, p4 = (u & 31) << 2;
        float4 v = *(const float4*)&so[co * 132 + p4];
        float bias = g_bp2[co];
        v.x += bias; v.y += bias; v.z += bias; v.w += bias;
        *(float4*)&out[((size_t)b * CH + co) * HW + p0 + p4] = v;
    }
}

// ---------------- small 192x192 GEMM core: 32x32 tile, 2x2/thread, FFMA2 ----------------
__device__ __forceinline__ void gemm_tile32(const float* __restrict__ Ab,
                                            const float* __restrict__ Bb,
                                            float* __restrict__ Cb,
                                            int transB, int i0, int j0) {
    __shared__ float As[16][34], Bs[16][34];
    int t = threadIdx.x;
    int tx = t & 15, ty = t >> 4;
    int li = t & 31, lkq = t >> 5;
    int lkb = t >> 4, lj2 = (t & 15) * 2;

    unsigned long long acc0 = 0ull, acc1 = 0ull;

    for (int kk = 0; kk < CH; kk += 16) {
        float2 av = *(const float2*)&Ab[(i0 + li) * CH + kk + lkq * 2];
        float2 bv;
        if (transB) bv = *(const float2*)&Bb[(j0 + li) * CH + kk + lkq * 2];
        else        bv = *(const float2*)&Bb[(kk + lkb) * CH + j0 + lj2];
        __syncthreads();
        As[lkq*2 + 0][li] = av.x;
        As[lkq*2 + 1][li] = av.y;
        if (transB) { Bs[lkq*2 + 0][li] = bv.x; Bs[lkq*2 + 1][li] = bv.y; }
        else        { *(float2*)&Bs[lkb][lj2] = bv; }
        __syncthreads();
        #pragma unroll
        for (int k = 0; k < 16; ++k) {
            float2 a2 = *(const float2*)&As[k][ty * 2];
            unsigned long long b2 = *(const unsigned long long*)&Bs[k][tx * 2];
            fma2(acc0, pack2(a2.x, a2.x), b2);
            fma2(acc1, pack2(a2.y, a2.y), b2);
        }
    }
    float o00, o01, o10, o11;
    unpack2(acc0, o00, o01);
    unpack2(acc1, o10, o11);
    *(float2*)&Cb[(i0 + ty*2 + 0) * CH + j0 + tx*2] = make_float2(o00, o01);
    *(float2*)&Cb[(i0 + ty*2 + 1) * CH + j0 + tx*2] = make_float2(o10, o11);
}

__global__ __launch_bounds__(256) void prep_weights(const float* __restrict__ wq,
                                                    const float* __restrict__ wk,
                                                    const float* __restrict__ wv,
                                                    const float* __restrict__ wout,
                                                    const float* __restrict__ wsplit,
                                                    const float* __restrict__ wproj) {
    const float *A, *B; float* C;
    switch (blockIdx.z) {
        case 0:  A = wq;   B = wsplit; C = g_Wq;  break;
        case 1:  A = wk;   B = wsplit; C = g_Wk;  break;
        case 2:  A = wv;   B = wsplit; C = g_Wv;  break;
        default: A = wout; B = wproj;  C = g_Wp2; break;
    }
    gemm_tile32(A, B, C, 0, blockIdx.x * 32, blockIdx.y * 32);
}

__global__ __launch_bounds__(256) void gemm192v2(const float* __restrict__ A,
                                                 const float* __restrict__ Bm,
                                                 float* __restrict__ Cm,
                                                 int aBatched, int bBatched, int transB) {
    int b = blockIdx.z;
    gemm_tile32(A + (aBatched ? b*CH*CH : 0),
                Bm + (bBatched ? b*CH*CH : 0),
                Cm + b*CH*CH, transB,
                blockIdx.x * 32, blockIdx.y * 32);
}

__global__ void bias_combine(const float* __restrict__ w_out, const float* __restrict__ b_proj) {
    int f = threadIdx.x;
    if (f < CH) {
        float s = 0.f;
        for (int o = 0; o < CH; ++o) s += w_out[f*CH+o] * b_proj[o];
        g_bp2[f] = s;
    }
}

__global__ void diag_norms() {
    int b = blockIdx.x, which = blockIdx.y;
    int j = threadIdx.x;
    if (j >= CH) return;
    const float* W = which ? g_Wk : g_Wq;
    const float* T = (which ? g_T2 : g_T1) + (size_t)b*CH*CH;
    float s = 0.f;
    for (int m = 0; m < CH; ++m) s += W[j*CH+m] * T[m*CH+j];
    (which ? g_nk2 : g_nq2)[b*CH+j] = s;
}

__global__ void softmax_rows() {
    int b = blockIdx.y, i = blockIdx.x;
    int j = threadIdx.x;
    const float* Grow = g_G + ((size_t)b*CH + i)*CH;
    float dk = fmaxf(sqrtf(g_nk2[b*CH+i]), EPSN);
    float dq = fmaxf(sqrtf(g_nq2[b*CH+j]), EPSN);
    float L = Grow[j] / (dk*dq);
    __shared__ float redm[6], reds[6];
    float m = L;
    #pragma unroll
    for (int o = 16; o > 0; o >>= 1) m = fmaxf(m, __shfl_xor_sync(0xffffffffu, m, o));
    if ((j & 31) == 0) redm[j>>5] = m;
    __syncthreads();
    float mx = fmaxf(fmaxf(fmaxf(redm[0],redm[1]),fmaxf(redm[2],redm[3])),fmaxf(redm[4],redm[5]));
    float e = expf(L - mx);
    float s = e;
    #pragma unroll
    for (int o = 16; o > 0; o >>= 1) s += __shfl_xor_sync(0xffffffffu, s, o);
    if ((j & 31) == 0) reds[j>>5] = s;
    __syncthreads();
    float sum = reds[0]+reds[1]+reds[2]+reds[3]+reds[4]+reds[5];
    g_attn[((size_t)b*CH + i)*CH + j] = e / sum;
}

// ---------------- launch ----------------
extern "C" void kernel_launch(void* const* d_in, const int* in_sizes, int n_in,
                              void* d_out, int out_size) {
    const float* x_in   = (const float*)d_in[0];
    const float* w_split= (const float*)d_in[1];
    const float* w_q    = (const float*)d_in[2];
    const float* w_k    = (const float*)d_in[3];
    const float* w_v    = (const float*)d_in[4];
    const float* w_proj = (const float*)d_in[5];
    const float* b_proj = (const float*)d_in[6];
    const float* w_out  = (const float*)d_in[7];
    float* out = (float*)d_out;

    float *pWq, *pWk, *pWv, *pWp2, *pS, *pT1, *pT2, *pG, *pAttn, *pA1, *pA2;
    cudaGetSymbolAddress((void**)&pWq,  g_Wq);
    cudaGetSymbolAddress((void**)&pWk,  g_Wk);
    cudaGetSymbolAddress((void**)&pWv,  g_Wv);
    cudaGetSymbolAddress((void**)&pWp2, g_Wp2);
    cudaGetSymbolAddress((void**)&pS,   g_S);
    cudaGetSymbolAddress((void**)&pT1,  g_T1);
    cudaGetSymbolAddress((void**)&pT2,  g_T2);
    cudaGetSymbolAddress((void**)&pG,   g_G);
    cudaGetSymbolAddress((void**)&pAttn,g_attn);
    cudaGetSymbolAddress((void**)&pA1,  g_A1);
    cudaGetSymbolAddress((void**)&pA2,  g_A2);

    cudaFuncSetAttribute(xxt_mma, cudaFuncAttributeMaxDynamicSharedMemorySize, 98304);
    cudaFuncSetAttribute(out_mma, cudaFuncAttributeMaxDynamicSharedMemorySize, 163840);

    // S = X X^T per batch (tensor cores, split-K) — no deps on weights
    xxt_mma<<<dim3(KSPLIT1, NB), 256, 98304>>>(x_in);

    // combined channel maps (tiny)
    prep_weights<<<dim3(6,6,4), 256>>>(w_q, w_k, w_v, w_out, w_split, w_proj);
    bias_combine<<<1, 192>>>(w_out, b_proj);

    s_reduce<<<(NB*CH*CH + 255)/256, 256>>>();

    // Gram + norms in channel space
    gemm192v2<<<dim3(6,6,NB), 256>>>(pS,  pWq, pT1, 1,0,1);   // T1 = S Wq'^T
    gemm192v2<<<dim3(6,6,NB), 256>>>(pS,  pWk, pT2, 1,0,1);   // T2 = S Wk'^T
    diag_norms<<<dim3(NB,2), 192>>>();
    gemm192v2<<<dim3(6,6,NB), 256>>>(pWk, pT1, pG,  0,1,0);   // G = Wk' T1

    softmax_rows<<<dim3(CH,NB), 192>>>();

    gemm192v2<<<dim3(6,6,NB), 256>>>(pWp2, pAttn, pA1, 0,1,0); // A1 = Wp2 attn
    gemm192v2<<<dim3(6,6,NB), 256>>>(pA1,  pWv,   pA2, 1,0,0); // A2 = A1 Wv'

    // out = A2 X + bp2 (tensor cores)
    out_mma<<<dim3(HW/128, NB), 256, 163840>>>(x_in, out);
}

// round 9
// speedup vs baseline: 2.2305x; 1.0505x over previous
#include <cuda_runtime.h>
#include <cuda_bf16.h>
#include <cstdint>

#define CH 192
#define NB 8
#define HW 16384
#define KSPLIT1 16
#define EPSN 1e-12f

// ---------------- mma.sync / ldmatrix helpers (sm_80+ baseline PTX) ----------------
__device__ __forceinline__ uint32_t smem_u32(const void* p) {
    uint32_t a;
    asm("{ .reg .u64 t; cvta.to.shared.u64 t, %1; cvt.u32.u64 %0, t; }" : "=r"(a) : "l"(p));
    return a;
}
__device__ __forceinline__ void hmma(float* d, const uint32_t* a, const uint32_t* b) {
    asm volatile("mma.sync.aligned.m16n8k16.row.col.f32.bf16.bf16.f32 "
        "{%0,%1,%2,%3}, {%4,%5,%6,%7}, {%8,%9}, {%0,%1,%2,%3};"
        : "+f"(d[0]), "+f"(d[1]), "+f"(d[2]), "+f"(d[3])
        : "r"(a[0]), "r"(a[1]), "r"(a[2]), "r"(a[3]), "r"(b[0]), "r"(b[1]));
}
__device__ __forceinline__ void ldsm4(uint32_t* r, uint32_t a) {
    asm volatile("ldmatrix.sync.aligned.m8n8.x4.shared.b16 {%0,%1,%2,%3}, [%4];"
        : "=r"(r[0]), "=r"(r[1]), "=r"(r[2]), "=r"(r[3]) : "r"(a));
}
__device__ __forceinline__ void ldsm4t(uint32_t* r, uint32_t a) {
    asm volatile("ldmatrix.sync.aligned.m8n8.x4.trans.shared.b16 {%0,%1,%2,%3}, [%4];"
        : "=r"(r[0]), "=r"(r[1]), "=r"(r[2]), "=r"(r[3]) : "r"(a));
}
// fp32 pair -> bf16 hi pair + bf16 lo pair (packed b32 each)
__device__ __forceinline__ void split2(float x, float y, uint32_t& h, uint32_t& l) {
    __nv_bfloat162 hb = __floats2bfloat162_rn(x, y);
    float2 hf = __bfloat1622float2(hb);
    __nv_bfloat162 lb = __floats2bfloat162_rn(x - hf.x, y - hf.y);
    h = *reinterpret_cast<uint32_t*>(&hb);
    l = *reinterpret_cast<uint32_t*>(&lb);
}
// fp32 pair -> hi, hi/2 (exact), lo
__device__ __forceinline__ void split3(float x, float y, uint32_t& h, uint32_t& hh, uint32_t& l) {
    __nv_bfloat162 hb = __floats2bfloat162_rn(x, y);
    float2 hf = __bfloat1622float2(hb);
    __nv_bfloat162 lb = __floats2bfloat162_rn(x - hf.x, y - hf.y);
    __nv_bfloat162 hhb = __floats2bfloat162_rn(0.5f * hf.x, 0.5f * hf.y);
    h  = *reinterpret_cast<uint32_t*>(&hb);
    hh = *reinterpret_cast<uint32_t*>(&hhb);
    l  = *reinterpret_cast<uint32_t*>(&lb);
}

// ---------------- packed f32x2 helpers (small GEMMs) ----------------
__device__ __forceinline__ unsigned long long pack2(float lo, float hi) {
    unsigned long long r;
    asm("mov.b64 %0, {%1, %2};" : "=l"(r) : "f"(lo), "f"(hi));
    return r;
}
__device__ __forceinline__ void unpack2(unsigned long long v, float& lo, float& hi) {
    asm("mov.b64 {%0, %1}, %2;" : "=f"(lo), "=f"(hi) : "l"(v));
}
__device__ __forceinline__ void fma2(unsigned long long& d, unsigned long long a, unsigned long long b) {
    asm("fma.rn.f32x2 %0, %1, %2, %0;" : "+l"(d) : "l"(a), "l"(b));
}

// ---------------- scratch ----------------
__device__ float g_Wq[CH*CH], g_Wk[CH*CH], g_Wv[CH*CH], g_Wp2[CH*CH], g_bp2[CH];
__device__ float g_Spart[NB*KSPLIT1*CH*CH];
__device__ float g_S[NB*CH*CH], g_T1[NB*CH*CH], g_T2[NB*CH*CH];
__device__ float g_G[NB*CH*CH], g_attn[NB*CH*CH], g_A1[NB*CH*CH], g_A2[NB*CH*CH];
__device__ float g_nk2[NB*CH], g_nq2[NB*CH];

// ============ GEMM1: M[b,p] = H (H/2)^T + H L^T ; S = sum_p (M + M^T) ============
// grid (KSPLIT1, NB), 256 thr, dyn smem 147456
// stage: XH 192x64 (24576) | XHh (24576) | XL (24576) = 73728, x2 stages
__global__ __launch_bounds__(256) void xxt_mma(const float* __restrict__ xin) {
    extern __shared__ char smem[];
    const int tid = threadIdx.x, wid = tid >> 5, lane = tid & 31;
    const int split = blockIdx.x, b = blockIdx.y;
    const float* Xb = xin + (size_t)b * CH * HW;
    const int kbase = split * (HW / KSPLIT1);
    const uint32_t sb = smem_u32(smem);
    const int m0 = (wid >> 2) * 96, n0 = (wid & 3) * 48;

    float d[6][6][4];
    #pragma unroll
    for (int i = 0; i < 6; ++i)
        #pragma unroll
        for (int j = 0; j < 6; ++j)
            #pragma unroll
            for (int q = 0; q < 4; ++q) d[i][j][q] = 0.f;

    auto stage_load = [&](int buf, int kb) {
        char* XH  = smem + buf * 73728;
        char* XHh = XH + 24576;
        char* XL  = XH + 49152;
        #pragma unroll
        for (int u = tid; u < 3072; u += 256) {
            int r = u >> 4, k4 = (u & 15) << 2;
            float4 v = *(const float4*)&Xb[(size_t)r * HW + kb + k4];
            uint32_t h0, hh0, l0, h1, hh1, l1;
            split3(v.x, v.y, h0, hh0, l0);
            split3(v.z, v.w, h1, hh1, l1);
            int sw = r * 128 + (((u & 15) << 3) ^ ((r & 7) << 4));
            *(uint2*)(XH  + sw) = make_uint2(h0, h1);
            *(uint2*)(XHh + sw) = make_uint2(hh0, hh1);
            *(uint2*)(XL  + sw) = make_uint2(l0, l1);
        }
    };

    const int xorv = (lane & 7) << 4;
    const int mat = lane >> 3;
    const int halfA = (lane >> 4) << 4;
    const int halfB = (mat & 1) << 4;
    const int rA15 = lane & 15;
    const int rB = ((mat >> 1) << 3) + (lane & 7);

    auto stage_compute = [&](int buf) {
        uint32_t baseH  = sb + buf * 73728;
        uint32_t baseHh = baseH + 24576;
        uint32_t baseL  = baseH + 49152;
        #pragma unroll 1
        for (int kk = 0; kk < 4; ++kk) {
            int colA = ((kk << 5) + halfA) ^ xorv;
            int colB = ((kk << 5) + halfB) ^ xorv;
            uint32_t ah[6][4], bh[3][4];
            #pragma unroll
            for (int i = 0; i < 6; ++i)
                ldsm4(ah[i], baseH + (m0 + 16*i + rA15) * 128 + colA);
            #pragma unroll
            for (int jj = 0; jj < 3; ++jj)
                ldsm4(bh[jj], baseHh + (n0 + jj*16 + rB) * 128 + colB);
            #pragma unroll
            for (int i = 0; i < 6; ++i)
                #pragma unroll
                for (int jj = 0; jj < 3; ++jj) {
                    hmma(d[i][2*jj],     ah[i], &bh[jj][0]);
                    hmma(d[i][2*jj + 1], ah[i], &bh[jj][2]);
                }
            uint32_t bl[3][4];
            #pragma unroll
            for (int jj = 0; jj < 3; ++jj)
                ldsm4(bl[jj], baseL + (n0 + jj*16 + rB) * 128 + colB);
            #pragma unroll
            for (int i = 0; i < 6; ++i)
                #pragma unroll
                for (int jj = 0; jj < 3; ++jj) {
                    hmma(d[i][2*jj],     ah[i], &bl[jj][0]);
                    hmma(d[i][2*jj + 1], ah[i], &bl[jj][2]);
                }
        }
    };

    stage_load(0, kbase);
    __syncthreads();
    for (int c = 0; c < 16; ++c) {
        if (c < 15) stage_load((c + 1) & 1, kbase + (c + 1) * 64);
        stage_compute(c & 1);
        __syncthreads();
    }

    float* Sp = g_Spart + (size_t)(b * KSPLIT1 + split) * CH * CH;
    int lr = lane >> 2, lc2 = (lane & 3) * 2;
    #pragma unroll
    for (int mi = 0; mi < 6; ++mi)
        #pragma unroll
        for (int nj = 0; nj < 6; ++nj) {
            int r = m0 + 16*mi + lr, cc = n0 + 8*nj + lc2;
            *(float2*)&Sp[r * CH + cc]       = make_float2(d[mi][nj][0], d[mi][nj][1]);
            *(float2*)&Sp[(r + 8) * CH + cc] = make_float2(d[mi][nj][2], d[mi][nj][3]);
        }
}

// S = sum_p (M_p + M_p^T)
__global__ void s_reduce() {
    int idx = blockIdx.x * 256 + threadIdx.x;
    if (idx < NB*CH*CH) {
        int b = idx / (CH*CH), e = idx % (CH*CH);
        int i = e / CH, j = e % CH;
        const float* Sp = g_Spart + (size_t)b * KSPLIT1 * CH * CH;
        float s = 0.f;
        #pragma unroll
        for (int p = 0; p < KSPLIT1; ++p)
            s += Sp[(size_t)p*CH*CH + i*CH + j] + Sp[(size_t)p*CH*CH + j*CH + i];
        g_S[idx] = s;
    }
}

// ============ GEMM2: out[b] = A2 X + bp2 via mma.sync (out-ch x pixels) ============
// grid (HW/128, NB), 512 thr (16 warps, warp tile 48x32), dyn smem 163840
// stage: A2H 192x64 (24576) | A2L (24576) | XH 64x128 (16384) | XL (16384) = 81920
__global__ __launch_bounds__(512) void out_mma(const float* __restrict__ xin,
                                               float* __restrict__ out) {
    extern __shared__ char smem[];
    const int tid = threadIdx.x, wid = tid >> 5, lane = tid & 31;
    const int p0 = blockIdx.x * 128, b = blockIdx.y;
    const float* Xb = xin + (size_t)b * CH * HW;
    const float* A2b = g_A2 + (size_t)b * CH * CH;
    const uint32_t sb = smem_u32(smem);
    const int m0 = (wid >> 2) * 48, n0p = (wid & 3) * 32;

    float d[3][4][4];
    #pragma unroll
    for (int i = 0; i < 3; ++i)
        #pragma unroll
        for (int j = 0; j < 4; ++j)
            #pragma unroll
            for (int q = 0; q < 4; ++q) d[i][j][q] = 0.f;

    auto stage_load = [&](int buf, int c0) {
        char* base = smem + buf * 81920;
        char* A2H = base;
        char* A2L = base + 24576;
        char* XH  = base + 49152;
        char* XL  = base + 65536;
        #pragma unroll
        for (int u = tid; u < 3072; u += 512) {   // A2: 192 co x 64 c
            int r = u >> 4, c4 = (u & 15) << 2;
            float4 v = *(const float4*)&A2b[r * CH + c0 + c4];
            uint32_t h0, l0, h1, l1;
            split2(v.x, v.y, h0, l0);
            split2(v.z, v.w, h1, l1);
            int sw = r * 128 + (((u & 15) << 3) ^ ((r & 7) << 4));
            *(uint2*)(A2H + sw) = make_uint2(h0, h1);
            *(uint2*)(A2L + sw) = make_uint2(l0, l1);
        }
        #pragma unroll
        for (int u = tid; u < 2048; u += 512) {   // X: 64 c x 128 p
            int r = u >> 5, p4 = (u & 31) << 2;
            float4 v = *(const float4*)&Xb[(size_t)(c0 + r) * HW + p0 + p4];
            uint32_t h0, l0, h1, l1;
            split2(v.x, v.y, h0, l0);
            split2(v.z, v.w, h1, l1);
            int sw = r * 256 + (((u & 31) << 3) ^ ((r & 7) << 4));
            *(uint2*)(XH + sw) = make_uint2(h0, h1);
            *(uint2*)(XL + sw) = make_uint2(l0, l1);
        }
    };

    const int xorv = (lane & 7) << 4;
    const int mat = lane >> 3;
    const int halfA = (lane >> 4) << 4;
    const int rA15 = lane & 15;
    const int rbX = ((mat & 1) << 3) + (lane & 7);     // X k-row within k16
    const int cbX = (n0p + ((mat >> 1) << 3)) * 2;     // X n-col bytes (+ jj*32)

    auto stage_compute = [&](int buf) {
        uint32_t baseAH = sb + buf * 81920;
        uint32_t baseAL = baseAH + 24576;
        uint32_t baseXH = baseAH + 49152;
        uint32_t baseXL = baseAH + 65536;
        #pragma unroll 1
        for (int kk = 0; kk < 4; ++kk) {
            int colA = ((kk << 5) + halfA) ^ xorv;
            int xrow = (kk * 16 + rbX) * 256;
            uint32_t ah[3][4], bt[2][4];
            #pragma unroll
            for (int mi = 0; mi < 3; ++mi)
                ldsm4(ah[mi], baseAH + (m0 + 16*mi + rA15) * 128 + colA);
            #pragma unroll
            for (int jj = 0; jj < 2; ++jj)
                ldsm4t(bt[jj], baseXH + xrow + ((cbX + jj*32) ^ xorv));
            #pragma unroll
            for (int mi = 0; mi < 3; ++mi)
                #pragma unroll
                for (int jj = 0; jj < 2; ++jj) {
                    hmma(d[mi][2*jj],     ah[mi], &bt[jj][0]);
                    hmma(d[mi][2*jj + 1], ah[mi], &bt[jj][2]);
                }
            uint32_t btl[2][4];
            #pragma unroll
            for (int jj = 0; jj < 2; ++jj)
                ldsm4t(btl[jj], baseXL + xrow + ((cbX + jj*32) ^ xorv));
            #pragma unroll
            for (int mi = 0; mi < 3; ++mi)
                #pragma unroll
                for (int jj = 0; jj < 2; ++jj) {
                    hmma(d[mi][2*jj],     ah[mi], &btl[jj][0]);
                    hmma(d[mi][2*jj + 1], ah[mi], &btl[jj][2]);
                }
            uint32_t al[3][4];
            #pragma unroll
            for (int mi = 0; mi < 3; ++mi)
                ldsm4(al[mi], baseAL + (m0 + 16*mi + rA15) * 128 + colA);
            #pragma unroll
            for (int mi = 0; mi < 3; ++mi)
                #pragma unroll
                for (int jj = 0; jj < 2; ++jj) {
                    hmma(d[mi][2*jj],     al[mi], &bt[jj][0]);
                    hmma(d[mi][2*jj + 1], al[mi], &bt[jj][2]);
                }
        }
    };

    stage_load(0, 0);
    __syncthreads();
    for (int c = 0; c < 3; ++c) {
        if (c < 2) stage_load((c + 1) & 1, (c + 1) * 64);
        stage_compute(c & 1);
        __syncthreads();
    }

    // stage output through smem for coalesced stores
    float* so = (float*)smem;   // 192 x 132 floats = 101376 B
    int lr = lane >> 2, lc2 = (lane & 3) * 2;
    #pragma unroll
    for (int mi = 0; mi < 3; ++mi)
        #pragma unroll
        for (int nj = 0; nj < 4; ++nj) {
            int r = m0 + 16*mi + lr, cc = n0p + 8*nj + lc2;
            *(float2*)&so[r * 132 + cc]       = make_float2(d[mi][nj][0], d[mi][nj][1]);
            *(float2*)&so[(r + 8) * 132 + cc] = make_float2(d[mi][nj][2], d[mi][nj][3]);
        }
    __syncthreads();
    #pragma unroll
    for (int u = tid; u < 6144; u += 512) {
        int co = u >> 5, p4 = (u & 31) << 2;
        float4 v = *(const float4*)&so[co * 132 + p4];
        float bias = g_bp2[co];
        v.x += bias; v.y += bias; v.z += bias; v.w += bias;
        *(float4*)&out[((size_t)b * CH + co) * HW + p0 + p4] = v;
    }
}

// ---------------- small 192x192 GEMM core: 32x32 tile, 2x2/thread, FFMA2 ----------------
__device__ __forceinline__ void gemm_tile32(const float* __restrict__ Ab,
                                            const float* __restrict__ Bb,
                                            float* __restrict__ Cb,
                                            int transB, int i0, int j0) {
    __shared__ float As[16][34], Bs[16][34];
    int t = threadIdx.x;
    int tx = t & 15, ty = t >> 4;
    int li = t & 31, lkq = t >> 5;
    int lkb = t >> 4, lj2 = (t & 15) * 2;

    unsigned long long acc0 = 0ull, acc1 = 0ull;

    for (int kk = 0; kk < CH; kk += 16) {
        float2 av = *(const float2*)&Ab[(i0 + li) * CH + kk + lkq * 2];
        float2 bv;
        if (transB) bv = *(const float2*)&Bb[(j0 + li) * CH + kk + lkq * 2];
        else        bv = *(const float2*)&Bb[(kk + lkb) * CH + j0 + lj2];
        __syncthreads();
        As[lkq*2 + 0][li] = av.x;
        As[lkq*2 + 1][li] = av.y;
        if (transB) { Bs[lkq*2 + 0][li] = bv.x; Bs[lkq*2 + 1][li] = bv.y; }
        else        { *(float2*)&Bs[lkb][lj2] = bv; }
        __syncthreads();
        #pragma unroll
        for (int k = 0; k < 16; ++k) {
            float2 a2 = *(const float2*)&As[k][ty * 2];
            unsigned long long b2 = *(const unsigned long long*)&Bs[k][tx * 2];
            fma2(acc0, pack2(a2.x, a2.x), b2);
            fma2(acc1, pack2(a2.y, a2.y), b2);
        }
    }
    float o00, o01, o10, o11;
    unpack2(acc0, o00, o01);
    unpack2(acc1, o10, o11);
    *(float2*)&Cb[(i0 + ty*2 + 0) * CH + j0 + tx*2] = make_float2(o00, o01);
    *(float2*)&Cb[(i0 + ty*2 + 1) * CH + j0 + tx*2] = make_float2(o10, o11);
}

__global__ __launch_bounds__(256) void prep_weights(const float* __restrict__ wq,
                                                    const float* __restrict__ wk,
                                                    const float* __restrict__ wv,
                                                    const float* __restrict__ wout,
                                                    const float* __restrict__ wsplit,
                                                    const float* __restrict__ wproj) {
    const float *A, *B; float* C;
    switch (blockIdx.z) {
        case 0:  A = wq;   B = wsplit; C = g_Wq;  break;
        case 1:  A = wk;   B = wsplit; C = g_Wk;  break;
        case 2:  A = wv;   B = wsplit; C = g_Wv;  break;
        default: A = wout; B = wproj;  C = g_Wp2; break;
    }
    gemm_tile32(A, B, C, 0, blockIdx.x * 32, blockIdx.y * 32);
}

__global__ __launch_bounds__(256) void gemm192v2(const float* __restrict__ A,
                                                 const float* __restrict__ Bm,
                                                 float* __restrict__ Cm,
                                                 int aBatched, int bBatched, int transB) {
    int b = blockIdx.z;
    gemm_tile32(A + (aBatched ? b*CH*CH : 0),
                Bm + (bBatched ? b*CH*CH : 0),
                Cm + b*CH*CH, transB,
                blockIdx.x * 32, blockIdx.y * 32);
}

__global__ void bias_combine(const float* __restrict__ w_out, const float* __restrict__ b_proj) {
    int f = threadIdx.x;
    if (f < CH) {
        float s = 0.f;
        for (int o = 0; o < CH; ++o) s += w_out[f*CH+o] * b_proj[o];
        g_bp2[f] = s;
    }
}

__global__ void diag_norms() {
    int b = blockIdx.x, which = blockIdx.y;
    int j = threadIdx.x;
    if (j >= CH) return;
    const float* W = which ? g_Wk : g_Wq;
    const float* T = (which ? g_T2 : g_T1) + (size_t)b*CH*CH;
    float s = 0.f;
    for (int m = 0; m < CH; ++m) s += W[j*CH+m] * T[m*CH+j];
    (which ? g_nk2 : g_nq2)[b*CH+j] = s;
}

__global__ void softmax_rows() {
    int b = blockIdx.y, i = blockIdx.x;
    int j = threadIdx.x;
    const float* Grow = g_G + ((size_t)b*CH + i)*CH;
    float dk = fmaxf(sqrtf(g_nk2[b*CH+i]), EPSN);
    float dq = fmaxf(sqrtf(g_nq2[b*CH+j]), EPSN);
    float L = Grow[j] / (dk*dq);
    __shared__ float redm[6], reds[6];
    float m = L;
    #pragma unroll
    for (int o = 16; o > 0; o >>= 1) m = fmaxf(m, __shfl_xor_sync(0xffffffffu, m, o));
    if ((j & 31) == 0) redm[j>>5] = m;
    __syncthreads();
    float mx = fmaxf(fmaxf(fmaxf(redm[0],redm[1]),fmaxf(redm[2],redm[3])),fmaxf(redm[4],redm[5]));
    float e = expf(L - mx);
    float s = e;
    #pragma unroll
    for (int o = 16; o > 0; o >>= 1) s += __shfl_xor_sync(0xffffffffu, s, o);
    if ((j & 31) == 0) reds[j>>5] = s;
    __syncthreads();
    float sum = reds[0]+reds[1]+reds[2]+reds[3]+reds[4]+reds[5];
    g_attn[((size_t)b*CH + i)*CH + j] = e / sum;
}

// ---------------- launch ----------------
extern "C" void kernel_launch(void* const* d_in, const int* in_sizes, int n_in,
                              void* d_out, int out_size) {
    const float* x_in   = (const float*)d_in[0];
    const float* w_split= (const float*)d_in[1];
    const float* w_q    = (const float*)d_in[2];
    const float* w_k    = (const float*)d_in[3];
    const float* w_v    = (const float*)d_in[4];
    const float* w_proj = (const float*)d_in[5];
    const float* b_proj = (const float*)d_in[6];
    const float* w_out  = (const float*)d_in[7];
    float* out = (float*)d_out;

    float *pWq, *pWk, *pWv, *pWp2, *pS, *pT1, *pT2, *pG, *pAttn, *pA1, *pA2;
    cudaGetSymbolAddress((void**)&pWq,  g_Wq);
    cudaGetSymbolAddress((void**)&pWk,  g_Wk);
    cudaGetSymbolAddress((void**)&pWv,  g_Wv);
    cudaGetSymbolAddress((void**)&pWp2, g_Wp2);
    cudaGetSymbolAddress((void**)&pS,   g_S);
    cudaGetSymbolAddress((void**)&pT1,  g_T1);
    cudaGetSymbolAddress((void**)&pT2,  g_T2);
    cudaGetSymbolAddress((void**)&pG,   g_G);
    cudaGetSymbolAddress((void**)&pAttn,g_attn);
    cudaGetSymbolAddress((void**)&pA1,  g_A1);
    cudaGetSymbolAddress((void**)&pA2,  g_A2);

    cudaFuncSetAttribute(xxt_mma, cudaFuncAttributeMaxDynamicSharedMemorySize, 147456);
    cudaFuncSetAttribute(out_mma, cudaFuncAttributeMaxDynamicSharedMemorySize, 163840);

    // M partials (tensor cores, split-K) — no deps on weights
    xxt_mma<<<dim3(KSPLIT1, NB), 256, 147456>>>(x_in);

    // combined channel maps (tiny)
    prep_weights<<<dim3(6,6,4), 256>>>(w_q, w_k, w_v, w_out, w_split, w_proj);
    bias_combine<<<1, 192>>>(w_out, b_proj);

    // S = sum (M + M^T)
    s_reduce<<<(NB*CH*CH + 255)/256, 256>>>();

    // Gram + norms in channel space
    gemm192v2<<<dim3(6,6,NB), 256>>>(pS,  pWq, pT1, 1,0,1);   // T1 = S Wq'^T
    gemm192v2<<<dim3(6,6,NB), 256>>>(pS,  pWk, pT2, 1,0,1);   // T2 = S Wk'^T
    diag_norms<<<dim3(NB,2), 192>>>();
    gemm192v2<<<dim3(6,6,NB), 256>>>(pWk, pT1, pG,  0,1,0);   // G = Wk' T1

    softmax_rows<<<dim3(CH,NB), 192>>>();

    gemm192v2<<<dim3(6,6,NB), 256>>>(pWp2, pAttn, pA1, 0,1,0); // A1 = Wp2 attn
    gemm192v2<<<dim3(6,6,NB), 256>>>(pA1,  pWv,   pA2, 1,0,0); // A2 = A1 Wv'

    // out = A2 X + bp2 (tensor cores)
    out_mma<<<dim3(HW/128, NB), 512, 163840>>>(x_in, out);
}

// round 10
// speedup vs baseline: 2.3547x; 1.0557x over previous
#include <cuda_runtime.h>
#include <cuda_bf16.h>
#include <cstdint>

#define CH 192
#define NB 8
#define HW 16384
#define KSPLIT1 16
#define EPSN 1e-12f

// ---------------- mma.sync / ldmatrix helpers (sm_80+ baseline PTX) ----------------
__device__ __forceinline__ uint32_t smem_u32(const void* p) {
    uint32_t a;
    asm("{ .reg .u64 t; cvta.to.shared.u64 t, %1; cvt.u32.u64 %0, t; }" : "=r"(a) : "l"(p));
    return a;
}
__device__ __forceinline__ void hmma(float* d, const uint32_t* a, const uint32_t* b) {
    asm volatile("mma.sync.aligned.m16n8k16.row.col.f32.bf16.bf16.f32 "
        "{%0,%1,%2,%3}, {%4,%5,%6,%7}, {%8,%9}, {%0,%1,%2,%3};"
        : "+f"(d[0]), "+f"(d[1]), "+f"(d[2]), "+f"(d[3])
        : "r"(a[0]), "r"(a[1]), "r"(a[2]), "r"(a[3]), "r"(b[0]), "r"(b[1]));
}
__device__ __forceinline__ void ldsm4(uint32_t* r, uint32_t a) {
    asm volatile("ldmatrix.sync.aligned.m8n8.x4.shared.b16 {%0,%1,%2,%3}, [%4];"
        : "=r"(r[0]), "=r"(r[1]), "=r"(r[2]), "=r"(r[3]) : "r"(a));
}
__device__ __forceinline__ void ldsm4t(uint32_t* r, uint32_t a) {
    asm volatile("ldmatrix.sync.aligned.m8n8.x4.trans.shared.b16 {%0,%1,%2,%3}, [%4];"
        : "=r"(r[0]), "=r"(r[1]), "=r"(r[2]), "=r"(r[3]) : "r"(a));
}
// fp32 pair -> bf16 hi pair + bf16 lo pair (packed b32 each)
__device__ __forceinline__ void split2(float x, float y, uint32_t& h, uint32_t& l) {
    __nv_bfloat162 hb = __floats2bfloat162_rn(x, y);
    float2 hf = __bfloat1622float2(hb);
    __nv_bfloat162 lb = __floats2bfloat162_rn(x - hf.x, y - hf.y);
    h = *reinterpret_cast<uint32_t*>(&hb);
    l = *reinterpret_cast<uint32_t*>(&lb);
}
// fp32 pair -> hi, hi/2 (exact), lo
__device__ __forceinline__ void split3(float x, float y, uint32_t& h, uint32_t& hh, uint32_t& l) {
    __nv_bfloat162 hb = __floats2bfloat162_rn(x, y);
    float2 hf = __bfloat1622float2(hb);
    __nv_bfloat162 lb = __floats2bfloat162_rn(x - hf.x, y - hf.y);
    __nv_bfloat162 hhb = __floats2bfloat162_rn(0.5f * hf.x, 0.5f * hf.y);
    h  = *reinterpret_cast<uint32_t*>(&hb);
    hh = *reinterpret_cast<uint32_t*>(&hhb);
    l  = *reinterpret_cast<uint32_t*>(&lb);
}

// ---------------- packed f32x2 helpers (small GEMMs) ----------------
__device__ __forceinline__ unsigned long long pack2(float lo, float hi) {
    unsigned long long r;
    asm("mov.b64 %0, {%1, %2};" : "=l"(r) : "f"(lo), "f"(hi));
    return r;
}
__device__ __forceinline__ void unpack2(unsigned long long v, float& lo, float& hi) {
    asm("mov.b64 {%0, %1}, %2;" : "=f"(lo), "=f"(hi) : "l"(v));
}
__device__ __forceinline__ void fma2(unsigned long long& d, unsigned long long a, unsigned long long b) {
    asm("fma.rn.f32x2 %0, %1, %2, %0;" : "+l"(d) : "l"(a), "l"(b));
}

// ---------------- scratch ----------------
__device__ float g_Wq[CH*CH], g_Wk[CH*CH], g_Wv[CH*CH], g_Wp2[CH*CH], g_bp2[CH];
__device__ float g_Spart[NB*KSPLIT1*CH*CH];
__device__ float g_S[NB*CH*CH], g_T1[NB*CH*CH], g_T2[NB*CH*CH];
__device__ float g_G[NB*CH*CH], g_attn[NB*CH*CH], g_A1[NB*CH*CH], g_A2[NB*CH*CH];
__device__ float g_nk2[NB*CH], g_nq2[NB*CH];
__device__ __nv_bfloat16 g_A2h[NB*CH*CH], g_A2l[NB*CH*CH];

// ============ GEMM1: M[b,p] = H (H/2)^T + H L^T ; S = sum_p (M + M^T) ============
// grid (KSPLIT1, NB), 512 thr (16 warps, warp tile 48x48), dyn smem 147456
// stage: XH 192x64 (24576) | XHh (24576) | XL (24576) = 73728, x2 stages
__global__ __launch_bounds__(512) void xxt_mma(const float* __restrict__ xin) {
    extern __shared__ char smem[];
    const int tid = threadIdx.x, wid = tid >> 5, lane = tid & 31;
    const int split = blockIdx.x, b = blockIdx.y;
    const float* Xb = xin + (size_t)b * CH * HW;
    const int kbase = split * (HW / KSPLIT1);
    const uint32_t sb = smem_u32(smem);
    const int m0 = (wid >> 2) * 48, n0 = (wid & 3) * 48;

    float d[3][6][4];
    #pragma unroll
    for (int i = 0; i < 3; ++i)
        #pragma unroll
        for (int j = 0; j < 6; ++j)
            #pragma unroll
            for (int q = 0; q < 4; ++q) d[i][j][q] = 0.f;

    auto stage_load = [&](int buf, int kb) {
        char* XH  = smem + buf * 73728;
        char* XHh = XH + 24576;
        char* XL  = XH + 49152;
        #pragma unroll
        for (int u = tid; u < 3072; u += 512) {
            int r = u >> 4, k4 = (u & 15) << 2;
            float4 v = *(const float4*)&Xb[(size_t)r * HW + kb + k4];
            uint32_t h0, hh0, l0, h1, hh1, l1;
            split3(v.x, v.y, h0, hh0, l0);
            split3(v.z, v.w, h1, hh1, l1);
            int sw = r * 128 + (((u & 15) << 3) ^ ((r & 7) << 4));
            *(uint2*)(XH  + sw) = make_uint2(h0, h1);
            *(uint2*)(XHh + sw) = make_uint2(hh0, hh1);
            *(uint2*)(XL  + sw) = make_uint2(l0, l1);
        }
    };

    const int xorv = (lane & 7) << 4;
    const int mat = lane >> 3;
    const int halfA = (lane >> 4) << 4;
    const int halfB = (mat & 1) << 4;
    const int rA15 = lane & 15;
    const int rB = ((mat >> 1) << 3) + (lane & 7);

    auto stage_compute = [&](int buf) {
        uint32_t baseH  = sb + buf * 73728;
        uint32_t baseHh = baseH + 24576;
        uint32_t baseL  = baseH + 49152;
        #pragma unroll 1
        for (int kk = 0; kk < 4; ++kk) {
            int colA = ((kk << 5) + halfA) ^ xorv;
            int colB = ((kk << 5) + halfB) ^ xorv;
            uint32_t ah[3][4], bh[3][4];
            #pragma unroll
            for (int i = 0; i < 3; ++i)
                ldsm4(ah[i], baseH + (m0 + 16*i + rA15) * 128 + colA);
            #pragma unroll
            for (int jj = 0; jj < 3; ++jj)
                ldsm4(bh[jj], baseHh + (n0 + jj*16 + rB) * 128 + colB);
            #pragma unroll
            for (int i = 0; i < 3; ++i)
                #pragma unroll
                for (int jj = 0; jj < 3; ++jj) {
                    hmma(d[i][2*jj],     ah[i], &bh[jj][0]);
                    hmma(d[i][2*jj + 1], ah[i], &bh[jj][2]);
                }
            uint32_t bl[3][4];
            #pragma unroll
            for (int jj = 0; jj < 3; ++jj)
                ldsm4(bl[jj], baseL + (n0 + jj*16 + rB) * 128 + colB);
            #pragma unroll
            for (int i = 0; i < 3; ++i)
                #pragma unroll
                for (int jj = 0; jj < 3; ++jj) {
                    hmma(d[i][2*jj],     ah[i], &bl[jj][0]);
                    hmma(d[i][2*jj + 1], ah[i], &bl[jj][2]);
                }
        }
    };

    stage_load(0, kbase);
    __syncthreads();
    for (int c = 0; c < 16; ++c) {
        if (c < 15) stage_load((c + 1) & 1, kbase + (c + 1) * 64);
        stage_compute(c & 1);
        __syncthreads();
    }

    float* Sp = g_Spart + (size_t)(b * KSPLIT1 + split) * CH * CH;
    int lr = lane >> 2, lc2 = (lane & 3) * 2;
    #pragma unroll
    for (int mi = 0; mi < 3; ++mi)
        #pragma unroll
        for (int nj = 0; nj < 6; ++nj) {
            int r = m0 + 16*mi + lr, cc = n0 + 8*nj + lc2;
            *(float2*)&Sp[r * CH + cc]       = make_float2(d[mi][nj][0], d[mi][nj][1]);
            *(float2*)&Sp[(r + 8) * CH + cc] = make_float2(d[mi][nj][2], d[mi][nj][3]);
        }
}

// S = sum_p (M_p + M_p^T), fully coalesced via 32x32 smem-transposed tiles
// grid (6,6,NB), 256 thr
__global__ __launch_bounds__(256) void symm_reduce() {
    __shared__ float tb[32][33];
    int b = blockIdx.z;
    int i0 = blockIdx.x * 32, j0 = blockIdx.y * 32;
    int c = threadIdx.x & 31, ty = threadIdx.x >> 5;   // 8 rows/pass
    const float* Sp = g_Spart + (size_t)b * KSPLIT1 * CH * CH;
    float a[4], bt[4];
    #pragma unroll
    for (int q = 0; q < 4; ++q) { a[q] = 0.f; bt[q] = 0.f; }
    #pragma unroll
    for (int p = 0; p < KSPLIT1; ++p) {
        const float* M = Sp + (size_t)p * CH * CH;
        #pragma unroll
        for (int q = 0; q < 4; ++q) {
            int r = ty + q * 8;
            a[q]  += M[(i0 + r) * CH + j0 + c];
            bt[q] += M[(j0 + r) * CH + i0 + c];
        }
    }
    #pragma unroll
    for (int q = 0; q < 4; ++q) tb[ty + q * 8][c] = bt[q];
    __syncthreads();
    float* Sb = g_S + (size_t)b * CH * CH;
    #pragma unroll
    for (int q = 0; q < 4; ++q) {
        int r = ty + q * 8;
        Sb[(i0 + r) * CH + j0 + c] = a[q] + tb[c][r];
    }
}

// ============ GEMM2: out[b] = A2 X + bp2 via mma.sync (out-ch x pixels) ============
// grid (HW/128, NB), 512 thr (16 warps, warp tile 48x32), dyn smem 163840
// stage: A2H 192x64 (24576) | A2L (24576) | XH 64x128 (16384) | XL (16384) = 81920
__global__ __launch_bounds__(512) void out_mma(const float* __restrict__ xin,
                                               float* __restrict__ out) {
    extern __shared__ char smem[];
    const int tid = threadIdx.x, wid = tid >> 5, lane = tid & 31;
    const int p0 = blockIdx.x * 128, b = blockIdx.y;
    const float* Xb = xin + (size_t)b * CH * HW;
    const uint32_t sb = smem_u32(smem);
    const int m0 = (wid >> 2) * 48, n0p = (wid & 3) * 32;

    float d[3][4][4];
    #pragma unroll
    for (int i = 0; i < 3; ++i)
        #pragma unroll
        for (int j = 0; j < 4; ++j)
            #pragma unroll
            for (int q = 0; q < 4; ++q) d[i][j][q] = 0.f;

    auto stage_load = [&](int buf, int c0) {
        char* base = smem + buf * 81920;
        char* A2H = base;
        char* A2L = base + 24576;
        char* XH  = base + 49152;
        char* XL  = base + 65536;
        #pragma unroll
        for (int u = tid; u < 1536; u += 512) {   // A2 (pre-split bf16): 192 co x 64 c
            int r = u >> 3, sg = u & 7;
            size_t ro = ((size_t)b * CH + r) * CH + c0 + sg * 8;
            uint4 vh = *(const uint4*)(g_A2h + ro);
            uint4 vl = *(const uint4*)(g_A2l + ro);
            int sw = r * 128 + ((sg << 4) ^ ((r & 7) << 4));
            *(uint4*)(A2H + sw) = vh;
            *(uint4*)(A2L + sw) = vl;
        }
        #pragma unroll
        for (int u = tid; u < 2048; u += 512) {   // X: 64 c x 128 p
            int r = u >> 5, p4 = (u & 31) << 2;
            float4 v = *(const float4*)&Xb[(size_t)(c0 + r) * HW + p0 + p4];
            uint32_t h0, l0, h1, l1;
            split2(v.x, v.y, h0, l0);
            split2(v.z, v.w, h1, l1);
            int sw = r * 256 + (((u & 31) << 3) ^ ((r & 7) << 4));
            *(uint2*)(XH + sw) = make_uint2(h0, h1);
            *(uint2*)(XL + sw) = make_uint2(l0, l1);
        }
    };

    const int xorv = (lane & 7) << 4;
    const int mat = lane >> 3;
    const int halfA = (lane >> 4) << 4;
    const int rA15 = lane & 15;
    const int rbX = ((mat & 1) << 3) + (lane & 7);     // X k-row within k16
    const int cbX = (n0p + ((mat >> 1) << 3)) * 2;     // X n-col bytes (+ jj*32)

    auto stage_compute = [&](int buf) {
        uint32_t baseAH = sb + buf * 81920;
        uint32_t baseAL = baseAH + 24576;
        uint32_t baseXH = baseAH + 49152;
        uint32_t baseXL = baseAH + 65536;
        #pragma unroll 1
        for (int kk = 0; kk < 4; ++kk) {
            int colA = ((kk << 5) + halfA) ^ xorv;
            int xrow = (kk * 16 + rbX) * 256;
            uint32_t ah[3][4], bt[2][4];
            #pragma unroll
            for (int mi = 0; mi < 3; ++mi)
                ldsm4(ah[mi], baseAH + (m0 + 16*mi + rA15) * 128 + colA);
            #pragma unroll
            for (int jj = 0; jj < 2; ++jj)
                ldsm4t(bt[jj], baseXH + xrow + ((cbX + jj*32) ^ xorv));
            #pragma unroll
            for (int mi = 0; mi < 3; ++mi)
                #pragma unroll
                for (int jj = 0; jj < 2; ++jj) {
                    hmma(d[mi][2*jj],     ah[mi], &bt[jj][0]);
                    hmma(d[mi][2*jj + 1], ah[mi], &bt[jj][2]);
                }
            uint32_t btl[2][4];
            #pragma unroll
            for (int jj = 0; jj < 2; ++jj)
                ldsm4t(btl[jj], baseXL + xrow + ((cbX + jj*32) ^ xorv));
            #pragma unroll
            for (int mi = 0; mi < 3; ++mi)
                #pragma unroll
                for (int jj = 0; jj < 2; ++jj) {
                    hmma(d[mi][2*jj],     ah[mi], &btl[jj][0]);
                    hmma(d[mi][2*jj + 1], ah[mi], &btl[jj][2]);
                }
            uint32_t al[3][4];
            #pragma unroll
            for (int mi = 0; mi < 3; ++mi)
                ldsm4(al[mi], baseAL + (m0 + 16*mi + rA15) * 128 + colA);
            #pragma unroll
            for (int mi = 0; mi < 3; ++mi)
                #pragma unroll
                for (int jj = 0; jj < 2; ++jj) {
                    hmma(d[mi][2*jj],     al[mi], &bt[jj][0]);
                    hmma(d[mi][2*jj + 1], al[mi], &bt[jj][2]);
                }
        }
    };

    stage_load(0, 0);
    __syncthreads();
    for (int c = 0; c < 3; ++c) {
        if (c < 2) stage_load((c + 1) & 1, (c + 1) * 64);
        stage_compute(c & 1);
        __syncthreads();
    }

    // stage output through smem for coalesced stores
    float* so = (float*)smem;   // 192 x 132 floats = 101376 B
    int lr = lane >> 2, lc2 = (lane & 3) * 2;
    #pragma unroll
    for (int mi = 0; mi < 3; ++mi)
        #pragma unroll
        for (int nj = 0; nj < 4; ++nj) {
            int r = m0 + 16*mi + lr, cc = n0p + 8*nj + lc2;
            *(float2*)&so[r * 132 + cc]       = make_float2(d[mi][nj][0], d[mi][nj][1]);
            *(float2*)&so[(r + 8) * 132 + cc] = make_float2(d[mi][nj][2], d[mi][nj][3]);
        }
    __syncthreads();
    #pragma unroll
    for (int u = tid; u < 6144; u += 512) {
        int co = u >> 5, p4 = (u & 31) << 2;
        float4 v = *(const float4*)&so[co * 132 + p4];
        float bias = g_bp2[co];
        v.x += bias; v.y += bias; v.z += bias; v.w += bias;
        *(float4*)&out[((size_t)b * CH + co) * HW + p0 + p4] = v;
    }
}

// ---------------- small 192x192 GEMM core: 32x32 tile, 2x2/thread, FFMA2 ----------------
__device__ __forceinline__ void gemm_tile32(const float* __restrict__ Ab,
                                            const float* __restrict__ Bb,
                                            float* __restrict__ Cb,
                                            int transB, int i0, int j0) {
    __shared__ float As[16][34], Bs[16][34];
    int t = threadIdx.x;
    int tx = t & 15, ty = t >> 4;
    int li = t & 31, lkq = t >> 5;
    int lkb = t >> 4, lj2 = (t & 15) * 2;

    unsigned long long acc0 = 0ull, acc1 = 0ull;

    for (int kk = 0; kk < CH; kk += 16) {
        float2 av = *(const float2*)&Ab[(i0 + li) * CH + kk + lkq * 2];
        float2 bv;
        if (transB) bv = *(const float2*)&Bb[(j0 + li) * CH + kk + lkq * 2];
        else        bv = *(const float2*)&Bb[(kk + lkb) * CH + j0 + lj2];
        __syncthreads();
        As[lkq*2 + 0][li] = av.x;
        As[lkq*2 + 1][li] = av.y;
        if (transB) { Bs[lkq*2 + 0][li] = bv.x; Bs[lkq*2 + 1][li] = bv.y; }
        else        { *(float2*)&Bs[lkb][lj2] = bv; }
        __syncthreads();
        #pragma unroll
        for (int k = 0; k < 16; ++k) {
            float2 a2 = *(const float2*)&As[k][ty * 2];
            unsigned long long b2 = *(const unsigned long long*)&Bs[k][tx * 2];
            fma2(acc0, pack2(a2.x, a2.x), b2);
            fma2(acc1, pack2(a2.y, a2.y), b2);
        }
    }
    float o00, o01, o10, o11;
    unpack2(acc0, o00, o01);
    unpack2(acc1, o10, o11);
    *(float2*)&Cb[(i0 + ty*2 + 0) * CH + j0 + tx*2] = make_float2(o00, o01);
    *(float2*)&Cb[(i0 + ty*2 + 1) * CH + j0 + tx*2] = make_float2(o10, o11);
}

__global__ __launch_bounds__(256) void prep_weights(const float* __restrict__ wq,
                                                    const float* __restrict__ wk,
                                                    const float* __restrict__ wv,
                                                    const float* __restrict__ wout,
                                                    const float* __restrict__ wsplit,
                                                    const float* __restrict__ wproj) {
    const float *A, *B; float* C;
    switch (blockIdx.z) {
        case 0:  A = wq;   B = wsplit; C = g_Wq;  break;
        case 1:  A = wk;   B = wsplit; C = g_Wk;  break;
        case 2:  A = wv;   B = wsplit; C = g_Wv;  break;
        default: A = wout; B = wproj;  C = g_Wp2; break;
    }
    gemm_tile32(A, B, C, 0, blockIdx.x * 32, blockIdx.y * 32);
}

// T1 = S Wq'^T and T2 = S Wk'^T in one launch (z: b = z>>1, which = z&1)
__global__ __launch_bounds__(256) void t12_gemm() {
    int z = blockIdx.z;
    int b = z >> 1, which = z & 1;
    const float* W = which ? g_Wk : g_Wq;
    float* T = (which ? g_T2 : g_T1) + (size_t)b * CH * CH;
    gemm_tile32(g_S + (size_t)b * CH * CH, W, T, 1, blockIdx.x * 32, blockIdx.y * 32);
}

__global__ __launch_bounds__(256) void gemm192v2(const float* __restrict__ A,
                                                 const float* __restrict__ Bm,
                                                 float* __restrict__ Cm,
                                                 int aBatched, int bBatched, int transB) {
    int b = blockIdx.z;
    gemm_tile32(A + (aBatched ? b*CH*CH : 0),
                Bm + (bBatched ? b*CH*CH : 0),
                Cm + b*CH*CH, transB,
                blockIdx.x * 32, blockIdx.y * 32);
}

__global__ void bias_combine(const float* __restrict__ w_out, const float* __restrict__ b_proj) {
    int f = threadIdx.x;
    if (f < CH) {
        float s = 0.f;
        for (int o = 0; o < CH; ++o) s += w_out[f*CH+o] * b_proj[o];
        g_bp2[f] = s;
    }
}

// A2 fp32 -> bf16 hi/lo (once, instead of per-CTA in out_mma)
__global__ void a2_conv() {
    int idx = blockIdx.x * 256 + threadIdx.x;
    if (idx < NB*CH*CH) {
        float v = g_A2[idx];
        __nv_bfloat16 h = __float2bfloat16(v);
        __nv_bfloat16 l = __float2bfloat16(v - __bfloat162float(h));
        g_A2h[idx] = h;
        g_A2l[idx] = l;
    }
}

__global__ void diag_norms() {
    int b = blockIdx.x, which = blockIdx.y;
    int j = threadIdx.x;
    if (j >= CH) return;
    const float* W = which ? g_Wk : g_Wq;
    const float* T = (which ? g_T2 : g_T1) + (size_t)b*CH*CH;
    float s = 0.f;
    for (int m = 0; m < CH; ++m) s += W[j*CH+m] * T[m*CH+j];
    (which ? g_nk2 : g_nq2)[b*CH+j] = s;
}

__global__ void softmax_rows() {
    int b = blockIdx.y, i = blockIdx.x;
    int j = threadIdx.x;
    const float* Grow = g_G + ((size_t)b*CH + i)*CH;
    float dk = fmaxf(sqrtf(g_nk2[b*CH+i]), EPSN);
    float dq = fmaxf(sqrtf(g_nq2[b*CH+j]), EPSN);
    float L = Grow[j] / (dk*dq);
    __shared__ float redm[6], reds[6];
    float m = L;
    #pragma unroll
    for (int o = 16; o > 0; o >>= 1) m = fmaxf(m, __shfl_xor_sync(0xffffffffu, m, o));
    if ((j & 31) == 0) redm[j>>5] = m;
    __syncthreads();
    float mx = fmaxf(fmaxf(fmaxf(redm[0],redm[1]),fmaxf(redm[2],redm[3])),fmaxf(redm[4],redm[5]));
    float e = expf(L - mx);
    float s = e;
    #pragma unroll
    for (int o = 16; o > 0; o >>= 1) s += __shfl_xor_sync(0xffffffffu, s, o);
    if ((j & 31) == 0) reds[j>>5] = s;
    __syncthreads();
    float sum = reds[0]+reds[1]+reds[2]+reds[3]+reds[4]+reds[5];
    g_attn[((size_t)b*CH + i)*CH + j] = e / sum;
}

// ---------------- launch ----------------
extern "C" void kernel_launch(void* const* d_in, const int* in_sizes, int n_in,
                              void* d_out, int out_size) {
    const float* x_in   = (const float*)d_in[0];
    const float* w_split= (const float*)d_in[1];
    const float* w_q    = (const float*)d_in[2];
    const float* w_k    = (const float*)d_in[3];
    const float* w_v    = (const float*)d_in[4];
    const float* w_proj = (const float*)d_in[5];
    const float* b_proj = (const float*)d_in[6];
    const float* w_out  = (const float*)d_in[7];
    float* out = (float*)d_out;

    float *pWq, *pWk, *pWv, *pWp2, *pS, *pT1, *pT2, *pG, *pAttn, *pA1, *pA2;
    cudaGetSymbolAddress((void**)&pWq,  g_Wq);
    cudaGetSymbolAddress((void**)&pWk,  g_Wk);
    cudaGetSymbolAddress((void**)&pWv,  g_Wv);
    cudaGetSymbolAddress((void**)&pWp2, g_Wp2);
    cudaGetSymbolAddress((void**)&pS,   g_S);
    cudaGetSymbolAddress((void**)&pT1,  g_T1);
    cudaGetSymbolAddress((void**)&pT2,  g_T2);
    cudaGetSymbolAddress((void**)&pG,   g_G);
    cudaGetSymbolAddress((void**)&pAttn,g_attn);
    cudaGetSymbolAddress((void**)&pA1,  g_A1);
    cudaGetSymbolAddress((void**)&pA2,  g_A2);

    cudaFuncSetAttribute(xxt_mma, cudaFuncAttributeMaxDynamicSharedMemorySize, 147456);
    cudaFuncSetAttribute(out_mma, cudaFuncAttributeMaxDynamicSharedMemorySize, 163840);

    // M partials (tensor cores, split-K) — no deps on weights
    xxt_mma<<<dim3(KSPLIT1, NB), 512, 147456>>>(x_in);

    // combined channel maps (tiny)
    prep_weights<<<dim3(6,6,4), 256>>>(w_q, w_k, w_v, w_out, w_split, w_proj);
    bias_combine<<<1, 192>>>(w_out, b_proj);

    // S = sum (M + M^T), coalesced
    symm_reduce<<<dim3(6,6,NB), 256>>>();

    // Gram + norms in channel space
    t12_gemm<<<dim3(6,6,2*NB), 256>>>();                      // T1, T2 fused
    diag_norms<<<dim3(NB,2), 192>>>();
    gemm192v2<<<dim3(6,6,NB), 256>>>(pWk, pT1, pG,  0,1,0);   // G = Wk' T1

    softmax_rows<<<dim3(CH,NB), 192>>>();

    gemm192v2<<<dim3(6,6,NB), 256>>>(pWp2, pAttn, pA1, 0,1,0); // A1 = Wp2 attn
    gemm192v2<<<dim3(6,6,NB), 256>>>(pA1,  pWv,   pA2, 1,0,0); // A2 = A1 Wv'
    a2_conv<<<(NB*CH*CH + 255)/256, 256>>>();

    // out = A2 X + bp2 (tensor cores)
    out_mma<<<dim3(HW/128, NB), 512, 163840>>>(x_in, out);
}

// round 11
// speedup vs baseline: 2.7214x; 1.1557x over previous
#include <cuda_runtime.h>
#include <cuda_fp16.h>
#include <cstdint>

#define CH 192
#define NB 8
#define HW 16384
#define KSPLIT1 16
#define EPSN 1e-12f
#define A2SCALE 4096.0f
#define A2INV   (1.0f/4096.0f)

// ---------------- mma.sync / ldmatrix helpers (sm_80+ baseline PTX) ----------------
__device__ __forceinline__ uint32_t smem_u32(const void* p) {
    uint32_t a;
    asm("{ .reg .u64 t; cvta.to.shared.u64 t, %1; cvt.u32.u64 %0, t; }" : "=r"(a) : "l"(p));
    return a;
}
__device__ __forceinline__ void hmma16(float* d, const uint32_t* a, const uint32_t* b) {
    asm volatile("mma.sync.aligned.m16n8k16.row.col.f32.f16.f16.f32 "
        "{%0,%1,%2,%3}, {%4,%5,%6,%7}, {%8,%9}, {%0,%1,%2,%3};"
        : "+f"(d[0]), "+f"(d[1]), "+f"(d[2]), "+f"(d[3])
        : "r"(a[0]), "r"(a[1]), "r"(a[2]), "r"(a[3]), "r"(b[0]), "r"(b[1]));
}
__device__ __forceinline__ void ldsm4(uint32_t* r, uint32_t a) {
    asm volatile("ldmatrix.sync.aligned.m8n8.x4.shared.b16 {%0,%1,%2,%3}, [%4];"
        : "=r"(r[0]), "=r"(r[1]), "=r"(r[2]), "=r"(r[3]) : "r"(a));
}
__device__ __forceinline__ void ldsm4t(uint32_t* r, uint32_t a) {
    asm volatile("ldmatrix.sync.aligned.m8n8.x4.trans.shared.b16 {%0,%1,%2,%3}, [%4];"
        : "=r"(r[0]), "=r"(r[1]), "=r"(r[2]), "=r"(r[3]) : "r"(a));
}
__device__ __forceinline__ uint32_t f2h2(float x, float y) {
    __half2 h = __floats2half2_rn(x, y);
    return *reinterpret_cast<uint32_t*>(&h);
}

// ---------------- packed f32x2 helpers (small GEMMs) ----------------
__device__ __forceinline__ unsigned long long pack2(float lo, float hi) {
    unsigned long long r;
    asm("mov.b64 %0, {%1, %2};" : "=l"(r) : "f"(lo), "f"(hi));
    return r;
}
__device__ __forceinline__ void unpack2(unsigned long long v, float& lo, float& hi) {
    asm("mov.b64 {%0, %1}, %2;" : "=f"(lo), "=f"(hi) : "l"(v));
}
__device__ __forceinline__ void fma2(unsigned long long& d, unsigned long long a, unsigned long long b) {
    asm("fma.rn.f32x2 %0, %1, %2, %0;" : "+l"(d) : "l"(a), "l"(b));
}

// ---------------- scratch ----------------
__device__ float g_Wq[CH*CH], g_Wk[CH*CH], g_Wv[CH*CH], g_Wp2[CH*CH], g_bp2[CH];
__device__ float g_Spart[NB*KSPLIT1*CH*CH];
__device__ float g_S[NB*CH*CH], g_T1[NB*CH*CH], g_T2[NB*CH*CH];
__device__ float g_G[NB*CH*CH], g_attn[NB*CH*CH], g_A1[NB*CH*CH], g_A2[NB*CH*CH];
__device__ float g_nk2[NB*CH], g_nq2[NB*CH];
__device__ __half g_A2h[NB*CH*CH], g_A2l[NB*CH*CH];   // scaled by A2SCALE

// ============ GEMM1: S_p[b] = Xf Xf^T (fp16, single term), split-K ============
// grid (KSPLIT1, NB), 512 thr (16 warps, warp tile 48x48), dyn smem 49152
// stage: XF 192x64 fp16 (24576 B), x2 stages
__global__ __launch_bounds__(512) void xxt_mma(const float* __restrict__ xin) {
    extern __shared__ char smem[];
    const int tid = threadIdx.x, wid = tid >> 5, lane = tid & 31;
    const int split = blockIdx.x, b = blockIdx.y;
    const float* Xb = xin + (size_t)b * CH * HW;
    const int kbase = split * (HW / KSPLIT1);
    const uint32_t sb = smem_u32(smem);
    const int m0 = (wid >> 2) * 48, n0 = (wid & 3) * 48;

    float d[3][6][4];
    #pragma unroll
    for (int i = 0; i < 3; ++i)
        #pragma unroll
        for (int j = 0; j < 6; ++j)
            #pragma unroll
            for (int q = 0; q < 4; ++q) d[i][j][q] = 0.f;

    auto stage_load = [&](int buf, int kb) {
        char* XF = smem + buf * 24576;
        #pragma unroll
        for (int u = tid; u < 3072; u += 512) {
            int r = u >> 4, k4 = (u & 15) << 2;
            float4 v = *(const float4*)&Xb[(size_t)r * HW + kb + k4];
            int sw = r * 128 + (((u & 15) << 3) ^ ((r & 7) << 4));
            *(uint2*)(XF + sw) = make_uint2(f2h2(v.x, v.y), f2h2(v.z, v.w));
        }
    };

    const int xorv = (lane & 7) << 4;
    const int mat = lane >> 3;
    const int halfA = (lane >> 4) << 4;
    const int halfB = (mat & 1) << 4;
    const int rA15 = lane & 15;
    const int rB = ((mat >> 1) << 3) + (lane & 7);

    auto stage_compute = [&](int buf) {
        uint32_t base = sb + buf * 24576;
        #pragma unroll 1
        for (int kk = 0; kk < 4; ++kk) {
            int colA = ((kk << 5) + halfA) ^ xorv;
            int colB = ((kk << 5) + halfB) ^ xorv;
            uint32_t ah[3][4], bh[3][4];
            #pragma unroll
            for (int i = 0; i < 3; ++i)
                ldsm4(ah[i], base + (m0 + 16*i + rA15) * 128 + colA);
            #pragma unroll
            for (int jj = 0; jj < 3; ++jj)
                ldsm4(bh[jj], base + (n0 + jj*16 + rB) * 128 + colB);
            #pragma unroll
            for (int i = 0; i < 3; ++i)
                #pragma unroll
                for (int jj = 0; jj < 3; ++jj) {
                    hmma16(d[i][2*jj],     ah[i], &bh[jj][0]);
                    hmma16(d[i][2*jj + 1], ah[i], &bh[jj][2]);
                }
        }
    };

    stage_load(0, kbase);
    __syncthreads();
    for (int c = 0; c < 16; ++c) {
        if (c < 15) stage_load((c + 1) & 1, kbase + (c + 1) * 64);
        stage_compute(c & 1);
        __syncthreads();
    }

    float* Sp = g_Spart + (size_t)(b * KSPLIT1 + split) * CH * CH;
    int lr = lane >> 2, lc2 = (lane & 3) * 2;
    #pragma unroll
    for (int mi = 0; mi < 3; ++mi)
        #pragma unroll
        for (int nj = 0; nj < 6; ++nj) {
            int r = m0 + 16*mi + lr, cc = n0 + 8*nj + lc2;
            *(float2*)&Sp[r * CH + cc]       = make_float2(d[mi][nj][0], d[mi][nj][1]);
            *(float2*)&Sp[(r + 8) * CH + cc] = make_float2(d[mi][nj][2], d[mi][nj][3]);
        }
}

// S = sum_p S_p (coalesced; S_p already symmetric)
__global__ void s_reduce() {
    int idx = blockIdx.x * 256 + threadIdx.x;
    if (idx < NB*CH*CH) {
        int b = idx / (CH*CH), e = idx % (CH*CH);
        float s = 0.f;
        #pragma unroll
        for (int p = 0; p < KSPLIT1; ++p)
            s += g_Spart[(size_t)(b*KSPLIT1 + p)*CH*CH + e];
        g_S[idx] = s;
    }
}

// ============ GEMM2: out[b] = (A2h+A2l)·Xf * A2INV + bp2 via mma.sync ============
// grid (HW/128, NB), 512 thr (16 warps, warp tile 48x32), dyn smem 131072
// stage: A2H 192x64 (24576) | A2L (24576) | XF 64x128 (16384) = 65536, x2 stages
__global__ __launch_bounds__(512) void out_mma(const float* __restrict__ xin,
                                               float* __restrict__ out) {
    extern __shared__ char smem[];
    const int tid = threadIdx.x, wid = tid >> 5, lane = tid & 31;
    const int p0 = blockIdx.x * 128, b = blockIdx.y;
    const float* Xb = xin + (size_t)b * CH * HW;
    const uint32_t sb = smem_u32(smem);
    const int m0 = (wid >> 2) * 48, n0p = (wid & 3) * 32;

    float d[3][4][4];
    #pragma unroll
    for (int i = 0; i < 3; ++i)
        #pragma unroll
        for (int j = 0; j < 4; ++j)
            #pragma unroll
            for (int q = 0; q < 4; ++q) d[i][j][q] = 0.f;

    auto stage_load = [&](int buf, int c0) {
        char* base = smem + buf * 65536;
        char* A2H = base;
        char* A2L = base + 24576;
        char* XF  = base + 49152;
        #pragma unroll
        for (int u = tid; u < 1536; u += 512) {   // A2 (pre-split fp16): 192 co x 64 c
            int r = u >> 3, sg = u & 7;
            size_t ro = ((size_t)b * CH + r) * CH + c0 + sg * 8;
            uint4 vh = *(const uint4*)(g_A2h + ro);
            uint4 vl = *(const uint4*)(g_A2l + ro);
            int sw = r * 128 + ((sg << 4) ^ ((r & 7) << 4));
            *(uint4*)(A2H + sw) = vh;
            *(uint4*)(A2L + sw) = vl;
        }
        #pragma unroll
        for (int u = tid; u < 2048; u += 512) {   // X: 64 c x 128 p, fp16
            int r = u >> 5, p4 = (u & 31) << 2;
            float4 v = *(const float4*)&Xb[(size_t)(c0 + r) * HW + p0 + p4];
            int sw = r * 256 + (((u & 31) << 3) ^ ((r & 7) << 4));
            *(uint2*)(XF + sw) = make_uint2(f2h2(v.x, v.y), f2h2(v.z, v.w));
        }
    };

    const int xorv = (lane & 7) << 4;
    const int mat = lane >> 3;
    const int halfA = (lane >> 4) << 4;
    const int rA15 = lane & 15;
    const int rbX = ((mat & 1) << 3) + (lane & 7);     // X k-row within k16
    const int cbX = (n0p + ((mat >> 1) << 3)) * 2;     // X n-col bytes (+ jj*32)

    auto stage_compute = [&](int buf) {
        uint32_t baseAH = sb + buf * 65536;
        uint32_t baseAL = baseAH + 24576;
        uint32_t baseXF = baseAH + 49152;
        #pragma unroll 1
        for (int kk = 0; kk < 4; ++kk) {
            int colA = ((kk << 5) + halfA) ^ xorv;
            int xrow = (kk * 16 + rbX) * 256;
            uint32_t ah[3][4], al[3][4], bt[2][4];
            #pragma unroll
            for (int mi = 0; mi < 3; ++mi)
                ldsm4(ah[mi], baseAH + (m0 + 16*mi + rA15) * 128 + colA);
            #pragma unroll
            for (int jj = 0; jj < 2; ++jj)
                ldsm4t(bt[jj], baseXF + xrow + ((cbX + jj*32) ^ xorv));
            #pragma unroll
            for (int mi = 0; mi < 3; ++mi)
                #pragma unroll
                for (int jj = 0; jj < 2; ++jj) {
                    hmma16(d[mi][2*jj],     ah[mi], &bt[jj][0]);
                    hmma16(d[mi][2*jj + 1], ah[mi], &bt[jj][2]);
                }
            #pragma unroll
            for (int mi = 0; mi < 3; ++mi)
                ldsm4(al[mi], baseAL + (m0 + 16*mi + rA15) * 128 + colA);
            #pragma unroll
            for (int mi = 0; mi < 3; ++mi)
                #pragma unroll
                for (int jj = 0; jj < 2; ++jj) {
                    hmma16(d[mi][2*jj],     al[mi], &bt[jj][0]);
                    hmma16(d[mi][2*jj + 1], al[mi], &bt[jj][2]);
                }
        }
    };

    stage_load(0, 0);
    __syncthreads();
    for (int c = 0; c < 3; ++c) {
        if (c < 2) stage_load((c + 1) & 1, (c + 1) * 64);
        stage_compute(c & 1);
        __syncthreads();
    }

    // stage output through smem for coalesced stores
    float* so = (float*)smem;   // 192 x 132 floats = 101376 B
    int lr = lane >> 2, lc2 = (lane & 3) * 2;
    #pragma unroll
    for (int mi = 0; mi < 3; ++mi)
        #pragma unroll
        for (int nj = 0; nj < 4; ++nj) {
            int r = m0 + 16*mi + lr, cc = n0p + 8*nj + lc2;
            *(float2*)&so[r * 132 + cc]       = make_float2(d[mi][nj][0], d[mi][nj][1]);
            *(float2*)&so[(r + 8) * 132 + cc] = make_float2(d[mi][nj][2], d[mi][nj][3]);
        }
    __syncthreads();
    #pragma unroll
    for (int u = tid; u < 6144; u += 512) {
        int co = u >> 5, p4 = (u & 31) << 2;
        float4 v = *(const float4*)&so[co * 132 + p4];
        float bias = g_bp2[co];
        v.x = v.x * A2INV + bias;
        v.y = v.y * A2INV + bias;
        v.z = v.z * A2INV + bias;
        v.w = v.w * A2INV + bias;
        *(float4*)&out[((size_t)b * CH + co) * HW + p0 + p4] = v;
    }
}

// ---------------- small 192x192 GEMM core: 32x32 tile, 2x2/thread, FFMA2 ----------------
__device__ __forceinline__ void gemm_tile32(const float* __restrict__ Ab,
                                            const float* __restrict__ Bb,
                                            float* __restrict__ Cb,
                                            int transB, int i0, int j0) {
    __shared__ float As[16][34], Bs[16][34];
    int t = threadIdx.x;
    int tx = t & 15, ty = t >> 4;
    int li = t & 31, lkq = t >> 5;
    int lkb = t >> 4, lj2 = (t & 15) * 2;

    unsigned long long acc0 = 0ull, acc1 = 0ull;

    for (int kk = 0; kk < CH; kk += 16) {
        float2 av = *(const float2*)&Ab[(i0 + li) * CH + kk + lkq * 2];
        float2 bv;
        if (transB) bv = *(const float2*)&Bb[(j0 + li) * CH + kk + lkq * 2];
        else        bv = *(const float2*)&Bb[(kk + lkb) * CH + j0 + lj2];
        __syncthreads();
        As[lkq*2 + 0][li] = av.x;
        As[lkq*2 + 1][li] = av.y;
        if (transB) { Bs[lkq*2 + 0][li] = bv.x; Bs[lkq*2 + 1][li] = bv.y; }
        else        { *(float2*)&Bs[lkb][lj2] = bv; }
        __syncthreads();
        #pragma unroll
        for (int k = 0; k < 16; ++k) {
            float2 a2 = *(const float2*)&As[k][ty * 2];
            unsigned long long b2 = *(const unsigned long long*)&Bs[k][tx * 2];
            fma2(acc0, pack2(a2.x, a2.x), b2);
            fma2(acc1, pack2(a2.y, a2.y), b2);
        }
    }
    float o00, o01, o10, o11;
    unpack2(acc0, o00, o01);
    unpack2(acc1, o10, o11);
    *(float2*)&Cb[(i0 + ty*2 + 0) * CH + j0 + tx*2] = make_float2(o00, o01);
    *(float2*)&Cb[(i0 + ty*2 + 1) * CH + j0 + tx*2] = make_float2(o10, o11);
}

__global__ __launch_bounds__(256) void prep_weights(const float* __restrict__ wq,
                                                    const float* __restrict__ wk,
                                                    const float* __restrict__ wv,
                                                    const float* __restrict__ wout,
                                                    const float* __restrict__ wsplit,
                                                    const float* __restrict__ wproj) {
    const float *A, *B; float* C;
    switch (blockIdx.z) {
        case 0:  A = wq;   B = wsplit; C = g_Wq;  break;
        case 1:  A = wk;   B = wsplit; C = g_Wk;  break;
        case 2:  A = wv;   B = wsplit; C = g_Wv;  break;
        default: A = wout; B = wproj;  C = g_Wp2; break;
    }
    gemm_tile32(A, B, C, 0, blockIdx.x * 32, blockIdx.y * 32);
}

// T1 = S Wq'^T and T2 = S Wk'^T in one launch (z: b = z>>1, which = z&1)
__global__ __launch_bounds__(256) void t12_gemm() {
    int z = blockIdx.z;
    int b = z >> 1, which = z & 1;
    const float* W = which ? g_Wk : g_Wq;
    float* T = (which ? g_T2 : g_T1) + (size_t)b * CH * CH;
    gemm_tile32(g_S + (size_t)b * CH * CH, W, T, 1, blockIdx.x * 32, blockIdx.y * 32);
}

__global__ __launch_bounds__(256) void gemm192v2(const float* __restrict__ A,
                                                 const float* __restrict__ Bm,
                                                 float* __restrict__ Cm,
                                                 int aBatched, int bBatched, int transB) {
    int b = blockIdx.z;
    gemm_tile32(A + (aBatched ? b*CH*CH : 0),
                Bm + (bBatched ? b*CH*CH : 0),
                Cm + b*CH*CH, transB,
                blockIdx.x * 32, blockIdx.y * 32);
}

__global__ void bias_combine(const float* __restrict__ w_out, const float* __restrict__ b_proj) {
    int f = threadIdx.x;
    if (f < CH) {
        float s = 0.f;
        for (int o = 0; o < CH; ++o) s += w_out[f*CH+o] * b_proj[o];
        g_bp2[f] = s;
    }
}

// A2 fp32 -> scaled fp16 hi/lo
__global__ void a2_conv() {
    int idx = blockIdx.x * 256 + threadIdx.x;
    if (idx < NB*CH*CH) {
        float v = g_A2[idx] * A2SCALE;
        __half h = __float2half_rn(v);
        __half l = __float2half_rn(v - __half2float(h));
        g_A2h[idx] = h;
        g_A2l[idx] = l;
    }
}

__global__ void diag_norms() {
    int b = blockIdx.x, which = blockIdx.y;
    int j = threadIdx.x;
    if (j >= CH) return;
    const float* W = which ? g_Wk : g_Wq;
    const float* T = (which ? g_T2 : g_T1) + (size_t)b*CH*CH;
    float s = 0.f;
    for (int m = 0; m < CH; ++m) s += W[j*CH+m] * T[m*CH+j];
    (which ? g_nk2 : g_nq2)[b*CH+j] = s;
}

__global__ void softmax_rows() {
    int b = blockIdx.y, i = blockIdx.x;
    int j = threadIdx.x;
    const float* Grow = g_G + ((size_t)b*CH + i)*CH;
    float dk = fmaxf(sqrtf(g_nk2[b*CH+i]), EPSN);
    float dq = fmaxf(sqrtf(g_nq2[b*CH+j]), EPSN);
    float L = Grow[j] / (dk*dq);
    __shared__ float redm[6], reds[6];
    float m = L;
    #pragma unroll
    for (int o = 16; o > 0; o >>= 1) m = fmaxf(m, __shfl_xor_sync(0xffffffffu, m, o));
    if ((j & 31) == 0) redm[j>>5] = m;
    __syncthreads();
    float mx = fmaxf(fmaxf(fmaxf(redm[0],redm[1]),fmaxf(redm[2],redm[3])),fmaxf(redm[4],redm[5]));
    float e = expf(L - mx);
    float s = e;
    #pragma unroll
    for (int o = 16; o > 0; o >>= 1) s += __shfl_xor_sync(0xffffffffu, s, o);
    if ((j & 31) == 0) reds[j>>5] = s;
    __syncthreads();
    float sum = reds[0]+reds[1]+reds[2]+reds[3]+reds[4]+reds[5];
    g_attn[((size_t)b*CH + i)*CH + j] = e / sum;
}

// ---------------- launch ----------------
extern "C" void kernel_launch(void* const* d_in, const int* in_sizes, int n_in,
                              void* d_out, int out_size) {
    const float* x_in   = (const float*)d_in[0];
    const float* w_split= (const float*)d_in[1];
    const float* w_q    = (const float*)d_in[2];
    const float* w_k    = (const float*)d_in[3];
    const float* w_v    = (const float*)d_in[4];
    const float* w_proj = (const float*)d_in[5];
    const float* b_proj = (const float*)d_in[6];
    const float* w_out  = (const float*)d_in[7];
    float* out = (float*)d_out;

    float *pWq, *pWk, *pWv, *pWp2, *pS, *pT1, *pT2, *pG, *pAttn, *pA1, *pA2;
    cudaGetSymbolAddress((void**)&pWq,  g_Wq);
    cudaGetSymbolAddress((void**)&pWk,  g_Wk);
    cudaGetSymbolAddress((void**)&pWv,  g_Wv);
    cudaGetSymbolAddress((void**)&pWp2, g_Wp2);
    cudaGetSymbolAddress((void**)&pS,   g_S);
    cudaGetSymbolAddress((void**)&pT1,  g_T1);
    cudaGetSymbolAddress((void**)&pT2,  g_T2);
    cudaGetSymbolAddress((void**)&pG,   g_G);
    cudaGetSymbolAddress((void**)&pAttn,g_attn);
    cudaGetSymbolAddress((void**)&pA1,  g_A1);
    cudaGetSymbolAddress((void**)&pA2,  g_A2);

    cudaFuncSetAttribute(xxt_mma, cudaFuncAttributeMaxDynamicSharedMemorySize, 49152);
    cudaFuncSetAttribute(out_mma, cudaFuncAttributeMaxDynamicSharedMemorySize, 131072);

    // S partials (tensor cores, split-K, fp16 single-term) — no deps on weights
    xxt_mma<<<dim3(KSPLIT1, NB), 512, 49152>>>(x_in);

    // combined channel maps (tiny)
    prep_weights<<<dim3(6,6,4), 256>>>(w_q, w_k, w_v, w_out, w_split, w_proj);
    bias_combine<<<1, 192>>>(w_out, b_proj);

    // S = sum_p S_p
    s_reduce<<<(NB*CH*CH + 255)/256, 256>>>();

    // Gram + norms in channel space
    t12_gemm<<<dim3(6,6,2*NB), 256>>>();                      // T1, T2 fused
    diag_norms<<<dim3(NB,2), 192>>>();
    gemm192v2<<<dim3(6,6,NB), 256>>>(pWk, pT1, pG,  0,1,0);   // G = Wk' T1

    softmax_rows<<<dim3(CH,NB), 192>>>();

    gemm192v2<<<dim3(6,6,NB), 256>>>(pWp2, pAttn, pA1, 0,1,0); // A1 = Wp2 attn
    gemm192v2<<<dim3(6,6,NB), 256>>>(pA1,  pWv,   pA2, 1,0,0); // A2 = A1 Wv'
    a2_conv<<<(NB*CH*CH + 255)/256, 256>>>();

    // out = A2 X + bp2 (tensor cores, fp16 2-term)
    out_mma<<<dim3(HW/128, NB), 512, 131072>>>(x_in, out);
}

// round 12
// speedup vs baseline: 2.9845x; 1.0967x over previous
#include <cuda_runtime.h>
#include <cuda_fp16.h>
#include <cstdint>

#define CH 192
#define NB 8
#define HW 16384
#define KSPLIT1 16
#define EPSN 1e-12f
#define A2SCALE 4096.0f
#define A2INV   (1.0f/4096.0f)

// ---------------- mma.sync / ldmatrix helpers (sm_80+ baseline PTX) ----------------
__device__ __forceinline__ uint32_t smem_u32(const void* p) {
    uint32_t a;
    asm("{ .reg .u64 t; cvta.to.shared.u64 t, %1; cvt.u32.u64 %0, t; }" : "=r"(a) : "l"(p));
    return a;
}
__device__ __forceinline__ void hmma16(float* d, const uint32_t* a, const uint32_t* b) {
    asm volatile("mma.sync.aligned.m16n8k16.row.col.f32.f16.f16.f32 "
        "{%0,%1,%2,%3}, {%4,%5,%6,%7}, {%8,%9}, {%0,%1,%2,%3};"
        : "+f"(d[0]), "+f"(d[1]), "+f"(d[2]), "+f"(d[3])
        : "r"(a[0]), "r"(a[1]), "r"(a[2]), "r"(a[3]), "r"(b[0]), "r"(b[1]));
}
__device__ __forceinline__ void ldsm4(uint32_t* r, uint32_t a) {
    asm volatile("ldmatrix.sync.aligned.m8n8.x4.shared.b16 {%0,%1,%2,%3}, [%4];"
        : "=r"(r[0]), "=r"(r[1]), "=r"(r[2]), "=r"(r[3]) : "r"(a));
}
__device__ __forceinline__ void ldsm4t(uint32_t* r, uint32_t a) {
    asm volatile("ldmatrix.sync.aligned.m8n8.x4.trans.shared.b16 {%0,%1,%2,%3}, [%4];"
        : "=r"(r[0]), "=r"(r[1]), "=r"(r[2]), "=r"(r[3]) : "r"(a));
}
__device__ __forceinline__ uint32_t f2h2(float x, float y) {
    __half2 h = __floats2half2_rn(x, y);
    return *reinterpret_cast<uint32_t*>(&h);
}

// ---------------- packed f32x2 helpers (small GEMMs) ----------------
__device__ __forceinline__ unsigned long long pack2(float lo, float hi) {
    unsigned long long r;
    asm("mov.b64 %0, {%1, %2};" : "=l"(r) : "f"(lo), "f"(hi));
    return r;
}
__device__ __forceinline__ void unpack2(unsigned long long v, float& lo, float& hi) {
    asm("mov.b64 {%0, %1}, %2;" : "=f"(lo), "=f"(hi) : "l"(v));
}
__device__ __forceinline__ void fma2(unsigned long long& d, unsigned long long a, unsigned long long b) {
    asm("fma.rn.f32x2 %0, %1, %2, %0;" : "+l"(d) : "l"(a), "l"(b));
}

// ---------------- scratch ----------------
__device__ float g_Wq[CH*CH], g_Wk[CH*CH], g_Wv[CH*CH], g_Wp2[CH*CH], g_bp2[CH];
__device__ float g_Spart[NB*KSPLIT1*CH*CH];
__device__ float g_S[NB*CH*CH], g_T1[NB*CH*CH], g_T2[NB*CH*CH];
__device__ float g_G[NB*CH*CH], g_attn[NB*CH*CH], g_A1[NB*CH*CH];
__device__ float g_nk2[NB*CH], g_nq2[NB*CH];
__device__ __half g_A2h[NB*CH*CH];   // A2 * A2SCALE, fp16

// ============ GEMM1: S_p[b] = Xf Xf^T (fp16, single term), split-K ============
// grid (KSPLIT1, NB), 512 thr (16 warps, warp tile 48x48), dyn smem 49152
__global__ __launch_bounds__(512) void xxt_mma(const float* __restrict__ xin) {
    extern __shared__ char smem[];
    const int tid = threadIdx.x, wid = tid >> 5, lane = tid & 31;
    const int split = blockIdx.x, b = blockIdx.y;
    const float* Xb = xin + (size_t)b * CH * HW;
    const int kbase = split * (HW / KSPLIT1);
    const uint32_t sb = smem_u32(smem);
    const int m0 = (wid >> 2) * 48, n0 = (wid & 3) * 48;

    float d[3][6][4];
    #pragma unroll
    for (int i = 0; i < 3; ++i)
        #pragma unroll
        for (int j = 0; j < 6; ++j)
            #pragma unroll
            for (int q = 0; q < 4; ++q) d[i][j][q] = 0.f;

    auto stage_load = [&](int buf, int kb) {
        char* XF = smem + buf * 24576;
        #pragma unroll
        for (int u = tid; u < 3072; u += 512) {
            int r = u >> 4, k4 = (u & 15) << 2;
            float4 v = *(const float4*)&Xb[(size_t)r * HW + kb + k4];
            int sw = r * 128 + (((u & 15) << 3) ^ ((r & 7) << 4));
            *(uint2*)(XF + sw) = make_uint2(f2h2(v.x, v.y), f2h2(v.z, v.w));
        }
    };

    const int xorv = (lane & 7) << 4;
    const int mat = lane >> 3;
    const int halfA = (lane >> 4) << 4;
    const int halfB = (mat & 1) << 4;
    const int rA15 = lane & 15;
    const int rB = ((mat >> 1) << 3) + (lane & 7);

    auto stage_compute = [&](int buf) {
        uint32_t base = sb + buf * 24576;
        #pragma unroll 1
        for (int kk = 0; kk < 4; ++kk) {
            int colA = ((kk << 5) + halfA) ^ xorv;
            int colB = ((kk << 5) + halfB) ^ xorv;
            uint32_t ah[3][4], bh[3][4];
            #pragma unroll
            for (int i = 0; i < 3; ++i)
                ldsm4(ah[i], base + (m0 + 16*i + rA15) * 128 + colA);
            #pragma unroll
            for (int jj = 0; jj < 3; ++jj)
                ldsm4(bh[jj], base + (n0 + jj*16 + rB) * 128 + colB);
            #pragma unroll
            for (int i = 0; i < 3; ++i)
                #pragma unroll
                for (int jj = 0; jj < 3; ++jj) {
                    hmma16(d[i][2*jj],     ah[i], &bh[jj][0]);
                    hmma16(d[i][2*jj + 1], ah[i], &bh[jj][2]);
                }
        }
    };

    stage_load(0, kbase);
    __syncthreads();
    for (int c = 0; c < 16; ++c) {
        if (c < 15) stage_load((c + 1) & 1, kbase + (c + 1) * 64);
        stage_compute(c & 1);
        __syncthreads();
    }

    float* Sp = g_Spart + (size_t)(b * KSPLIT1 + split) * CH * CH;
    int lr = lane >> 2, lc2 = (lane & 3) * 2;
    #pragma unroll
    for (int mi = 0; mi < 3; ++mi)
        #pragma unroll
        for (int nj = 0; nj < 6; ++nj) {
            int r = m0 + 16*mi + lr, cc = n0 + 8*nj + lc2;
            *(float2*)&Sp[r * CH + cc]       = make_float2(d[mi][nj][0], d[mi][nj][1]);
            *(float2*)&Sp[(r + 8) * CH + cc] = make_float2(d[mi][nj][2], d[mi][nj][3]);
        }
}

// S = sum_p S_p (float4 vectorized)
__global__ void s_reduce() {
    int idx = blockIdx.x * 256 + threadIdx.x;   // over NB*CH*CH/4 = 73728
    if (idx < NB*CH*CH/4) {
        int b = idx / (CH*CH/4), e = idx % (CH*CH/4);
        const float4* Sp = (const float4*)(g_Spart + (size_t)b * KSPLIT1 * CH * CH) + e;
        float4 s = make_float4(0.f, 0.f, 0.f, 0.f);
        #pragma unroll
        for (int p = 0; p < KSPLIT1; ++p) {
            float4 v = Sp[p * (CH*CH/4)];
            s.x += v.x; s.y += v.y; s.z += v.z; s.w += v.w;
        }
        ((float4*)(g_S + (size_t)b * CH * CH))[e] = s;
    }
}

// ============ GEMM2: out[b] = A2f·Xf * A2INV + bp2 (single-term fp16) ============
// grid (HW/128, NB), 512 thr (16 warps, warp tile 48x32), dyn smem 101376
// stage: A2F 192x64 fp16 (24576) | XF 64x128 fp16 (16384) = 40960, x2 stages
__global__ __launch_bounds__(512) void out_mma(const float* __restrict__ xin,
                                               float* __restrict__ out) {
    extern __shared__ char smem[];
    const int tid = threadIdx.x, wid = tid >> 5, lane = tid & 31;
    const int p0 = blockIdx.x * 128, b = blockIdx.y;
    const float* Xb = xin + (size_t)b * CH * HW;
    const uint32_t sb = smem_u32(smem);
    const int m0 = (wid >> 2) * 48, n0p = (wid & 3) * 32;

    float d[3][4][4];
    #pragma unroll
    for (int i = 0; i < 3; ++i)
        #pragma unroll
        for (int j = 0; j < 4; ++j)
            #pragma unroll
            for (int q = 0; q < 4; ++q) d[i][j][q] = 0.f;

    auto stage_load = [&](int buf, int c0) {
        char* base = smem + buf * 40960;
        char* A2F = base;
        char* XF  = base + 24576;
        #pragma unroll
        for (int u = tid; u < 1536; u += 512) {   // A2 fp16: 192 co x 64 c
            int r = u >> 3, sg = u & 7;
            uint4 vh = *(const uint4*)(g_A2h + ((size_t)b * CH + r) * CH + c0 + sg * 8);
            int sw = r * 128 + ((sg << 4) ^ ((r & 7) << 4));
            *(uint4*)(A2F + sw) = vh;
        }
        #pragma unroll
        for (int u = tid; u < 2048; u += 512) {   // X: 64 c x 128 p, fp16
            int r = u >> 5, p4 = (u & 31) << 2;
            float4 v = *(const float4*)&Xb[(size_t)(c0 + r) * HW + p0 + p4];
            int sw = r * 256 + (((u & 31) << 3) ^ ((r & 7) << 4));
            *(uint2*)(XF + sw) = make_uint2(f2h2(v.x, v.y), f2h2(v.z, v.w));
        }
    };

    const int xorv = (lane & 7) << 4;
    const int mat = lane >> 3;
    const int halfA = (lane >> 4) << 4;
    const int rA15 = lane & 15;
    const int rbX = ((mat & 1) << 3) + (lane & 7);     // X k-row within k16
    const int cbX = (n0p + ((mat >> 1) << 3)) * 2;     // X n-col bytes (+ jj*32)

    auto stage_compute = [&](int buf) {
        uint32_t baseAF = sb + buf * 40960;
        uint32_t baseXF = baseAF + 24576;
        #pragma unroll 1
        for (int kk = 0; kk < 4; ++kk) {
            int colA = ((kk << 5) + halfA) ^ xorv;
            int xrow = (kk * 16 + rbX) * 256;
            uint32_t ah[3][4], bt[2][4];
            #pragma unroll
            for (int mi = 0; mi < 3; ++mi)
                ldsm4(ah[mi], baseAF + (m0 + 16*mi + rA15) * 128 + colA);
            #pragma unroll
            for (int jj = 0; jj < 2; ++jj)
                ldsm4t(bt[jj], baseXF + xrow + ((cbX + jj*32) ^ xorv));
            #pragma unroll
            for (int mi = 0; mi < 3; ++mi)
                #pragma unroll
                for (int jj = 0; jj < 2; ++jj) {
                    hmma16(d[mi][2*jj],     ah[mi], &bt[jj][0]);
                    hmma16(d[mi][2*jj + 1], ah[mi], &bt[jj][2]);
                }
        }
    };

    stage_load(0, 0);
    __syncthreads();
    for (int c = 0; c < 3; ++c) {
        if (c < 2) stage_load((c + 1) & 1, (c + 1) * 64);
        stage_compute(c & 1);
        __syncthreads();
    }

    // stage output through smem for coalesced stores
    float* so = (float*)smem;   // 192 x 132 floats = 101376 B
    int lr = lane >> 2, lc2 = (lane & 3) * 2;
    #pragma unroll
    for (int mi = 0; mi < 3; ++mi)
        #pragma unroll
        for (int nj = 0; nj < 4; ++nj) {
            int r = m0 + 16*mi + lr, cc = n0p + 8*nj + lc2;
            *(float2*)&so[r * 132 + cc]       = make_float2(d[mi][nj][0], d[mi][nj][1]);
            *(float2*)&so[(r + 8) * 132 + cc] = make_float2(d[mi][nj][2], d[mi][nj][3]);
        }
    __syncthreads();
    #pragma unroll
    for (int u = tid; u < 6144; u += 512) {
        int co = u >> 5, p4 = (u & 31) << 2;
        float4 v = *(const float4*)&so[co * 132 + p4];
        float bias = g_bp2[co];
        v.x = v.x * A2INV + bias;
        v.y = v.y * A2INV + bias;
        v.z = v.z * A2INV + bias;
        v.w = v.w * A2INV + bias;
        *(float4*)&out[((size_t)b * CH + co) * HW + p0 + p4] = v;
    }
}

// ---------------- small 192x192 GEMM core: 32x32 tile, 2x2/thread, FFMA2 ----------------
// Epilogue mode: 0 = fp32 store, 1 = scaled fp16 store to g_A2h
template <int EPI>
__device__ __forceinline__ void gemm_tile32(const float* __restrict__ Ab,
                                            const float* __restrict__ Bb,
                                            void* __restrict__ Cb,
                                            int transB, int i0, int j0) {
    __shared__ float As[16][34], Bs[16][34];
    int t = threadIdx.x;
    int tx = t & 15, ty = t >> 4;
    int li = t & 31, lkq = t >> 5;
    int lkb = t >> 4, lj2 = (t & 15) * 2;

    unsigned long long acc0 = 0ull, acc1 = 0ull;

    for (int kk = 0; kk < CH; kk += 16) {
        float2 av = *(const float2*)&Ab[(i0 + li) * CH + kk + lkq * 2];
        float2 bv;
        if (transB) bv = *(const float2*)&Bb[(j0 + li) * CH + kk + lkq * 2];
        else        bv = *(const float2*)&Bb[(kk + lkb) * CH + j0 + lj2];
        __syncthreads();
        As[lkq*2 + 0][li] = av.x;
        As[lkq*2 + 1][li] = av.y;
        if (transB) { Bs[lkq*2 + 0][li] = bv.x; Bs[lkq*2 + 1][li] = bv.y; }
        else        { *(float2*)&Bs[lkb][lj2] = bv; }
        __syncthreads();
        #pragma unroll
        for (int k = 0; k < 16; ++k) {
            float2 a2 = *(const float2*)&As[k][ty * 2];
            unsigned long long b2 = *(const unsigned long long*)&Bs[k][tx * 2];
            fma2(acc0, pack2(a2.x, a2.x), b2);
            fma2(acc1, pack2(a2.y, a2.y), b2);
        }
    }
    float o00, o01, o10, o11;
    unpack2(acc0, o00, o01);
    unpack2(acc1, o10, o11);
    if (EPI == 0) {
        float* C = (float*)Cb;
        *(float2*)&C[(i0 + ty*2 + 0) * CH + j0 + tx*2] = make_float2(o00, o01);
        *(float2*)&C[(i0 + ty*2 + 1) * CH + j0 + tx*2] = make_float2(o10, o11);
    } else {
        __half* C = (__half*)Cb;
        __half2 r0 = __floats2half2_rn(o00 * A2SCALE, o01 * A2SCALE);
        __half2 r1 = __floats2half2_rn(o10 * A2SCALE, o11 * A2SCALE);
        *(__half2*)&C[(i0 + ty*2 + 0) * CH + j0 + tx*2] = r0;
        *(__half2*)&C[(i0 + ty*2 + 1) * CH + j0 + tx*2] = r1;
    }
}

__global__ __launch_bounds__(256) void prep_weights(const float* __restrict__ wq,
                                                    const float* __restrict__ wk,
                                                    const float* __restrict__ wv,
                                                    const float* __restrict__ wout,
                                                    const float* __restrict__ wsplit,
                                                    const float* __restrict__ wproj) {
    const float *A, *B; float* C;
    switch (blockIdx.z) {
        case 0:  A = wq;   B = wsplit; C = g_Wq;  break;
        case 1:  A = wk;   B = wsplit; C = g_Wk;  break;
        case 2:  A = wv;   B = wsplit; C = g_Wv;  break;
        default: A = wout; B = wproj;  C = g_Wp2; break;
    }
    gemm_tile32<0>(A, B, C, 0, blockIdx.x * 32, blockIdx.y * 32);
}

// T1 = S Wq'^T and T2 = S Wk'^T in one launch (z: b = z>>1, which = z&1)
__global__ __launch_bounds__(256) void t12_gemm() {
    int z = blockIdx.z;
    int b = z >> 1, which = z & 1;
    const float* W = which ? g_Wk : g_Wq;
    float* T = (which ? g_T2 : g_T1) + (size_t)b * CH * CH;
    gemm_tile32<0>(g_S + (size_t)b * CH * CH, W, T, 1, blockIdx.x * 32, blockIdx.y * 32);
}

__global__ __launch_bounds__(256) void gemm192v2(const float* __restrict__ A,
                                                 const float* __restrict__ Bm,
                                                 float* __restrict__ Cm,
                                                 int aBatched, int bBatched, int transB) {
    int b = blockIdx.z;
    gemm_tile32<0>(A + (aBatched ? b*CH*CH : 0),
                   Bm + (bBatched ? b*CH*CH : 0),
                   Cm + b*CH*CH, transB,
                   blockIdx.x * 32, blockIdx.y * 32);
}

// A2 = A1·Wv' with fused scaled-fp16 epilogue -> g_A2h
__global__ __launch_bounds__(256) void a2_gemm() {
    int b = blockIdx.z;
    gemm_tile32<1>(g_A1 + (size_t)b * CH * CH, g_Wv,
                   g_A2h + (size_t)b * CH * CH, 0,
                   blockIdx.x * 32, blockIdx.y * 32);
}

__global__ void bias_combine(const float* __restrict__ w_out, const float* __restrict__ b_proj) {
    int f = threadIdx.x;
    if (f < CH) {
        float s = 0.f;
        for (int o = 0; o < CH; ++o) s += w_out[f*CH+o] * b_proj[o];
        g_bp2[f] = s;
    }
}

__global__ void diag_norms() {
    int b = blockIdx.x, which = blockIdx.y;
    int j = threadIdx.x;
    if (j >= CH) return;
    const float* W = which ? g_Wk : g_Wq;
    const float* T = (which ? g_T2 : g_T1) + (size_t)b*CH*CH;
    float s = 0.f;
    for (int m = 0; m < CH; ++m) s += W[j*CH+m] * T[m*CH+j];
    (which ? g_nk2 : g_nq2)[b*CH+j] = s;
}

__global__ void softmax_rows() {
    int b = blockIdx.y, i = blockIdx.x;
    int j = threadIdx.x;
    const float* Grow = g_G + ((size_t)b*CH + i)*CH;
    float dk = fmaxf(sqrtf(g_nk2[b*CH+i]), EPSN);
    float dq = fmaxf(sqrtf(g_nq2[b*CH+j]), EPSN);
    float L = Grow[j] / (dk*dq);
    __shared__ float redm[6], reds[6];
    float m = L;
    #pragma unroll
    for (int o = 16; o > 0; o >>= 1) m = fmaxf(m, __shfl_xor_sync(0xffffffffu, m, o));
    if ((j & 31) == 0) redm[j>>5] = m;
    __syncthreads();
    float mx = fmaxf(fmaxf(fmaxf(redm[0],redm[1]),fmaxf(redm[2],redm[3])),fmaxf(redm[4],redm[5]));
    float e = expf(L - mx);
    float s = e;
    #pragma unroll
    for (int o = 16; o > 0; o >>= 1) s += __shfl_xor_sync(0xffffffffu, s, o);
    if ((j & 31) == 0) reds[j>>5] = s;
    __syncthreads();
    float sum = reds[0]+reds[1]+reds[2]+reds[3]+reds[4]+reds[5];
    g_attn[((size_t)b*CH + i)*CH + j] = e / sum;
}

// ---------------- launch ----------------
extern "C" void kernel_launch(void* const* d_in, const int* in_sizes, int n_in,
                              void* d_out, int out_size) {
    const float* x_in   = (const float*)d_in[0];
    const float* w_split= (const float*)d_in[1];
    const float* w_q    = (const float*)d_in[2];
    const float* w_k    = (const float*)d_in[3];
    const float* w_v    = (const float*)d_in[4];
    const float* w_proj = (const float*)d_in[5];
    const float* b_proj = (const float*)d_in[6];
    const float* w_out  = (const float*)d_in[7];
    float* out = (float*)d_out;

    float *pWk, *pWp2, *pT1, *pG, *pAttn, *pA1;
    cudaGetSymbolAddress((void**)&pWk,  g_Wk);
    cudaGetSymbolAddress((void**)&pWp2, g_Wp2);
    cudaGetSymbolAddress((void**)&pT1,  g_T1);
    cudaGetSymbolAddress((void**)&pG,   g_G);
    cudaGetSymbolAddress((void**)&pAttn,g_attn);
    cudaGetSymbolAddress((void**)&pA1,  g_A1);

    cudaFuncSetAttribute(xxt_mma, cudaFuncAttributeMaxDynamicSharedMemorySize, 49152);
    cudaFuncSetAttribute(out_mma, cudaFuncAttributeMaxDynamicSharedMemorySize, 101376);

    // S partials (tensor cores, split-K, fp16 single-term) — no deps on weights
    xxt_mma<<<dim3(KSPLIT1, NB), 512, 49152>>>(x_in);

    // combined channel maps (tiny)
    prep_weights<<<dim3(6,6,4), 256>>>(w_q, w_k, w_v, w_out, w_split, w_proj);
    bias_combine<<<1, 192>>>(w_out, b_proj);

    // S = sum_p S_p
    s_reduce<<<(NB*CH*CH/4 + 255)/256, 256>>>();

    // Gram + norms in channel space
    t12_gemm<<<dim3(6,6,2*NB), 256>>>();                      // T1, T2 fused
    diag_norms<<<dim3(NB,2), 192>>>();
    gemm192v2<<<dim3(6,6,NB), 256>>>(pWk, pT1, pG,  0,1,0);   // G = Wk' T1

    softmax_rows<<<dim3(CH,NB), 192>>>();

    gemm192v2<<<dim3(6,6,NB), 256>>>(pWp2, pAttn, pA1, 0,1,0); // A1 = Wp2 attn
    a2_gemm<<<dim3(6,6,NB), 256>>>();                          // A2 (fp16 fused)

    // out = A2f X + bp2 (tensor cores, fp16 single-term)
    out_mma<<<dim3(HW/128, NB), 512, 101376>>>(x_in, out);
}

// round 13
// speedup vs baseline: 3.1698x; 1.0621x over previous
#include <cuda_runtime.h>
#include <cuda_fp16.h>
#include <cstdint>

#define CH 192
#define NB 8
#define HW 16384
#define KSPLIT1 16
#define EPSN 1e-12f
#define A2SCALE 4096.0f
#define A2INV   (1.0f/4096.0f)

// ---------------- mma.sync / ldmatrix helpers (sm_80+ baseline PTX) ----------------
__device__ __forceinline__ uint32_t smem_u32(const void* p) {
    uint32_t a;
    asm("{ .reg .u64 t; cvta.to.shared.u64 t, %1; cvt.u32.u64 %0, t; }" : "=r"(a) : "l"(p));
    return a;
}
__device__ __forceinline__ void hmma16(float* d, const uint32_t* a, const uint32_t* b) {
    asm volatile("mma.sync.aligned.m16n8k16.row.col.f32.f16.f16.f32 "
        "{%0,%1,%2,%3}, {%4,%5,%6,%7}, {%8,%9}, {%0,%1,%2,%3};"
        : "+f"(d[0]), "+f"(d[1]), "+f"(d[2]), "+f"(d[3])
        : "r"(a[0]), "r"(a[1]), "r"(a[2]), "r"(a[3]), "r"(b[0]), "r"(b[1]));
}
__device__ __forceinline__ void ldsm4(uint32_t* r, uint32_t a) {
    asm volatile("ldmatrix.sync.aligned.m8n8.x4.shared.b16 {%0,%1,%2,%3}, [%4];"
        : "=r"(r[0]), "=r"(r[1]), "=r"(r[2]), "=r"(r[3]) : "r"(a));
}
__device__ __forceinline__ void ldsm4t(uint32_t* r, uint32_t a) {
    asm volatile("ldmatrix.sync.aligned.m8n8.x4.trans.shared.b16 {%0,%1,%2,%3}, [%4];"
        : "=r"(r[0]), "=r"(r[1]), "=r"(r[2]), "=r"(r[3]) : "r"(a));
}
__device__ __forceinline__ uint32_t f2h2(float x, float y) {
    __half2 h = __floats2half2_rn(x, y);
    return *reinterpret_cast<uint32_t*>(&h);
}

// ---------------- packed f32x2 helpers (small GEMMs) ----------------
__device__ __forceinline__ unsigned long long pack2(float lo, float hi) {
    unsigned long long r;
    asm("mov.b64 %0, {%1, %2};" : "=l"(r) : "f"(lo), "f"(hi));
    return r;
}
__device__ __forceinline__ void unpack2(unsigned long long v, float& lo, float& hi) {
    asm("mov.b64 {%0, %1}, %2;" : "=f"(lo), "=f"(hi) : "l"(v));
}
__device__ __forceinline__ void fma2(unsigned long long& d, unsigned long long a, unsigned long long b) {
    asm("fma.rn.f32x2 %0, %1, %2, %0;" : "+l"(d) : "l"(a), "l"(b));
}

// ---------------- scratch ----------------
__device__ float g_Wq[CH*CH], g_Wk[CH*CH], g_Wv[CH*CH], g_Wp2[CH*CH], g_bp2[CH];
__device__ float g_Spart[NB*KSPLIT1*CH*CH];
__device__ float g_S[NB*CH*CH], g_T1[NB*CH*CH], g_T2[NB*CH*CH];
__device__ float g_attn[NB*CH*CH], g_A1[NB*CH*CH];
__device__ float g_nk2[NB*CH], g_nq2[NB*CH];
__device__ __half g_A2h[NB*CH*CH];      // A2 * A2SCALE, fp16
__device__ __half g_Xf[(size_t)NB*CH*HW];  // X in fp16 (written by xxt_mma)

// ============ GEMM1: S_p[b] = Xf Xf^T (fp16, single term), split-K ============
// grid (KSPLIT1, NB), 512 thr (16 warps, warp tile 48x48), dyn smem 49152
// Register-prefetch pipeline: LDG(next) -> compute(cur) -> cvt+STS(next) -> bar
__global__ __launch_bounds__(512) void xxt_mma(const float* __restrict__ xin) {
    extern __shared__ char smem[];
    const int tid = threadIdx.x, wid = tid >> 5, lane = tid & 31;
    const int split = blockIdx.x, b = blockIdx.y;
    const float* Xb = xin + (size_t)b * CH * HW;
    const int kbase = split * (HW / KSPLIT1);
    const uint32_t sb = smem_u32(smem);
    const int m0 = (wid >> 2) * 48, n0 = (wid & 3) * 48;

    float d[3][6][4];
    #pragma unroll
    for (int i = 0; i < 3; ++i)
        #pragma unroll
        for (int j = 0; j < 6; ++j)
            #pragma unroll
            for (int q = 0; q < 4; ++q) d[i][j][q] = 0.f;

    auto ldx = [&](float4* v, int kb) {
        #pragma unroll
        for (int i = 0; i < 6; ++i) {
            int u = tid + (i << 9);
            int r = u >> 4, k4 = (u & 15) << 2;
            v[i] = *(const float4*)&Xb[(size_t)r * HW + kb + k4];
        }
    };
    auto stx = [&](const float4* v, int buf, int kb) {
        char* XF = smem + buf * 24576;
        #pragma unroll
        for (int i = 0; i < 6; ++i) {
            int u = tid + (i << 9);
            int r = u >> 4, k4 = (u & 15) << 2;
            uint2 hw = make_uint2(f2h2(v[i].x, v[i].y), f2h2(v[i].z, v[i].w));
            int sw = r * 128 + (((u & 15) << 3) ^ ((r & 7) << 4));
            *(uint2*)(XF + sw) = hw;
            *(uint2*)&g_Xf[((size_t)b * CH + r) * HW + kb + k4] = hw;  // fp16 X for out_mma
        }
    };

    const int xorv = (lane & 7) << 4;
    const int mat = lane >> 3;
    const int halfA = (lane >> 4) << 4;
    const int halfB = (mat & 1) << 4;
    const int rA15 = lane & 15;
    const int rB = ((mat >> 1) << 3) + (lane & 7);

    auto stage_compute = [&](int buf) {
        uint32_t base = sb + buf * 24576;
        #pragma unroll 1
        for (int kk = 0; kk < 4; ++kk) {
            int colA = ((kk << 5) + halfA) ^ xorv;
            int colB = ((kk << 5) + halfB) ^ xorv;
            uint32_t ah[3][4], bh[3][4];
            #pragma unroll
            for (int i = 0; i < 3; ++i)
                ldsm4(ah[i], base + (m0 + 16*i + rA15) * 128 + colA);
            #pragma unroll
            for (int jj = 0; jj < 3; ++jj)
                ldsm4(bh[jj], base + (n0 + jj*16 + rB) * 128 + colB);
            #pragma unroll
            for (int i = 0; i < 3; ++i)
                #pragma unroll
                for (int jj = 0; jj < 3; ++jj) {
                    hmma16(d[i][2*jj],     ah[i], &bh[jj][0]);
                    hmma16(d[i][2*jj + 1], ah[i], &bh[jj][2]);
                }
        }
    };

    {
        float4 v0[6];
        ldx(v0, kbase);
        stx(v0, 0, kbase);
    }
    __syncthreads();
    for (int c = 0; c < 16; ++c) {
        float4 vn[6];
        if (c < 15) ldx(vn, kbase + (c + 1) * 64);   // LDG issued, result not touched yet
        stage_compute(c & 1);                         // hides LDG latency
        if (c < 15) stx(vn, (c + 1) & 1, kbase + (c + 1) * 64);
        __syncthreads();
    }

    float* Sp = g_Spart + (size_t)(b * KSPLIT1 + split) * CH * CH;
    int lr = lane >> 2, lc2 = (lane & 3) * 2;
    #pragma unroll
    for (int mi = 0; mi < 3; ++mi)
        #pragma unroll
        for (int nj = 0; nj < 6; ++nj) {
            int r = m0 + 16*mi + lr, cc = n0 + 8*nj + lc2;
            *(float2*)&Sp[r * CH + cc]       = make_float2(d[mi][nj][0], d[mi][nj][1]);
            *(float2*)&Sp[(r + 8) * CH + cc] = make_float2(d[mi][nj][2], d[mi][nj][3]);
        }
}

// S = sum_p S_p (float4 vectorized)
__global__ void s_reduce() {
    int idx = blockIdx.x * 256 + threadIdx.x;   // over NB*CH*CH/4 = 73728
    if (idx < NB*CH*CH/4) {
        int b = idx / (CH*CH/4), e = idx % (CH*CH/4);
        const float4* Sp = (const float4*)(g_Spart + (size_t)b * KSPLIT1 * CH * CH) + e;
        float4 s = make_float4(0.f, 0.f, 0.f, 0.f);
        #pragma unroll
        for (int p = 0; p < KSPLIT1; ++p) {
            float4 v = Sp[p * (CH*CH/4)];
            s.x += v.x; s.y += v.y; s.z += v.z; s.w += v.w;
        }
        ((float4*)(g_S + (size_t)b * CH * CH))[e] = s;
    }
}

// ============ GEMM2: out[b] = A2f·Xf * A2INV + bp2 (single-term fp16) ============
// grid (HW/128, NB), 512 thr (16 warps, warp tile 48x32), dyn smem 101376
// stage: A2F 192x64 fp16 (24576) | XF 64x128 fp16 (16384) = 40960, x2 stages
__global__ __launch_bounds__(512) void out_mma(float* __restrict__ out) {
    extern __shared__ char smem[];
    const int tid = threadIdx.x, wid = tid >> 5, lane = tid & 31;
    const int p0 = blockIdx.x * 128, b = blockIdx.y;
    const uint32_t sb = smem_u32(smem);
    const int m0 = (wid >> 2) * 48, n0p = (wid & 3) * 32;

    float d[3][4][4];
    #pragma unroll
    for (int i = 0; i < 3; ++i)
        #pragma unroll
        for (int j = 0; j < 4; ++j)
            #pragma unroll
            for (int q = 0; q < 4; ++q) d[i][j][q] = 0.f;

    auto ldstage = [&](uint4* va, uint4* vx, int c0) {
        #pragma unroll
        for (int i = 0; i < 3; ++i) {          // A2 fp16: 192 co x 64 c
            int u = tid + (i << 9);
            int r = u >> 3, sg = u & 7;
            va[i] = *(const uint4*)&g_A2h[((size_t)b * CH + r) * CH + c0 + sg * 8];
        }
        #pragma unroll
        for (int i = 0; i < 2; ++i) {          // Xf fp16: 64 c x 128 p
            int u = tid + (i << 9);
            int r = u >> 4, c8 = (u & 15) << 3;
            vx[i] = *(const uint4*)&g_Xf[((size_t)b * CH + c0 + r) * HW + p0 + c8];
        }
    };
    auto ststage = [&](const uint4* va, const uint4* vx, int buf) {
        char* A2F = smem + buf * 40960;
        char* XF  = A2F + 24576;
        #pragma unroll
        for (int i = 0; i < 3; ++i) {
            int u = tid + (i << 9);
            int r = u >> 3, sg = u & 7;
            int sw = r * 128 + ((sg << 4) ^ ((r & 7) << 4));
            *(uint4*)(A2F + sw) = va[i];
        }
        #pragma unroll
        for (int i = 0; i < 2; ++i) {
            int u = tid + (i << 9);
            int r = u >> 4;
            int sw = r * 256 + ((((u & 15)) << 4) ^ ((r & 7) << 4));
            *(uint4*)(XF + sw) = vx[i];
        }
    };

    const int xorv = (lane & 7) << 4;
    const int mat = lane >> 3;
    const int halfA = (lane >> 4) << 4;
    const int rA15 = lane & 15;
    const int rbX = ((mat & 1) << 3) + (lane & 7);     // X k-row within k16
    const int cbX = (n0p + ((mat >> 1) << 3)) * 2;     // X n-col bytes (+ jj*32)

    auto stage_compute = [&](int buf) {
        uint32_t baseAF = sb + buf * 40960;
        uint32_t baseXF = baseAF + 24576;
        #pragma unroll 1
        for (int kk = 0; kk < 4; ++kk) {
            int colA = ((kk << 5) + halfA) ^ xorv;
            int xrow = (kk * 16 + rbX) * 256;
            uint32_t ah[3][4], bt[2][4];
            #pragma unroll
            for (int mi = 0; mi < 3; ++mi)
                ldsm4(ah[mi], baseAF + (m0 + 16*mi + rA15) * 128 + colA);
            #pragma unroll
            for (int jj = 0; jj < 2; ++jj)
                ldsm4t(bt[jj], baseXF + xrow + ((cbX + jj*32) ^ xorv));
            #pragma unroll
            for (int mi = 0; mi < 3; ++mi)
                #pragma unroll
                for (int jj = 0; jj < 2; ++jj) {
                    hmma16(d[mi][2*jj],     ah[mi], &bt[jj][0]);
                    hmma16(d[mi][2*jj + 1], ah[mi], &bt[jj][2]);
                }
        }
    };

    {
        uint4 va0[3], vx0[2];
        ldstage(va0, vx0, 0);
        ststage(va0, vx0, 0);
    }
    __syncthreads();
    for (int c = 0; c < 3; ++c) {
        uint4 va[3], vx[2];
        if (c < 2) ldstage(va, vx, (c + 1) * 64);
        stage_compute(c & 1);
        if (c < 2) ststage(va, vx, (c + 1) & 1);
        __syncthreads();
    }

    // stage output through smem for coalesced stores
    float* so = (float*)smem;   // 192 x 132 floats = 101376 B
    int lr = lane >> 2, lc2 = (lane & 3) * 2;
    #pragma unroll
    for (int mi = 0; mi < 3; ++mi)
        #pragma unroll
        for (int nj = 0; nj < 4; ++nj) {
            int r = m0 + 16*mi + lr, cc = n0p + 8*nj + lc2;
            *(float2*)&so[r * 132 + cc]       = make_float2(d[mi][nj][0], d[mi][nj][1]);
            *(float2*)&so[(r + 8) * 132 + cc] = make_float2(d[mi][nj][2], d[mi][nj][3]);
        }
    __syncthreads();
    #pragma unroll
    for (int u = tid; u < 6144; u += 512) {
        int co = u >> 5, p4 = (u & 31) << 2;
        float4 v = *(const float4*)&so[co * 132 + p4];
        float bias = g_bp2[co];
        v.x = v.x * A2INV + bias;
        v.y = v.y * A2INV + bias;
        v.z = v.z * A2INV + bias;
        v.w = v.w * A2INV + bias;
        *(float4*)&out[((size_t)b * CH + co) * HW + p0 + p4] = v;
    }
}

// ---------------- small 192x192 GEMM core: 32x32 tile, 2x2/thread, FFMA2 ----------------
// Epilogue mode: 0 = fp32 store, 1 = scaled fp16 store
template <int EPI>
__device__ __forceinline__ void gemm_tile32(const float* __restrict__ Ab,
                                            const float* __restrict__ Bb,
                                            void* __restrict__ Cb,
                                            int transB, int i0, int j0) {
    __shared__ float As[16][34], Bs[16][34];
    int t = threadIdx.x;
    int tx = t & 15, ty = t >> 4;
    int li = t & 31, lkq = t >> 5;
    int lkb = t >> 4, lj2 = (t & 15) * 2;

    unsigned long long acc0 = 0ull, acc1 = 0ull;

    for (int kk = 0; kk < CH; kk += 16) {
        float2 av = *(const float2*)&Ab[(i0 + li) * CH + kk + lkq * 2];
        float2 bv;
        if (transB) bv = *(const float2*)&Bb[(j0 + li) * CH + kk + lkq * 2];
        else        bv = *(const float2*)&Bb[(kk + lkb) * CH + j0 + lj2];
        __syncthreads();
        As[lkq*2 + 0][li] = av.x;
        As[lkq*2 + 1][li] = av.y;
        if (transB) { Bs[lkq*2 + 0][li] = bv.x; Bs[lkq*2 + 1][li] = bv.y; }
        else        { *(float2*)&Bs[lkb][lj2] = bv; }
        __syncthreads();
        #pragma unroll
        for (int k = 0; k < 16; ++k) {
            float2 a2 = *(const float2*)&As[k][ty * 2];
            unsigned long long b2 = *(const unsigned long long*)&Bs[k][tx * 2];
            fma2(acc0, pack2(a2.x, a2.x), b2);
            fma2(acc1, pack2(a2.y, a2.y), b2);
        }
    }
    float o00, o01, o10, o11;
    unpack2(acc0, o00, o01);
    unpack2(acc1, o10, o11);
    if (EPI == 0) {
        float* C = (float*)Cb;
        *(float2*)&C[(i0 + ty*2 + 0) * CH + j0 + tx*2] = make_float2(o00, o01);
        *(float2*)&C[(i0 + ty*2 + 1) * CH + j0 + tx*2] = make_float2(o10, o11);
    } else {
        __half* C = (__half*)Cb;
        __half2 r0 = __floats2half2_rn(o00 * A2SCALE, o01 * A2SCALE);
        __half2 r1 = __floats2half2_rn(o10 * A2SCALE, o11 * A2SCALE);
        *(__half2*)&C[(i0 + ty*2 + 0) * CH + j0 + tx*2] = r0;
        *(__half2*)&C[(i0 + ty*2 + 1) * CH + j0 + tx*2] = r1;
    }
}

__global__ __launch_bounds__(256) void prep_weights(const float* __restrict__ wq,
                                                    const float* __restrict__ wk,
                                                    const float* __restrict__ wv,
                                                    const float* __restrict__ wout,
                                                    const float* __restrict__ wsplit,
                                                    const float* __restrict__ wproj) {
    const float *A, *B; float* C;
    switch (blockIdx.z) {
        case 0:  A = wq;   B = wsplit; C = g_Wq;  break;
        case 1:  A = wk;   B = wsplit; C = g_Wk;  break;
        case 2:  A = wv;   B = wsplit; C = g_Wv;  break;
        default: A = wout; B = wproj;  C = g_Wp2; break;
    }
    gemm_tile32<0>(A, B, C, 0, blockIdx.x * 32, blockIdx.y * 32);
}

// T1 = S Wq'^T and T2 = S Wk'^T in one launch (z: b = z>>1, which = z&1)
__global__ __launch_bounds__(256) void t12_gemm() {
    int z = blockIdx.z;
    int b = z >> 1, which = z & 1;
    const float* W = which ? g_Wk : g_Wq;
    float* T = (which ? g_T2 : g_T1) + (size_t)b * CH * CH;
    gemm_tile32<0>(g_S + (size_t)b * CH * CH, W, T, 1, blockIdx.x * 32, blockIdx.y * 32);
}

__global__ __launch_bounds__(256) void gemm192v2(const float* __restrict__ A,
                                                 const float* __restrict__ Bm,
                                                 float* __restrict__ Cm,
                                                 int aBatched, int bBatched, int transB) {
    int b = blockIdx.z;
    gemm_tile32<0>(A + (aBatched ? b*CH*CH : 0),
                   Bm + (bBatched ? b*CH*CH : 0),
                   Cm + b*CH*CH, transB,
                   blockIdx.x * 32, blockIdx.y * 32);
}

// A2 = A1·Wv' with fused scaled-fp16 epilogue -> g_A2h
__global__ __launch_bounds__(256) void a2_gemm() {
    int b = blockIdx.z;
    gemm_tile32<1>(g_A1 + (size_t)b * CH * CH, g_Wv,
                   g_A2h + (size_t)b * CH * CH, 0,
                   blockIdx.x * 32, blockIdx.y * 32);
}

__global__ void bias_combine(const float* __restrict__ w_out, const float* __restrict__ b_proj) {
    int f = threadIdx.x;
    if (f < CH) {
        float s = 0.f;
        for (int o = 0; o < CH; ++o) s += w_out[f*CH+o] * b_proj[o];
        g_bp2[f] = s;
    }
}

__global__ void diag_norms() {
    int b = blockIdx.x, which = blockIdx.y;
    int j = threadIdx.x;
    if (j >= CH) return;
    const float* W = which ? g_Wk : g_Wq;
    const float* T = (which ? g_T2 : g_T1) + (size_t)b*CH*CH;
    float s = 0.f;
    for (int m = 0; m < CH; ++m) s += W[j*CH+m] * T[m*CH+j];
    (which ? g_nk2 : g_nq2)[b*CH+j] = s;
}

// ============ Fused: G-rows (32x192 tile of Wk'·T1) + softmax -> attn ============
// grid (6, NB), 256 thr
__global__ __launch_bounds__(256) void g_softmax() {
    __shared__ float As[16][33];    // Wk' block, [k][row]
    __shared__ float Bs[16][196];   // T1 block,  [k][col]
    __shared__ float Gs[32][196];
    __shared__ float sdq[CH];
    const int b = blockIdx.y, i0 = blockIdx.x * 32;
    const int tid = threadIdx.x;
    const int tx = tid & 31, ty = tid >> 5;
    const float* T1b = g_T1 + (size_t)b * CH * CH;

    unsigned long long acc[4][3];
    #pragma unroll
    for (int q = 0; q < 4; ++q)
        #pragma unroll
        for (int s = 0; s < 3; ++s) acc[q][s] = 0ull;

    for (int kk = 0; kk < CH; kk += 16) {
        {
            int r = tid >> 3, k2 = (tid & 7) * 2;
            float2 w = *(const float2*)&g_Wk[(i0 + r) * CH + kk + k2];
            As[k2][r] = w.x;
            As[k2 + 1][r] = w.y;
        }
        #pragma unroll
        for (int s = 0; s < 3; ++s) {
            int lin = s * 256 + tid;
            int kr = lin / 48, c4 = (lin % 48) * 4;
            *(float4*)&Bs[kr][c4] = *(const float4*)&T1b[(kk + kr) * CH + c4];
        }
        __syncthreads();
        #pragma unroll
        for (int k = 0; k < 16; ++k) {
            float a0 = As[k][ty], a1 = As[k][ty + 8], a2 = As[k][ty + 16], a3 = As[k][ty + 24];
            unsigned long long b0 = *(const unsigned long long*)&Bs[k][tx * 2];
            unsigned long long b1 = *(const unsigned long long*)&Bs[k][tx * 2 + 64];
            unsigned long long b2 = *(const unsigned long long*)&Bs[k][tx * 2 + 128];
            fma2(acc[0][0], pack2(a0, a0), b0); fma2(acc[0][1], pack2(a0, a0), b1); fma2(acc[0][2], pack2(a0, a0), b2);
            fma2(acc[1][0], pack2(a1, a1), b0); fma2(acc[1][1], pack2(a1, a1), b1); fma2(acc[1][2], pack2(a1, a1), b2);
            fma2(acc[2][0], pack2(a2, a2), b0); fma2(acc[2][1], pack2(a2, a2), b1); fma2(acc[2][2], pack2(a2, a2), b2);
            fma2(acc[3][0], pack2(a3, a3), b0); fma2(acc[3][1], pack2(a3, a3), b1); fma2(acc[3][2], pack2(a3, a3), b2);
        }
        __syncthreads();
    }
    #pragma unroll
    for (int q = 0; q < 4; ++q)
        #pragma unroll
        for (int s = 0; s < 3; ++s) {
            float lo, hi;
            unpack2(acc[q][s], lo, hi);
            Gs[ty + 8*q][tx * 2 + s * 64]     = lo;
            Gs[ty + 8*q][tx * 2 + s * 64 + 1] = hi;
        }
    if (tid < CH) sdq[tid] = fmaxf(sqrtf(g_nq2[b * CH + tid]), EPSN);
    __syncthreads();

    // softmax: warp w handles rows 4w..4w+3
    const int w = tid >> 5, lane = tid & 31;
    #pragma unroll
    for (int rr = 0; rr < 4; ++rr) {
        int row = w * 4 + rr;
        float dk = fmaxf(sqrtf(g_nk2[b * CH + i0 + row]), EPSN);
        float L[6];
        #pragma unroll
        for (int t = 0; t < 6; ++t)
            L[t] = Gs[row][lane + 32 * t] / (dk * sdq[lane + 32 * t]);
        float m = L[0];
        #pragma unroll
        for (int t = 1; t < 6; ++t) m = fmaxf(m, L[t]);
        #pragma unroll
        for (int o = 16; o > 0; o >>= 1) m = fmaxf(m, __shfl_xor_sync(0xffffffffu, m, o));
        float e[6], sum = 0.f;
        #pragma unroll
        for (int t = 0; t < 6; ++t) { e[t] = expf(L[t] - m); sum += e[t]; }
        #pragma unroll
        for (int o = 16; o > 0; o >>= 1) sum += __shfl_xor_sync(0xffffffffu, sum, o);
        float inv = 1.f / sum;
        #pragma unroll
        for (int t = 0; t < 6; ++t)
            g_attn[((size_t)b * CH + i0 + row) * CH + lane + 32 * t] = e[t] * inv;
    }
}

// ---------------- launch ----------------
extern "C" void kernel_launch(void* const* d_in, const int* in_sizes, int n_in,
                              void* d_out, int out_size) {
    const float* x_in   = (const float*)d_in[0];
    const float* w_split= (const float*)d_in[1];
    const float* w_q    = (const float*)d_in[2];
    const float* w_k    = (const float*)d_in[3];
    const float* w_v    = (const float*)d_in[4];
    const float* w_proj = (const float*)d_in[5];
    const float* b_proj = (const float*)d_in[6];
    const float* w_out  = (const float*)d_in[7];
    float* out = (float*)d_out;

    float *pWp2, *pAttn, *pA1;
    cudaGetSymbolAddress((void**)&pWp2, g_Wp2);
    cudaGetSymbolAddress((void**)&pAttn,g_attn);
    cudaGetSymbolAddress((void**)&pA1,  g_A1);

    cudaFuncSetAttribute(xxt_mma, cudaFuncAttributeMaxDynamicSharedMemorySize, 49152);
    cudaFuncSetAttribute(out_mma, cudaFuncAttributeMaxDynamicSharedMemorySize, 101376);

    // S partials (tensor cores, split-K, fp16 single-term); also emits g_Xf
    xxt_mma<<<dim3(KSPLIT1, NB), 512, 49152>>>(x_in);

    // combined channel maps (tiny)
    prep_weights<<<dim3(6,6,4), 256>>>(w_q, w_k, w_v, w_out, w_split, w_proj);
    bias_combine<<<1, 192>>>(w_out, b_proj);

    // S = sum_p S_p
    s_reduce<<<(NB*CH*CH/4 + 255)/256, 256>>>();

    // Gram + norms in channel space
    t12_gemm<<<dim3(6,6,2*NB), 256>>>();          // T1, T2 fused
    diag_norms<<<dim3(NB,2), 192>>>();
    g_softmax<<<dim3(6,NB), 256>>>();             // G + softmax fused -> attn

    gemm192v2<<<dim3(6,6,NB), 256>>>(pWp2, pAttn, pA1, 0,1,0); // A1 = Wp2 attn
    a2_gemm<<<dim3(6,6,NB), 256>>>();                          // A2 (fp16 fused)

    // out = A2f Xf + bp2 (tensor cores, fp16 single-term)
    out_mma<<<dim3(HW/128, NB), 512, 101376>>>(out);
}

// round 14
// speedup vs baseline: 3.1748x; 1.0016x over previous
#include <cuda_runtime.h>
#include <cuda_fp16.h>
#include <cstdint>

#define CH 192
#define NB 8
#define HW 16384
#define KSPLIT1 16
#define EPSN 1e-12f
#define A2SCALE 4096.0f
#define A2INV   (1.0f/4096.0f)

// ---------------- mma.sync / ldmatrix helpers (sm_80+ baseline PTX) ----------------
__device__ __forceinline__ uint32_t smem_u32(const void* p) {
    uint32_t a;
    asm("{ .reg .u64 t; cvta.to.shared.u64 t, %1; cvt.u32.u64 %0, t; }" : "=r"(a) : "l"(p));
    return a;
}
__device__ __forceinline__ void hmma16(float* d, const uint32_t* a, const uint32_t* b) {
    asm volatile("mma.sync.aligned.m16n8k16.row.col.f32.f16.f16.f32 "
        "{%0,%1,%2,%3}, {%4,%5,%6,%7}, {%8,%9}, {%0,%1,%2,%3};"
        : "+f"(d[0]), "+f"(d[1]), "+f"(d[2]), "+f"(d[3])
        : "r"(a[0]), "r"(a[1]), "r"(a[2]), "r"(a[3]), "r"(b[0]), "r"(b[1]));
}
__device__ __forceinline__ void ldsm4(uint32_t* r, uint32_t a) {
    asm volatile("ldmatrix.sync.aligned.m8n8.x4.shared.b16 {%0,%1,%2,%3}, [%4];"
        : "=r"(r[0]), "=r"(r[1]), "=r"(r[2]), "=r"(r[3]) : "r"(a));
}
__device__ __forceinline__ void ldsm4t(uint32_t* r, uint32_t a) {
    asm volatile("ldmatrix.sync.aligned.m8n8.x4.trans.shared.b16 {%0,%1,%2,%3}, [%4];"
        : "=r"(r[0]), "=r"(r[1]), "=r"(r[2]), "=r"(r[3]) : "r"(a));
}
__device__ __forceinline__ uint32_t f2h2(float x, float y) {
    __half2 h = __floats2half2_rn(x, y);
    return *reinterpret_cast<uint32_t*>(&h);
}

// ---------------- packed f32x2 helpers (small GEMMs) ----------------
__device__ __forceinline__ unsigned long long pack2(float lo, float hi) {
    unsigned long long r;
    asm("mov.b64 %0, {%1, %2};" : "=l"(r) : "f"(lo), "f"(hi));
    return r;
}
__device__ __forceinline__ void unpack2(unsigned long long v, float& lo, float& hi) {
    asm("mov.b64 {%0, %1}, %2;" : "=f"(lo), "=f"(hi) : "l"(v));
}
__device__ __forceinline__ void fma2(unsigned long long& d, unsigned long long a, unsigned long long b) {
    asm("fma.rn.f32x2 %0, %1, %2, %0;" : "+l"(d) : "l"(a), "l"(b));
}

// ---------------- scratch ----------------
__device__ float g_Wq[CH*CH], g_Wk[CH*CH], g_Wv[CH*CH], g_Wp2[CH*CH], g_bp2[CH];
__device__ float g_Spart[NB*KSPLIT1*CH*CH];
__device__ float g_S[NB*CH*CH], g_T1[NB*CH*CH], g_T2[NB*CH*CH];
__device__ float g_attn[NB*CH*CH];
__device__ float g_nk2[NB*CH], g_nq2[NB*CH];
__device__ __half g_A2h[NB*CH*CH];         // A2 * A2SCALE, fp16
__device__ __half g_Xf[(size_t)NB*CH*HW];  // X in fp16 (written by xxt_mma)

// Upper-band 16x48 tiles (i: 0..11 of 16 rows, j: 0..3 of 48 cols), j >= jmin(i)
__constant__ int cTI[30] = {0,0,0,0, 1,1,1,1, 2,2,2,2, 3,3,3, 4,4,4, 5,5,5, 6,6, 7,7, 8,8, 9, 10, 11};
__constant__ int cTJ[30] = {0,1,2,3, 0,1,2,3, 0,1,2,3, 1,2,3, 1,2,3, 1,2,3, 2,3, 2,3, 2,3, 3, 3, 3};

// ============ GEMM1: S_p[b] = Xf Xf^T upper band only (symmetric), split-K ============
// grid (KSPLIT1, NB), 512 thr, dyn smem 49152. Warp w computes tiles w and w+16 (w<14).
__global__ __launch_bounds__(512) void xxt_mma(const float* __restrict__ xin) {
    extern __shared__ char smem[];
    const int tid = threadIdx.x, wid = tid >> 5, lane = tid & 31;
    const int split = blockIdx.x, b = blockIdx.y;
    const float* Xb = xin + (size_t)b * CH * HW;
    const int kbase = split * (HW / KSPLIT1);
    const uint32_t sb = smem_u32(smem);

    const int i0a = cTI[wid] * 16, j0a = cTJ[wid] * 48;
    const bool has2 = (wid < 14);
    const int i0b = has2 ? cTI[wid + 16] * 16 : 0;
    const int j0b = has2 ? cTJ[wid + 16] * 48 : 0;

    float dA[6][4], dB[6][4];
    #pragma unroll
    for (int j = 0; j < 6; ++j)
        #pragma unroll
        for (int q = 0; q < 4; ++q) { dA[j][q] = 0.f; dB[j][q] = 0.f; }

    auto ldx = [&](float4* v, int kb) {
        #pragma unroll
        for (int i = 0; i < 6; ++i) {
            int u = tid + (i << 9);
            int r = u >> 4, k4 = (u & 15) << 2;
            v[i] = *(const float4*)&Xb[(size_t)r * HW + kb + k4];
        }
    };
    auto stx = [&](const float4* v, int buf, int kb) {
        char* XF = smem + buf * 24576;
        #pragma unroll
        for (int i = 0; i < 6; ++i) {
            int u = tid + (i << 9);
            int r = u >> 4, k4 = (u & 15) << 2;
            uint2 hw = make_uint2(f2h2(v[i].x, v[i].y), f2h2(v[i].z, v[i].w));
            int sw = r * 128 + (((u & 15) << 3) ^ ((r & 7) << 4));
            *(uint2*)(XF + sw) = hw;
            *(uint2*)&g_Xf[((size_t)b * CH + r) * HW + kb + k4] = hw;  // fp16 X for out_mma
        }
    };

    const int xorv = (lane & 7) << 4;
    const int mat = lane >> 3;
    const int halfA = (lane >> 4) << 4;
    const int halfB = (mat & 1) << 4;
    const int rA15 = lane & 15;
    const int rB = ((mat >> 1) << 3) + (lane & 7);

    auto stage_compute = [&](int buf) {
        uint32_t base = sb + buf * 24576;
        #pragma unroll 1
        for (int kk = 0; kk < 4; ++kk) {
            int colA = ((kk << 5) + halfA) ^ xorv;
            int colB = ((kk << 5) + halfB) ^ xorv;
            uint32_t ah[4], bh[3][4];
            ldsm4(ah, base + (i0a + rA15) * 128 + colA);
            #pragma unroll
            for (int jj = 0; jj < 3; ++jj)
                ldsm4(bh[jj], base + (j0a + jj*16 + rB) * 128 + colB);
            #pragma unroll
            for (int jj = 0; jj < 3; ++jj) {
                hmma16(dA[2*jj],     ah, &bh[jj][0]);
                hmma16(dA[2*jj + 1], ah, &bh[jj][2]);
            }
            if (has2) {
                uint32_t ah2[4], bh2[3][4];
                ldsm4(ah2, base + (i0b + rA15) * 128 + colA);
                #pragma unroll
                for (int jj = 0; jj < 3; ++jj)
                    ldsm4(bh2[jj], base + (j0b + jj*16 + rB) * 128 + colB);
                #pragma unroll
                for (int jj = 0; jj < 3; ++jj) {
                    hmma16(dB[2*jj],     ah2, &bh2[jj][0]);
                    hmma16(dB[2*jj + 1], ah2, &bh2[jj][2]);
                }
            }
        }
    };

    {
        float4 v0[6];
        ldx(v0, kbase);
        stx(v0, 0, kbase);
    }
    __syncthreads();
    for (int c = 0; c < 16; ++c) {
        float4 vn[6];
        if (c < 15) ldx(vn, kbase + (c + 1) * 64);   // LDG issued, result not consumed yet
        stage_compute(c & 1);                         // hides LDG latency
        if (c < 15) stx(vn, (c + 1) & 1, kbase + (c + 1) * 64);
        __syncthreads();
    }

    float* Sp = g_Spart + (size_t)(b * KSPLIT1 + split) * CH * CH;
    int lr = lane >> 2, lc2 = (lane & 3) * 2;
    #pragma unroll
    for (int nj = 0; nj < 6; ++nj) {
        int r = i0a + lr, cc = j0a + 8*nj + lc2;
        *(float2*)&Sp[r * CH + cc]       = make_float2(dA[nj][0], dA[nj][1]);
        *(float2*)&Sp[(r + 8) * CH + cc] = make_float2(dA[nj][2], dA[nj][3]);
    }
    if (has2) {
        #pragma unroll
        for (int nj = 0; nj < 6; ++nj) {
            int r = i0b + lr, cc = j0b + 8*nj + lc2;
            *(float2*)&Sp[r * CH + cc]       = make_float2(dB[nj][0], dB[nj][1]);
            *(float2*)&Sp[(r + 8) * CH + cc] = make_float2(dB[nj][2], dB[nj][3]);
        }
    }
}

// element coverage: tile (r/16, c/48) is in the upper-band set
__device__ __forceinline__ bool s_cov(int r, int c) {
    return (48 * (c / 48) + 47) >= (16 * (r / 16));
}

// S = sum_p S_p with symmetrization. grid (6,6,NB), 256 thr, 32x32 tiles.
__global__ __launch_bounds__(256) void s_reduce() {
    __shared__ float tb[32][33];
    const int b = blockIdx.z, I0 = blockIdx.x * 32, J0 = blockIdx.y * 32;
    const int c = threadIdx.x & 31, ty = threadIdx.x >> 5;
    const float* Sp = g_Spart + (size_t)b * KSPLIT1 * CH * CH;

    const int ibmin = I0 >> 4, ibmax = (I0 + 31) >> 4;
    const int jbmin = J0 / 48, jbmax = (J0 + 31) / 48;
    const bool fullCov = (48 * jbmin + 47) >= (16 * ibmax);
    const bool fullUnc = (48 * jbmax + 47) < (16 * ibmin);

    float dsum[4];
    if (!fullUnc) {
        #pragma unroll
        for (int q = 0; q < 4; ++q) {
            int r = I0 + ty + 8*q;
            float s = 0.f;
            #pragma unroll
            for (int p = 0; p < KSPLIT1; ++p)
                s += Sp[(size_t)p*CH*CH + r*CH + J0 + c];
            dsum[q] = s;
        }
    }
    if (!fullCov) {
        #pragma unroll
        for (int q = 0; q < 4; ++q) {
            int rr = J0 + ty + 8*q;
            float s = 0.f;
            #pragma unroll
            for (int p = 0; p < KSPLIT1; ++p)
                s += Sp[(size_t)p*CH*CH + rr*CH + I0 + c];
            tb[ty + 8*q][c] = s;
        }
        __syncthreads();
    }
    float* Sb = g_S + (size_t)b * CH * CH;
    #pragma unroll
    for (int q = 0; q < 4; ++q) {
        int r = I0 + ty + 8*q, cc = J0 + c;
        float v;
        if (fullCov)      v = dsum[q];
        else if (fullUnc) v = tb[c][ty + 8*q];
        else              v = s_cov(r, cc) ? dsum[q] : tb[c][ty + 8*q];
        Sb[r * CH + cc] = v;
    }
}

// ============ GEMM2: out[b] = A2f·Xf * A2INV + bp2 (single-term fp16) ============
// grid (HW/128, NB), 512 thr (16 warps, warp tile 48x32), dyn smem 101376
__global__ __launch_bounds__(512) void out_mma(float* __restrict__ out) {
    extern __shared__ char smem[];
    const int tid = threadIdx.x, wid = tid >> 5, lane = tid & 31;
    const int p0 = blockIdx.x * 128, b = blockIdx.y;
    const uint32_t sb = smem_u32(smem);
    const int m0 = (wid >> 2) * 48, n0p = (wid & 3) * 32;

    float d[3][4][4];
    #pragma unroll
    for (int i = 0; i < 3; ++i)
        #pragma unroll
        for (int j = 0; j < 4; ++j)
            #pragma unroll
            for (int q = 0; q < 4; ++q) d[i][j][q] = 0.f;

    auto ldstage = [&](uint4* va, uint4* vx, int c0) {
        #pragma unroll
        for (int i = 0; i < 3; ++i) {
            int u = tid + (i << 9);
            int r = u >> 3, sg = u & 7;
            va[i] = *(const uint4*)&g_A2h[((size_t)b * CH + r) * CH + c0 + sg * 8];
        }
        #pragma unroll
        for (int i = 0; i < 2; ++i) {
            int u = tid + (i << 9);
            int r = u >> 4, c8 = (u & 15) << 3;
            vx[i] = *(const uint4*)&g_Xf[((size_t)b * CH + c0 + r) * HW + p0 + c8];
        }
    };
    auto ststage = [&](const uint4* va, const uint4* vx, int buf) {
        char* A2F = smem + buf * 40960;
        char* XF  = A2F + 24576;
        #pragma unroll
        for (int i = 0; i < 3; ++i) {
            int u = tid + (i << 9);
            int r = u >> 3, sg = u & 7;
            int sw = r * 128 + ((sg << 4) ^ ((r & 7) << 4));
            *(uint4*)(A2F + sw) = va[i];
        }
        #pragma unroll
        for (int i = 0; i < 2; ++i) {
            int u = tid + (i << 9);
            int r = u >> 4;
            int sw = r * 256 + ((((u & 15)) << 4) ^ ((r & 7) << 4));
            *(uint4*)(XF + sw) = vx[i];
        }
    };

    const int xorv = (lane & 7) << 4;
    const int mat = lane >> 3;
    const int halfA = (lane >> 4) << 4;
    const int rA15 = lane & 15;
    const int rbX = ((mat & 1) << 3) + (lane & 7);
    const int cbX = (n0p + ((mat >> 1) << 3)) * 2;

    auto stage_compute = [&](int buf) {
        uint32_t baseAF = sb + buf * 40960;
        uint32_t baseXF = baseAF + 24576;
        #pragma unroll 1
        for (int kk = 0; kk < 4; ++kk) {
            int colA = ((kk << 5) + halfA) ^ xorv;
            int xrow = (kk * 16 + rbX) * 256;
            uint32_t ah[3][4], bt[2][4];
            #pragma unroll
            for (int mi = 0; mi < 3; ++mi)
                ldsm4(ah[mi], baseAF + (m0 + 16*mi + rA15) * 128 + colA);
            #pragma unroll
            for (int jj = 0; jj < 2; ++jj)
                ldsm4t(bt[jj], baseXF + xrow + ((cbX + jj*32) ^ xorv));
            #pragma unroll
            for (int mi = 0; mi < 3; ++mi)
                #pragma unroll
                for (int jj = 0; jj < 2; ++jj) {
                    hmma16(d[mi][2*jj],     ah[mi], &bt[jj][0]);
                    hmma16(d[mi][2*jj + 1], ah[mi], &bt[jj][2]);
                }
        }
    };

    {
        uint4 va0[3], vx0[2];
        ldstage(va0, vx0, 0);
        ststage(va0, vx0, 0);
    }
    __syncthreads();
    for (int c = 0; c < 3; ++c) {
        uint4 va[3], vx[2];
        if (c < 2) ldstage(va, vx, (c + 1) * 64);
        stage_compute(c & 1);
        if (c < 2) ststage(va, vx, (c + 1) & 1);
        __syncthreads();
    }

    float* so = (float*)smem;   // 192 x 132 floats
    int lr = lane >> 2, lc2 = (lane & 3) * 2;
    #pragma unroll
    for (int mi = 0; mi < 3; ++mi)
        #pragma unroll
        for (int nj = 0; nj < 4; ++nj) {
            int r = m0 + 16*mi + lr, cc = n0p + 8*nj + lc2;
            *(float2*)&so[r * 132 + cc]       = make_float2(d[mi][nj][0], d[mi][nj][1]);
            *(float2*)&so[(r + 8) * 132 + cc] = make_float2(d[mi][nj][2], d[mi][nj][3]);
        }
    __syncthreads();
    #pragma unroll
    for (int u = tid; u < 6144; u += 512) {
        int co = u >> 5, p4 = (u & 31) << 2;
        float4 v = *(const float4*)&so[co * 132 + p4];
        float bias = g_bp2[co];
        v.x = v.x * A2INV + bias;
        v.y = v.y * A2INV + bias;
        v.z = v.z * A2INV + bias;
        v.w = v.w * A2INV + bias;
        *(float4*)&out[((size_t)b * CH + co) * HW + p0 + p4] = v;
    }
}

// ---------------- small 192x192 GEMM core: 32x32 tile, 2x2/thread, FFMA2 ----------------
__device__ __forceinline__ void gemm_tile32(const float* __restrict__ Ab,
                                            const float* __restrict__ Bb,
                                            float* __restrict__ Cb,
                                            int transB, int i0, int j0) {
    __shared__ float As[16][34], Bs[16][34];
    int t = threadIdx.x;
    int tx = t & 15, ty = t >> 4;
    int li = t & 31, lkq = t >> 5;
    int lkb = t >> 4, lj2 = (t & 15) * 2;

    unsigned long long acc0 = 0ull, acc1 = 0ull;

    for (int kk = 0; kk < CH; kk += 16) {
        float2 av = *(const float2*)&Ab[(i0 + li) * CH + kk + lkq * 2];
        float2 bv;
        if (transB) bv = *(const float2*)&Bb[(j0 + li) * CH + kk + lkq * 2];
        else        bv = *(const float2*)&Bb[(kk + lkb) * CH + j0 + lj2];
        __syncthreads();
        As[lkq*2 + 0][li] = av.x;
        As[lkq*2 + 1][li] = av.y;
        if (transB) { Bs[lkq*2 + 0][li] = bv.x; Bs[lkq*2 + 1][li] = bv.y; }
        else        { *(float2*)&Bs[lkb][lj2] = bv; }
        __syncthreads();
        #pragma unroll
        for (int k = 0; k < 16; ++k) {
            float2 a2 = *(const float2*)&As[k][ty * 2];
            unsigned long long b2 = *(const unsigned long long*)&Bs[k][tx * 2];
            fma2(acc0, pack2(a2.x, a2.x), b2);
            fma2(acc1, pack2(a2.y, a2.y), b2);
        }
    }
    float o00, o01, o10, o11;
    unpack2(acc0, o00, o01);
    unpack2(acc1, o10, o11);
    *(float2*)&Cb[(i0 + ty*2 + 0) * CH + j0 + tx*2] = make_float2(o00, o01);
    *(float2*)&Cb[(i0 + ty*2 + 1) * CH + j0 + tx*2] = make_float2(o10, o11);
}

// z=0..3: weight-combine GEMMs; z=4 (block 0,0): bp2 = w_out · b_proj
__global__ __launch_bounds__(256) void prep_weights(const float* __restrict__ wq,
                                                    const float* __restrict__ wk,
                                                    const float* __restrict__ wv,
                                                    const float* __restrict__ wout,
                                                    const float* __restrict__ wsplit,
                                                    const float* __restrict__ wproj,
                                                    const float* __restrict__ bproj) {
    if (blockIdx.z == 4) {
        if (blockIdx.x == 0 && blockIdx.y == 0) {
            int f = threadIdx.x;
            if (f < CH) {
                float s = 0.f;
                for (int o = 0; o < CH; ++o) s += wout[f*CH+o] * bproj[o];
                g_bp2[f] = s;
            }
        }
        return;
    }
    const float *A, *B; float* C;
    switch (blockIdx.z) {
        case 0:  A = wq;   B = wsplit; C = g_Wq;  break;
        case 1:  A = wk;   B = wsplit; C = g_Wk;  break;
        case 2:  A = wv;   B = wsplit; C = g_Wv;  break;
        default: A = wout; B = wproj;  C = g_Wp2; break;
    }
    gemm_tile32(A, B, C, 0, blockIdx.x * 32, blockIdx.y * 32);
}

// T1 = S Wq'^T and T2 = S Wk'^T in one launch
__global__ __launch_bounds__(256) void t12_gemm() {
    int z = blockIdx.z;
    int b = z >> 1, which = z & 1;
    const float* W = which ? g_Wk : g_Wq;
    float* T = (which ? g_T2 : g_T1) + (size_t)b * CH * CH;
    gemm_tile32(g_S + (size_t)b * CH * CH, W, T, 1, blockIdx.x * 32, blockIdx.y * 32);
}

__global__ void diag_norms() {
    int b = blockIdx.x, which = blockIdx.y;
    int j = threadIdx.x;
    if (j >= CH) return;
    const float* W = which ? g_Wk : g_Wq;
    const float* T = (which ? g_T2 : g_T1) + (size_t)b*CH*CH;
    float s = 0.f;
    for (int m = 0; m < CH; ++m) s += W[j*CH+m] * T[m*CH+j];
    (which ? g_nk2 : g_nq2)[b*CH+j] = s;
}

// ============ Fused: G-rows (32x192 of Wk'·T1) + softmax -> attn. grid (6, NB) ============
__global__ __launch_bounds__(256) void g_softmax() {
    __shared__ float As[16][33];
    __shared__ float Bs[16][196];
    __shared__ float Gs[32][196];
    __shared__ float sdq[CH];
    const int b = blockIdx.y, i0 = blockIdx.x * 32;
    const int tid = threadIdx.x;
    const int tx = tid & 31, ty = tid >> 5;
    const float* T1b = g_T1 + (size_t)b * CH * CH;

    unsigned long long acc[4][3];
    #pragma unroll
    for (int q = 0; q < 4; ++q)
        #pragma unroll
        for (int s = 0; s < 3; ++s) acc[q][s] = 0ull;

    for (int kk = 0; kk < CH; kk += 16) {
        {
            int r = tid >> 3, k2 = (tid & 7) * 2;
            float2 w = *(const float2*)&g_Wk[(i0 + r) * CH + kk + k2];
            As[k2][r] = w.x;
            As[k2 + 1][r] = w.y;
        }
        #pragma unroll
        for (int s = 0; s < 3; ++s) {
            int lin = s * 256 + tid;
            int kr = lin / 48, c4 = (lin % 48) * 4;
            *(float4*)&Bs[kr][c4] = *(const float4*)&T1b[(kk + kr) * CH + c4];
        }
        __syncthreads();
        #pragma unroll
        for (int k = 0; k < 16; ++k) {
            float a0 = As[k][ty], a1 = As[k][ty + 8], a2 = As[k][ty + 16], a3 = As[k][ty + 24];
            unsigned long long b0 = *(const unsigned long long*)&Bs[k][tx * 2];
            unsigned long long b1 = *(const unsigned long long*)&Bs[k][tx * 2 + 64];
            unsigned long long b2 = *(const unsigned long long*)&Bs[k][tx * 2 + 128];
            fma2(acc[0][0], pack2(a0, a0), b0); fma2(acc[0][1], pack2(a0, a0), b1); fma2(acc[0][2], pack2(a0, a0), b2);
            fma2(acc[1][0], pack2(a1, a1), b0); fma2(acc[1][1], pack2(a1, a1), b1); fma2(acc[1][2], pack2(a1, a1), b2);
            fma2(acc[2][0], pack2(a2, a2), b0); fma2(acc[2][1], pack2(a2, a2), b1); fma2(acc[2][2], pack2(a2, a2), b2);
            fma2(acc[3][0], pack2(a3, a3), b0); fma2(acc[3][1], pack2(a3, a3), b1); fma2(acc[3][2], pack2(a3, a3), b2);
        }
        __syncthreads();
    }
    #pragma unroll
    for (int q = 0; q < 4; ++q)
        #pragma unroll
        for (int s = 0; s < 3; ++s) {
            float lo, hi;
            unpack2(acc[q][s], lo, hi);
            Gs[ty + 8*q][tx * 2 + s * 64]     = lo;
            Gs[ty + 8*q][tx * 2 + s * 64 + 1] = hi;
        }
    if (tid < CH) sdq[tid] = fmaxf(sqrtf(g_nq2[b * CH + tid]), EPSN);
    __syncthreads();

    const int w = tid >> 5, lane = tid & 31;
    #pragma unroll
    for (int rr = 0; rr < 4; ++rr) {
        int row = w * 4 + rr;
        float dk = fmaxf(sqrtf(g_nk2[b * CH + i0 + row]), EPSN);
        float L[6];
        #pragma unroll
        for (int t = 0; t < 6; ++t)
            L[t] = Gs[row][lane + 32 * t] / (dk * sdq[lane + 32 * t]);
        float m = L[0];
        #pragma unroll
        for (int t = 1; t < 6; ++t) m = fmaxf(m, L[t]);
        #pragma unroll
        for (int o = 16; o > 0; o >>= 1) m = fmaxf(m, __shfl_xor_sync(0xffffffffu, m, o));
        float e[6], sum = 0.f;
        #pragma unroll
        for (int t = 0; t < 6; ++t) { e[t] = expf(L[t] - m); sum += e[t]; }
        #pragma unroll
        for (int o = 16; o > 0; o >>= 1) sum += __shfl_xor_sync(0xffffffffu, sum, o);
        float inv = 1.f / sum;
        #pragma unroll
        for (int t = 0; t < 6; ++t)
            g_attn[((size_t)b * CH + i0 + row) * CH + lane + 32 * t] = e[t] * inv;
    }
}

// ============ Fused: A2 = (Wp2·attn)·Wv', scaled fp16 out. grid (6, NB), 256 thr ============
__global__ __launch_bounds__(256) void a12_gemm() {
    __shared__ float As[16][33];
    __shared__ float Bs[16][196];
    __shared__ float A1t[192][33];   // [col][row]
    const int b = blockIdx.y, i0 = blockIdx.x * 32;
    const int tid = threadIdx.x;
    const int tx = tid & 31, ty = tid >> 5;
    const float* attnb = g_attn + (size_t)b * CH * CH;

    unsigned long long acc[4][3];
    #pragma unroll
    for (int q = 0; q < 4; ++q)
        #pragma unroll
        for (int s = 0; s < 3; ++s) acc[q][s] = 0ull;

    // Phase 1: A1blk = Wp2[i0..i0+31, :] · attn_b   (32 x 192)
    for (int kk = 0; kk < CH; kk += 16) {
        {
            int r = tid >> 3, k2 = (tid & 7) * 2;
            float2 w = *(const float2*)&g_Wp2[(i0 + r) * CH + kk + k2];
            As[k2][r] = w.x;
            As[k2 + 1][r] = w.y;
        }
        #pragma unroll
        for (int s = 0; s < 3; ++s) {
            int lin = s * 256 + tid;
            int kr = lin / 48, c4 = (lin % 48) * 4;
            *(float4*)&Bs[kr][c4] = *(const float4*)&attnb[(kk + kr) * CH + c4];
        }
        __syncthreads();
        #pragma unroll
        for (int k = 0; k < 16; ++k) {
            float a0 = As[k][ty], a1 = As[k][ty + 8], a2 = As[k][ty + 16], a3 = As[k][ty + 24];
            unsigned long long b0 = *(const unsigned long long*)&Bs[k][tx * 2];
            unsigned long long b1 = *(const unsigned long long*)&Bs[k][tx * 2 + 64];
            unsigned long long b2 = *(const unsigned long long*)&Bs[k][tx * 2 + 128];
            fma2(acc[0][0], pack2(a0, a0), b0); fma2(acc[0][1], pack2(a0, a0), b1); fma2(acc[0][2], pack2(a0, a0), b2);
            fma2(acc[1][0], pack2(a1, a1), b0); fma2(acc[1][1], pack2(a1, a1), b1); fma2(acc[1][2], pack2(a1, a1), b2);
            fma2(acc[2][0], pack2(a2, a2), b0); fma2(acc[2][1], pack2(a2, a2), b1); fma2(acc[2][2], pack2(a2, a2), b2);
            fma2(acc[3][0], pack2(a3, a3), b0); fma2(acc[3][1], pack2(a3, a3), b1); fma2(acc[3][2], pack2(a3, a3), b2);
        }
        __syncthreads();
    }
    #pragma unroll
    for (int q = 0; q < 4; ++q)
        #pragma unroll
        for (int s = 0; s < 3; ++s) {
            float lo, hi;
            unpack2(acc[q][s], lo, hi);
            A1t[tx * 2 + s * 64][ty + 8*q]     = lo;
            A1t[tx * 2 + s * 64 + 1][ty + 8*q] = hi;
        }
    __syncthreads();

    // Phase 2: A2blk = A1blk · Wv'   (32 x 192), scaled fp16 store
    unsigned long long acc2[4][3];
    #pragma unroll
    for (int q = 0; q < 4; ++q)
        #pragma unroll
        for (int s = 0; s < 3; ++s) acc2[q][s] = 0ull;

    for (int kk = 0; kk < CH; kk += 16) {
        #pragma unroll
        for (int s = 0; s < 3; ++s) {
            int lin = s * 256 + tid;
            int kr = lin / 48, c4 = (lin % 48) * 4;
            *(float4*)&Bs[kr][c4] = *(const float4*)&g_Wv[(kk + kr) * CH + c4];
        }
        __syncthreads();
        #pragma unroll
        for (int k = 0; k < 16; ++k) {
            float a0 = A1t[kk + k][ty], a1 = A1t[kk + k][ty + 8],
                  a2 = A1t[kk + k][ty + 16], a3 = A1t[kk + k][ty + 24];
            unsigned long long b0 = *(const unsigned long long*)&Bs[k][tx * 2];
            unsigned long long b1 = *(const unsigned long long*)&Bs[k][tx * 2 + 64];
            unsigned long long b2 = *(const unsigned long long*)&Bs[k][tx * 2 + 128];
            fma2(acc2[0][0], pack2(a0, a0), b0); fma2(acc2[0][1], pack2(a0, a0), b1); fma2(acc2[0][2], pack2(a0, a0), b2);
            fma2(acc2[1][0], pack2(a1, a1), b0); fma2(acc2[1][1], pack2(a1, a1), b1); fma2(acc2[1][2], pack2(a1, a1), b2);
            fma2(acc2[2][0], pack2(a2, a2), b0); fma2(acc2[2][1], pack2(a2, a2), b1); fma2(acc2[2][2], pack2(a2, a2), b2);
            fma2(acc2[3][0], pack2(a3, a3), b0); fma2(acc2[3][1], pack2(a3, a3), b1); fma2(acc2[3][2], pack2(a3, a3), b2);
        }
        __syncthreads();
    }
    #pragma unroll
    for (int q = 0; q < 4; ++q)
        #pragma unroll
        for (int s = 0; s < 3; ++s) {
            float lo, hi;
            unpack2(acc2[q][s], lo, hi);
            __half2 hv = __floats2half2_rn(lo * A2SCALE, hi * A2SCALE);
            *(__half2*)&g_A2h[((size_t)b * CH + i0 + ty + 8*q) * CH + tx * 2 + s * 64] = hv;
        }
}

// ---------------- launch ----------------
extern "C" void kernel_launch(void* const* d_in, const int* in_sizes, int n_in,
                              void* d_out, int out_size) {
    const float* x_in   = (const float*)d_in[0];
    const float* w_split= (const float*)d_in[1];
    const float* w_q    = (const float*)d_in[2];
    const float* w_k    = (const float*)d_in[3];
    const float* w_v    = (const float*)d_in[4];
    const float* w_proj = (const float*)d_in[5];
    const float* b_proj = (const float*)d_in[6];
    const float* w_out  = (const float*)d_in[7];
    float* out = (float*)d_out;

    cudaFuncSetAttribute(xxt_mma, cudaFuncAttributeMaxDynamicSharedMemorySize, 49152);
    cudaFuncSetAttribute(out_mma, cudaFuncAttributeMaxDynamicSharedMemorySize, 101376);

    // S partials (upper band only, fp16 single-term); also emits g_Xf
    xxt_mma<<<dim3(KSPLIT1, NB), 512, 49152>>>(x_in);

    // combined channel maps + bias (one launch)
    prep_weights<<<dim3(6,6,5), 256>>>(w_q, w_k, w_v, w_out, w_split, w_proj, b_proj);

    // S = sum_p S_p with symmetrization
    s_reduce<<<dim3(6,6,NB), 256>>>();

    // Gram + norms in channel space
    t12_gemm<<<dim3(6,6,2*NB), 256>>>();
    diag_norms<<<dim3(NB,2), 192>>>();
    g_softmax<<<dim3(6,NB), 256>>>();             // G + softmax fused -> attn

    a12_gemm<<<dim3(6,NB), 256>>>();              // A2 = (Wp2·attn)·Wv', fp16

    // out = A2f Xf + bp2 (tensor cores, fp16 single-term)
    out_mma<<<dim3(HW/128, NB), 512, 101376>>>(out);
}

// round 15
// speedup vs baseline: 3.6695x; 1.1558x over previous
#include <cuda_runtime.h>
#include <cuda_fp16.h>
#include <cstdint>

#define CH 192
#define NB 8
#define HW 16384
#define KSPLIT1 16
#define EPSN 1e-12f
#define A2SCALE 4096.0f
#define A2INV   (1.0f/4096.0f)

// ---------------- mma.sync / ldmatrix helpers ----------------
__device__ __forceinline__ uint32_t smem_u32(const void* p) {
    uint32_t a;
    asm("{ .reg .u64 t; cvta.to.shared.u64 t, %1; cvt.u32.u64 %0, t; }" : "=r"(a) : "l"(p));
    return a;
}
__device__ __forceinline__ void hmma16(float* d, const uint32_t* a, const uint32_t* b) {
    asm volatile("mma.sync.aligned.m16n8k16.row.col.f32.f16.f16.f32 "
        "{%0,%1,%2,%3}, {%4,%5,%6,%7}, {%8,%9}, {%0,%1,%2,%3};"
        : "+f"(d[0]), "+f"(d[1]), "+f"(d[2]), "+f"(d[3])
        : "r"(a[0]), "r"(a[1]), "r"(a[2]), "r"(a[3]), "r"(b[0]), "r"(b[1]));
}
__device__ __forceinline__ void ldsm4(uint32_t* r, uint32_t a) {
    asm volatile("ldmatrix.sync.aligned.m8n8.x4.shared.b16 {%0,%1,%2,%3}, [%4];"
        : "=r"(r[0]), "=r"(r[1]), "=r"(r[2]), "=r"(r[3]) : "r"(a));
}
__device__ __forceinline__ void ldsm4t(uint32_t* r, uint32_t a) {
    asm volatile("ldmatrix.sync.aligned.m8n8.x4.trans.shared.b16 {%0,%1,%2,%3}, [%4];"
        : "=r"(r[0]), "=r"(r[1]), "=r"(r[2]), "=r"(r[3]) : "r"(a));
}
__device__ __forceinline__ uint32_t f2h2(float x, float y) {
    __half2 h = __floats2half2_rn(x, y);
    return *reinterpret_cast<uint32_t*>(&h);
}

// ---------------- packed f32x2 helpers ----------------
__device__ __forceinline__ unsigned long long pack2(float lo, float hi) {
    unsigned long long r;
    asm("mov.b64 %0, {%1, %2};" : "=l"(r) : "f"(lo), "f"(hi));
    return r;
}
__device__ __forceinline__ void unpack2(unsigned long long v, float& lo, float& hi) {
    asm("mov.b64 {%0, %1}, %2;" : "=f"(lo), "=f"(hi) : "l"(v));
}
__device__ __forceinline__ void fma2(unsigned long long& d, unsigned long long a, unsigned long long b) {
    asm("fma.rn.f32x2 %0, %1, %2, %0;" : "+l"(d) : "l"(a), "l"(b));
}

// ---------------- scratch ----------------
__device__ float g_Wq[CH*CH], g_WqT[CH*CH], g_Wk[CH*CH], g_Wv[CH*CH], g_Wp2[CH*CH], g_bp2[CH];
__device__ float g_Spart[NB*KSPLIT1*CH*CH];
__device__ float g_S[NB*CH*CH], g_K2[NB*CH*CH];
__device__ float g_attn[NB*CH*CH];
__device__ float g_nk2[NB*CH], g_nq2[NB*CH];
__device__ __half g_A2h[NB*CH*CH];         // A2 * A2SCALE, fp16
__device__ __half g_Xf[(size_t)NB*CH*HW];  // X in fp16 (written by xxt_mma)

// Upper-band 16x48 tiles
__constant__ int cTI[30] = {0,0,0,0, 1,1,1,1, 2,2,2,2, 3,3,3, 4,4,4, 5,5,5, 6,6, 7,7, 8,8, 9, 10, 11};
__constant__ int cTJ[30] = {0,1,2,3, 0,1,2,3, 0,1,2,3, 1,2,3, 1,2,3, 1,2,3, 2,3, 2,3, 2,3, 3, 3, 3};

// ============ GEMM1: S_p[b] = Xf Xf^T upper band only, split-K ============
__global__ __launch_bounds__(512) void xxt_mma(const float* __restrict__ xin) {
    extern __shared__ char smem[];
    const int tid = threadIdx.x, wid = tid >> 5, lane = tid & 31;
    const int split = blockIdx.x, b = blockIdx.y;
    const float* Xb = xin + (size_t)b * CH * HW;
    const int kbase = split * (HW / KSPLIT1);
    const uint32_t sb = smem_u32(smem);

    const int i0a = cTI[wid] * 16, j0a = cTJ[wid] * 48;
    const bool has2 = (wid < 14);
    const int i0b = has2 ? cTI[wid + 16] * 16 : 0;
    const int j0b = has2 ? cTJ[wid + 16] * 48 : 0;

    float dA[6][4], dB[6][4];
    #pragma unroll
    for (int j = 0; j < 6; ++j)
        #pragma unroll
        for (int q = 0; q < 4; ++q) { dA[j][q] = 0.f; dB[j][q] = 0.f; }

    auto ldx = [&](float4* v, int kb) {
        #pragma unroll
        for (int i = 0; i < 6; ++i) {
            int u = tid + (i << 9);
            int r = u >> 4, k4 = (u & 15) << 2;
            v[i] = *(const float4*)&Xb[(size_t)r * HW + kb + k4];
        }
    };
    auto stx = [&](const float4* v, int buf, int kb) {
        char* XF = smem + buf * 24576;
        #pragma unroll
        for (int i = 0; i < 6; ++i) {
            int u = tid + (i << 9);
            int r = u >> 4, k4 = (u & 15) << 2;
            uint2 hw = make_uint2(f2h2(v[i].x, v[i].y), f2h2(v[i].z, v[i].w));
            int sw = r * 128 + (((u & 15) << 3) ^ ((r & 7) << 4));
            *(uint2*)(XF + sw) = hw;
            *(uint2*)&g_Xf[((size_t)b * CH + r) * HW + kb + k4] = hw;
        }
    };

    const int xorv = (lane & 7) << 4;
    const int mat = lane >> 3;
    const int halfA = (lane >> 4) << 4;
    const int halfB = (mat & 1) << 4;
    const int rA15 = lane & 15;
    const int rB = ((mat >> 1) << 3) + (lane & 7);

    auto stage_compute = [&](int buf) {
        uint32_t base = sb + buf * 24576;
        #pragma unroll 1
        for (int kk = 0; kk < 4; ++kk) {
            int colA = ((kk << 5) + halfA) ^ xorv;
            int colB = ((kk << 5) + halfB) ^ xorv;
            uint32_t ah[4], bh[3][4];
            ldsm4(ah, base + (i0a + rA15) * 128 + colA);
            #pragma unroll
            for (int jj = 0; jj < 3; ++jj)
                ldsm4(bh[jj], base + (j0a + jj*16 + rB) * 128 + colB);
            #pragma unroll
            for (int jj = 0; jj < 3; ++jj) {
                hmma16(dA[2*jj],     ah, &bh[jj][0]);
                hmma16(dA[2*jj + 1], ah, &bh[jj][2]);
            }
            if (has2) {
                uint32_t ah2[4], bh2[3][4];
                ldsm4(ah2, base + (i0b + rA15) * 128 + colA);
                #pragma unroll
                for (int jj = 0; jj < 3; ++jj)
                    ldsm4(bh2[jj], base + (j0b + jj*16 + rB) * 128 + colB);
                #pragma unroll
                for (int jj = 0; jj < 3; ++jj) {
                    hmma16(dB[2*jj],     ah2, &bh2[jj][0]);
                    hmma16(dB[2*jj + 1], ah2, &bh2[jj][2]);
                }
            }
        }
    };

    {
        float4 v0[6];
        ldx(v0, kbase);
        stx(v0, 0, kbase);
    }
    __syncthreads();
    for (int c = 0; c < 16; ++c) {
        float4 vn[6];
        if (c < 15) ldx(vn, kbase + (c + 1) * 64);
        stage_compute(c & 1);
        if (c < 15) stx(vn, (c + 1) & 1, kbase + (c + 1) * 64);
        __syncthreads();
    }

    float* Sp = g_Spart + (size_t)(b * KSPLIT1 + split) * CH * CH;
    int lr = lane >> 2, lc2 = (lane & 3) * 2;
    #pragma unroll
    for (int nj = 0; nj < 6; ++nj) {
        int r = i0a + lr, cc = j0a + 8*nj + lc2;
        *(float2*)&Sp[r * CH + cc]       = make_float2(dA[nj][0], dA[nj][1]);
        *(float2*)&Sp[(r + 8) * CH + cc] = make_float2(dA[nj][2], dA[nj][3]);
    }
    if (has2) {
        #pragma unroll
        for (int nj = 0; nj < 6; ++nj) {
            int r = i0b + lr, cc = j0b + 8*nj + lc2;
            *(float2*)&Sp[r * CH + cc]       = make_float2(dB[nj][0], dB[nj][1]);
            *(float2*)&Sp[(r + 8) * CH + cc] = make_float2(dB[nj][2], dB[nj][3]);
        }
    }
}

__device__ __forceinline__ bool s_cov(int r, int c) {
    return (48 * (c / 48) + 47) >= (16 * (r / 16));
}

// S = sum_p S_p with symmetrization. grid (6,6,NB), 256 thr.
__global__ __launch_bounds__(256) void s_reduce() {
    __shared__ float tb[32][33];
    const int b = blockIdx.z, I0 = blockIdx.x * 32, J0 = blockIdx.y * 32;
    const int c = threadIdx.x & 31, ty = threadIdx.x >> 5;
    const float* Sp = g_Spart + (size_t)b * KSPLIT1 * CH * CH;

    const int ibmin = I0 >> 4, ibmax = (I0 + 31) >> 4;
    const int jbmin = J0 / 48, jbmax = (J0 + 31) / 48;
    const bool fullCov = (48 * jbmin + 47) >= (16 * ibmax);
    const bool fullUnc = (48 * jbmax + 47) < (16 * ibmin);

    float dsum[4];
    if (!fullUnc) {
        #pragma unroll
        for (int q = 0; q < 4; ++q) {
            int r = I0 + ty + 8*q;
            float s = 0.f;
            #pragma unroll
            for (int p = 0; p < KSPLIT1; ++p)
                s += Sp[(size_t)p*CH*CH + r*CH + J0 + c];
            dsum[q] = s;
        }
    }
    if (!fullCov) {
        #pragma unroll
        for (int q = 0; q < 4; ++q) {
            int rr = J0 + ty + 8*q;
            float s = 0.f;
            #pragma unroll
            for (int p = 0; p < KSPLIT1; ++p)
                s += Sp[(size_t)p*CH*CH + rr*CH + I0 + c];
            tb[ty + 8*q][c] = s;
        }
        __syncthreads();
    }
    float* Sb = g_S + (size_t)b * CH * CH;
    #pragma unroll
    for (int q = 0; q < 4; ++q) {
        int r = I0 + ty + 8*q, cc = J0 + c;
        float v;
        if (fullCov)      v = dsum[q];
        else if (fullUnc) v = tb[c][ty + 8*q];
        else              v = s_cov(r, cc) ? dsum[q] : tb[c][ty + 8*q];
        Sb[r * CH + cc] = v;
    }
}

// ============ GEMM2: out[b] = A2f·Xf * A2INV + bp2 ============
__global__ __launch_bounds__(512) void out_mma(float* __restrict__ out) {
    extern __shared__ char smem[];
    const int tid = threadIdx.x, wid = tid >> 5, lane = tid & 31;
    const int p0 = blockIdx.x * 128, b = blockIdx.y;
    const uint32_t sb = smem_u32(smem);
    const int m0 = (wid >> 2) * 48, n0p = (wid & 3) * 32;

    float d[3][4][4];
    #pragma unroll
    for (int i = 0; i < 3; ++i)
        #pragma unroll
        for (int j = 0; j < 4; ++j)
            #pragma unroll
            for (int q = 0; q < 4; ++q) d[i][j][q] = 0.f;

    auto ldstage = [&](uint4* va, uint4* vx, int c0) {
        #pragma unroll
        for (int i = 0; i < 3; ++i) {
            int u = tid + (i << 9);
            int r = u >> 3, sg = u & 7;
            va[i] = *(const uint4*)&g_A2h[((size_t)b * CH + r) * CH + c0 + sg * 8];
        }
        #pragma unroll
        for (int i = 0; i < 2; ++i) {
            int u = tid + (i << 9);
            int r = u >> 4, c8 = (u & 15) << 3;
            vx[i] = *(const uint4*)&g_Xf[((size_t)b * CH + c0 + r) * HW + p0 + c8];
        }
    };
    auto ststage = [&](const uint4* va, const uint4* vx, int buf) {
        char* A2F = smem + buf * 40960;
        char* XF  = A2F + 24576;
        #pragma unroll
        for (int i = 0; i < 3; ++i) {
            int u = tid + (i << 9);
            int r = u >> 3, sg = u & 7;
            int sw = r * 128 + ((sg << 4) ^ ((r & 7) << 4));
            *(uint4*)(A2F + sw) = va[i];
        }
        #pragma unroll
        for (int i = 0; i < 2; ++i) {
            int u = tid + (i << 9);
            int r = u >> 4;
            int sw = r * 256 + ((((u & 15)) << 4) ^ ((r & 7) << 4));
            *(uint4*)(XF + sw) = vx[i];
        }
    };

    const int xorv = (lane & 7) << 4;
    const int mat = lane >> 3;
    const int halfA = (lane >> 4) << 4;
    const int rA15 = lane & 15;
    const int rbX = ((mat & 1) << 3) + (lane & 7);
    const int cbX = (n0p + ((mat >> 1) << 3)) * 2;

    auto stage_compute = [&](int buf) {
        uint32_t baseAF = sb + buf * 40960;
        uint32_t baseXF = baseAF + 24576;
        #pragma unroll 1
        for (int kk = 0; kk < 4; ++kk) {
            int colA = ((kk << 5) + halfA) ^ xorv;
            int xrow = (kk * 16 + rbX) * 256;
            uint32_t ah[3][4], bt[2][4];
            #pragma unroll
            for (int mi = 0; mi < 3; ++mi)
                ldsm4(ah[mi], baseAF + (m0 + 16*mi + rA15) * 128 + colA);
            #pragma unroll
            for (int jj = 0; jj < 2; ++jj)
                ldsm4t(bt[jj], baseXF + xrow + ((cbX + jj*32) ^ xorv));
            #pragma unroll
            for (int mi = 0; mi < 3; ++mi)
                #pragma unroll
                for (int jj = 0; jj < 2; ++jj) {
                    hmma16(d[mi][2*jj],     ah[mi], &bt[jj][0]);
                    hmma16(d[mi][2*jj + 1], ah[mi], &bt[jj][2]);
                }
        }
    };

    {
        uint4 va0[3], vx0[2];
        ldstage(va0, vx0, 0);
        ststage(va0, vx0, 0);
    }
    __syncthreads();
    for (int c = 0; c < 3; ++c) {
        uint4 va[3], vx[2];
        if (c < 2) ldstage(va, vx, (c + 1) * 64);
        stage_compute(c & 1);
        if (c < 2) ststage(va, vx, (c + 1) & 1);
        __syncthreads();
    }

    float* so = (float*)smem;
    int lr = lane >> 2, lc2 = (lane & 3) * 2;
    #pragma unroll
    for (int mi = 0; mi < 3; ++mi)
        #pragma unroll
        for (int nj = 0; nj < 4; ++nj) {
            int r = m0 + 16*mi + lr, cc = n0p + 8*nj + lc2;
            *(float2*)&so[r * 132 + cc]       = make_float2(d[mi][nj][0], d[mi][nj][1]);
            *(float2*)&so[(r + 8) * 132 + cc] = make_float2(d[mi][nj][2], d[mi][nj][3]);
        }
    __syncthreads();
    #pragma unroll
    for (int u = tid; u < 6144; u += 512) {
        int co = u >> 5, p4 = (u & 31) << 2;
        float4 v = *(const float4*)&so[co * 132 + p4];
        float bias = g_bp2[co];
        v.x = v.x * A2INV + bias;
        v.y = v.y * A2INV + bias;
        v.z = v.z * A2INV + bias;
        v.w = v.w * A2INV + bias;
        *(float4*)&out[((size_t)b * CH + co) * HW + p0 + p4] = v;
    }
}

// ---------------- small 192x192 GEMM core (optionally also writes C^T) ----------------
__device__ __forceinline__ void gemm_tile32(const float* __restrict__ Ab,
                                            const float* __restrict__ Bb,
                                            float* __restrict__ Cb,
                                            float* __restrict__ CbT,
                                            int i0, int j0) {
    __shared__ float As[16][34], Bs[16][34];
    int t = threadIdx.x;
    int tx = t & 15, ty = t >> 4;
    int li = t & 31, lkq = t >> 5;
    int lkb = t >> 4, lj2 = (t & 15) * 2;

    unsigned long long acc0 = 0ull, acc1 = 0ull;

    for (int kk = 0; kk < CH; kk += 16) {
        float2 av = *(const float2*)&Ab[(i0 + li) * CH + kk + lkq * 2];
        float2 bv = *(const float2*)&Bb[(kk + lkb) * CH + j0 + lj2];
        __syncthreads();
        As[lkq*2 + 0][li] = av.x;
        As[lkq*2 + 1][li] = av.y;
        *(float2*)&Bs[lkb][lj2] = bv;
        __syncthreads();
        #pragma unroll
        for (int k = 0; k < 16; ++k) {
            float2 a2 = *(const float2*)&As[k][ty * 2];
            unsigned long long b2 = *(const unsigned long long*)&Bs[k][tx * 2];
            fma2(acc0, pack2(a2.x, a2.x), b2);
            fma2(acc1, pack2(a2.y, a2.y), b2);
        }
    }
    float o00, o01, o10, o11;
    unpack2(acc0, o00, o01);
    unpack2(acc1, o10, o11);
    *(float2*)&Cb[(i0 + ty*2 + 0) * CH + j0 + tx*2] = make_float2(o00, o01);
    *(float2*)&Cb[(i0 + ty*2 + 1) * CH + j0 + tx*2] = make_float2(o10, o11);
    if (CbT) {
        *(float2*)&CbT[(j0 + tx*2 + 0) * CH + i0 + ty*2] = make_float2(o00, o10);
        *(float2*)&CbT[(j0 + tx*2 + 1) * CH + i0 + ty*2] = make_float2(o01, o11);
    }
}

// z=0..3: weight-combine GEMMs (z=0 also emits Wq'^T); z=4 block(0,0): bp2
__global__ __launch_bounds__(256) void prep_weights(const float* __restrict__ wq,
                                                    const float* __restrict__ wk,
                                                    const float* __restrict__ wv,
                                                    const float* __restrict__ wout,
                                                    const float* __restrict__ wsplit,
                                                    const float* __restrict__ wproj,
                                                    const float* __restrict__ bproj) {
    if (blockIdx.z == 4) {
        if (blockIdx.x == 0 && blockIdx.y == 0) {
            int f = threadIdx.x;
            if (f < CH) {
                float s = 0.f;
                for (int o = 0; o < CH; ++o) s += wout[f*CH+o] * bproj[o];
                g_bp2[f] = s;
            }
        }
        return;
    }
    const float *A, *B; float *C, *CT = nullptr;
    switch (blockIdx.z) {
        case 0:  A = wq;   B = wsplit; C = g_Wq;  CT = g_WqT; break;
        case 1:  A = wk;   B = wsplit; C = g_Wk;  break;
        case 2:  A = wv;   B = wsplit; C = g_Wv;  break;
        default: A = wout; B = wproj;  C = g_Wp2; break;
    }
    gemm_tile32(A, B, C, CT, blockIdx.x * 32, blockIdx.y * 32);
}

// ============ pk_gemm: P=Wq'·S (nq2 only) / K2=Wk'·S (stored + nk2) ============
// grid (6, 2, NB), 256 thr. Row-tile 32x192, fused diag-norm epilogue.
__global__ __launch_bounds__(256) void pk_gemm() {
    __shared__ float As[16][33];
    __shared__ float Bs[16][196];
    const int i0 = blockIdx.x * 32, which = blockIdx.y, b = blockIdx.z;
    const float* W = which ? g_Wk : g_Wq;
    const float* Sb = g_S + (size_t)b * CH * CH;
    const int tid = threadIdx.x;
    const int tx = tid & 31, ty = tid >> 5;

    unsigned long long acc[4][3];
    #pragma unroll
    for (int q = 0; q < 4; ++q)
        #pragma unroll
        for (int s = 0; s < 3; ++s) acc[q][s] = 0ull;

    for (int kk = 0; kk < CH; kk += 16) {
        {
            int r = tid >> 3, k2 = (tid & 7) * 2;
            float2 w = *(const float2*)&W[(i0 + r) * CH + kk + k2];
            As[k2][r] = w.x;
            As[k2 + 1][r] = w.y;
        }
        #pragma unroll
        for (int s = 0; s < 3; ++s) {
            int lin = s * 256 + tid;
            int kr = lin / 48, c4 = (lin % 48) * 4;
            *(float4*)&Bs[kr][c4] = *(const float4*)&Sb[(kk + kr) * CH + c4];
        }
        __syncthreads();
        #pragma unroll
        for (int k = 0; k < 16; ++k) {
            float a0 = As[k][ty], a1 = As[k][ty + 8], a2 = As[k][ty + 16], a3 = As[k][ty + 24];
            unsigned long long b0 = *(const unsigned long long*)&Bs[k][tx * 2];
            unsigned long long b1 = *(const unsigned long long*)&Bs[k][tx * 2 + 64];
            unsigned long long b2 = *(const unsigned long long*)&Bs[k][tx * 2 + 128];
            fma2(acc[0][0], pack2(a0, a0), b0); fma2(acc[0][1], pack2(a0, a0), b1); fma2(acc[0][2], pack2(a0, a0), b2);
            fma2(acc[1][0], pack2(a1, a1), b0); fma2(acc[1][1], pack2(a1, a1), b1); fma2(acc[1][2], pack2(a1, a1), b2);
            fma2(acc[2][0], pack2(a2, a2), b0); fma2(acc[2][1], pack2(a2, a2), b1); fma2(acc[2][2], pack2(a2, a2), b2);
            fma2(acc[3][0], pack2(a3, a3), b0); fma2(acc[3][1], pack2(a3, a3), b1); fma2(acc[3][2], pack2(a3, a3), b2);
        }
        __syncthreads();
    }

    // epilogue: optional K2 store + diag norm dot(row, W[row])
    float part[4] = {0.f, 0.f, 0.f, 0.f};
    #pragma unroll
    for (int q = 0; q < 4; ++q) {
        int row = i0 + ty + 8*q;
        #pragma unroll
        for (int s = 0; s < 3; ++s) {
            float lo, hi;
            unpack2(acc[q][s], lo, hi);
            int col = tx * 2 + s * 64;
            if (which)
                *(float2*)&g_K2[((size_t)b * CH + row) * CH + col] = make_float2(lo, hi);
            float2 wv = *(const float2*)&W[row * CH + col];
            part[q] += lo * wv.x + hi * wv.y;
        }
    }
    #pragma unroll
    for (int q = 0; q < 4; ++q) {
        #pragma unroll
        for (int o = 16; o > 0; o >>= 1)
            part[q] += __shfl_xor_sync(0xffffffffu, part[q], o);
        if (tx == 0)
            (which ? g_nk2 : g_nq2)[b * CH + i0 + ty + 8*q] = part[q];
    }
}

// ============ Fused: G = K2·Wq'^T (32x192 rows) + softmax -> attn. grid (6, NB) ============
__global__ __launch_bounds__(256) void g_softmax() {
    __shared__ float As[16][33];
    __shared__ float Bs[16][196];
    __shared__ float Gs[32][196];
    __shared__ float sdq[CH];
    const int b = blockIdx.y, i0 = blockIdx.x * 32;
    const int tid = threadIdx.x;
    const int tx = tid & 31, ty = tid >> 5;
    const float* K2b = g_K2 + (size_t)b * CH * CH;

    unsigned long long acc[4][3];
    #pragma unroll
    for (int q = 0; q < 4; ++q)
        #pragma unroll
        for (int s = 0; s < 3; ++s) acc[q][s] = 0ull;

    for (int kk = 0; kk < CH; kk += 16) {
        {
            int r = tid >> 3, k2 = (tid & 7) * 2;
            float2 w = *(const float2*)&K2b[(i0 + r) * CH + kk + k2];
            As[k2][r] = w.x;
            As[k2 + 1][r] = w.y;
        }
        #pragma unroll
        for (int s = 0; s < 3; ++s) {
            int lin = s * 256 + tid;
            int kr = lin / 48, c4 = (lin % 48) * 4;
            *(float4*)&Bs[kr][c4] = *(const float4*)&g_WqT[(kk + kr) * CH + c4];
        }
        __syncthreads();
        #pragma unroll
        for (int k = 0; k < 16; ++k) {
            float a0 = As[k][ty], a1 = As[k][ty + 8], a2 = As[k][ty + 16], a3 = As[k][ty + 24];
            unsigned long long b0 = *(const unsigned long long*)&Bs[k][tx * 2];
            unsigned long long b1 = *(const unsigned long long*)&Bs[k][tx * 2 + 64];
            unsigned long long b2 = *(const unsigned long long*)&Bs[k][tx * 2 + 128];
            fma2(acc[0][0], pack2(a0, a0), b0); fma2(acc[0][1], pack2(a0, a0), b1); fma2(acc[0][2], pack2(a0, a0), b2);
            fma2(acc[1][0], pack2(a1, a1), b0); fma2(acc[1][1], pack2(a1, a1), b1); fma2(acc[1][2], pack2(a1, a1), b2);
            fma2(acc[2][0], pack2(a2, a2), b0); fma2(acc[2][1], pack2(a2, a2), b1); fma2(acc[2][2], pack2(a2, a2), b2);
            fma2(acc[3][0], pack2(a3, a3), b0); fma2(acc[3][1], pack2(a3, a3), b1); fma2(acc[3][2], pack2(a3, a3), b2);
        }
        __syncthreads();
    }
    #pragma unroll
    for (int q = 0; q < 4; ++q)
        #pragma unroll
        for (int s = 0; s < 3; ++s) {
            float lo, hi;
            unpack2(acc[q][s], lo, hi);
            Gs[ty + 8*q][tx * 2 + s * 64]     = lo;
            Gs[ty + 8*q][tx * 2 + s * 64 + 1] = hi;
        }
    if (tid < CH) sdq[tid] = fmaxf(sqrtf(g_nq2[b * CH + tid]), EPSN);
    __syncthreads();

    const int w = tid >> 5, lane = tid & 31;
    #pragma unroll
    for (int rr = 0; rr < 4; ++rr) {
        int row = w * 4 + rr;
        float dk = fmaxf(sqrtf(g_nk2[b * CH + i0 + row]), EPSN);
        float L[6];
        #pragma unroll
        for (int t = 0; t < 6; ++t)
            L[t] = Gs[row][lane + 32 * t] / (dk * sdq[lane + 32 * t]);
        float m = L[0];
        #pragma unroll
        for (int t = 1; t < 6; ++t) m = fmaxf(m, L[t]);
        #pragma unroll
        for (int o = 16; o > 0; o >>= 1) m = fmaxf(m, __shfl_xor_sync(0xffffffffu, m, o));
        float e[6], sum = 0.f;
        #pragma unroll
        for (int t = 0; t < 6; ++t) { e[t] = expf(L[t] - m); sum += e[t]; }
        #pragma unroll
        for (int o = 16; o > 0; o >>= 1) sum += __shfl_xor_sync(0xffffffffu, sum, o);
        float inv = 1.f / sum;
        #pragma unroll
        for (int t = 0; t < 6; ++t)
            g_attn[((size_t)b * CH + i0 + row) * CH + lane + 32 * t] = e[t] * inv;
    }
}

// ============ Fused: A2 = (Wp2·attn)·Wv', scaled fp16 out. grid (6, NB) ============
__global__ __launch_bounds__(256) void a12_gemm() {
    __shared__ float As[16][33];
    __shared__ float Bs[16][196];
    __shared__ float A1t[192][33];
    const int b = blockIdx.y, i0 = blockIdx.x * 32;
    const int tid = threadIdx.x;
    const int tx = tid & 31, ty = tid >> 5;
    const float* attnb = g_attn + (size_t)b * CH * CH;

    unsigned long long acc[4][3];
    #pragma unroll
    for (int q = 0; q < 4; ++q)
        #pragma unroll
        for (int s = 0; s < 3; ++s) acc[q][s] = 0ull;

    for (int kk = 0; kk < CH; kk += 16) {
        {
            int r = tid >> 3, k2 = (tid & 7) * 2;
            float2 w = *(const float2*)&g_Wp2[(i0 + r) * CH + kk + k2];
            As[k2][r] = w.x;
            As[k2 + 1][r] = w.y;
        }
        #pragma unroll
        for (int s = 0; s < 3; ++s) {
            int lin = s * 256 + tid;
            int kr = lin / 48, c4 = (lin % 48) * 4;
            *(float4*)&Bs[kr][c4] = *(const float4*)&attnb[(kk + kr) * CH + c4];
        }
        __syncthreads();
        #pragma unroll
        for (int k = 0; k < 16; ++k) {
            float a0 = As[k][ty], a1 = As[k][ty + 8], a2 = As[k][ty + 16], a3 = As[k][ty + 24];
            unsigned long long b0 = *(const unsigned long long*)&Bs[k][tx * 2];
            unsigned long long b1 = *(const unsigned long long*)&Bs[k][tx * 2 + 64];
            unsigned long long b2 = *(const unsigned long long*)&Bs[k][tx * 2 + 128];
            fma2(acc[0][0], pack2(a0, a0), b0); fma2(acc[0][1], pack2(a0, a0), b1); fma2(acc[0][2], pack2(a0, a0), b2);
            fma2(acc[1][0], pack2(a1, a1), b0); fma2(acc[1][1], pack2(a1, a1), b1); fma2(acc[1][2], pack2(a1, a1), b2);
            fma2(acc[2][0], pack2(a2, a2), b0); fma2(acc[2][1], pack2(a2, a2), b1); fma2(acc[2][2], pack2(a2, a2), b2);
            fma2(acc[3][0], pack2(a3, a3), b0); fma2(acc[3][1], pack2(a3, a3), b1); fma2(acc[3][2], pack2(a3, a3), b2);
        }
        __syncthreads();
    }
    #pragma unroll
    for (int q = 0; q < 4; ++q)
        #pragma unroll
        for (int s = 0; s < 3; ++s) {
            float lo, hi;
            unpack2(acc[q][s], lo, hi);
            A1t[tx * 2 + s * 64][ty + 8*q]     = lo;
            A1t[tx * 2 + s * 64 + 1][ty + 8*q] = hi;
        }
    __syncthreads();

    unsigned long long acc2[4][3];
    #pragma unroll
    for (int q = 0; q < 4; ++q)
        #pragma unroll
        for (int s = 0; s < 3; ++s) acc2[q][s] = 0ull;

    for (int kk = 0; kk < CH; kk += 16) {
        #pragma unroll
        for (int s = 0; s < 3; ++s) {
            int lin = s * 256 + tid;
            int kr = lin / 48, c4 = (lin % 48) * 4;
            *(float4*)&Bs[kr][c4] = *(const float4*)&g_Wv[(kk + kr) * CH + c4];
        }
        __syncthreads();
        #pragma unroll
        for (int k = 0; k < 16; ++k) {
            float a0 = A1t[kk + k][ty], a1 = A1t[kk + k][ty + 8],
                  a2 = A1t[kk + k][ty + 16], a3 = A1t[kk + k][ty + 24];
            unsigned long long b0 = *(const unsigned long long*)&Bs[k][tx * 2];
            unsigned long long b1 = *(const unsigned long long*)&Bs[k][tx * 2 + 64];
            unsigned long long b2 = *(const unsigned long long*)&Bs[k][tx * 2 + 128];
            fma2(acc2[0][0], pack2(a0, a0), b0); fma2(acc2[0][1], pack2(a0, a0), b1); fma2(acc2[0][2], pack2(a0, a0), b2);
            fma2(acc2[1][0], pack2(a1, a1), b0); fma2(acc2[1][1], pack2(a1, a1), b1); fma2(acc2[1][2], pack2(a1, a1), b2);
            fma2(acc2[2][0], pack2(a2, a2), b0); fma2(acc2[2][1], pack2(a2, a2), b1); fma2(acc2[2][2], pack2(a2, a2), b2);
            fma2(acc2[3][0], pack2(a3, a3), b0); fma2(acc2[3][1], pack2(a3, a3), b1); fma2(acc2[3][2], pack2(a3, a3), b2);
        }
        __syncthreads();
    }
    #pragma unroll
    for (int q = 0; q < 4; ++q)
        #pragma unroll
        for (int s = 0; s < 3; ++s) {
            float lo, hi;
            unpack2(acc2[q][s], lo, hi);
            __half2 hv = __floats2half2_rn(lo * A2SCALE, hi * A2SCALE);
            *(__half2*)&g_A2h[((size_t)b * CH + i0 + ty + 8*q) * CH + tx * 2 + s * 64] = hv;
        }
}

// ---------------- launch ----------------
extern "C" void kernel_launch(void* const* d_in, const int* in_sizes, int n_in,
                              void* d_out, int out_size) {
    const float* x_in   = (const float*)d_in[0];
    const float* w_split= (const float*)d_in[1];
    const float* w_q    = (const float*)d_in[2];
    const float* w_k    = (const float*)d_in[3];
    const float* w_v    = (const float*)d_in[4];
    const float* w_proj = (const float*)d_in[5];
    const float* b_proj = (const float*)d_in[6];
    const float* w_out  = (const float*)d_in[7];
    float* out = (float*)d_out;

    cudaFuncSetAttribute(xxt_mma, cudaFuncAttributeMaxDynamicSharedMemorySize, 49152);
    cudaFuncSetAttribute(out_mma, cudaFuncAttributeMaxDynamicSharedMemorySize, 101376);

    // S partials (upper band, fp16 single-term); also emits g_Xf
    xxt_mma<<<dim3(KSPLIT1, NB), 512, 49152>>>(x_in);

    // combined channel maps (+Wq'^T) + bias (one launch)
    prep_weights<<<dim3(6,6,5), 256>>>(w_q, w_k, w_v, w_out, w_split, w_proj, b_proj);

    // S = sum_p S_p with symmetrization
    s_reduce<<<dim3(6,6,NB), 256>>>();

    // P/K2 + fused diag norms (replaces t12_gemm + diag_norms)
    pk_gemm<<<dim3(6,2,NB), 256>>>();

    // G = K2·Wq'^T + softmax fused -> attn
    g_softmax<<<dim3(6,NB), 256>>>();

    // A2 = (Wp2·attn)·Wv', fp16
    a12_gemm<<<dim3(6,NB), 256>>>();

    // out = A2f Xf + bp2
    out_mma<<<dim3(HW/128, NB), 512, 101376>>>(out);
}

// round 16
// speedup vs baseline: 3.6743x; 1.0013x over previous
#include <cuda_runtime.h>
#include <cuda_fp16.h>
#include <cstdint>

#define CH 192
#define NB 8
#define HW 16384
#define KSPLIT1 16
#define EPSN 1e-12f
#define A2SCALE 4096.0f
#define A2INV   (1.0f/4096.0f)

// ---------------- mma.sync / ldmatrix helpers ----------------
__device__ __forceinline__ uint32_t smem_u32(const void* p) {
    uint32_t a;
    asm("{ .reg .u64 t; cvta.to.shared.u64 t, %1; cvt.u32.u64 %0, t; }" : "=r"(a) : "l"(p));
    return a;
}
__device__ __forceinline__ void hmma16(float* d, const uint32_t* a, const uint32_t* b) {
    asm volatile("mma.sync.aligned.m16n8k16.row.col.f32.f16.f16.f32 "
        "{%0,%1,%2,%3}, {%4,%5,%6,%7}, {%8,%9}, {%0,%1,%2,%3};"
        : "+f"(d[0]), "+f"(d[1]), "+f"(d[2]), "+f"(d[3])
        : "r"(a[0]), "r"(a[1]), "r"(a[2]), "r"(a[3]), "r"(b[0]), "r"(b[1]));
}
__device__ __forceinline__ void ldsm4(uint32_t* r, uint32_t a) {
    asm volatile("ldmatrix.sync.aligned.m8n8.x4.shared.b16 {%0,%1,%2,%3}, [%4];"
        : "=r"(r[0]), "=r"(r[1]), "=r"(r[2]), "=r"(r[3]) : "r"(a));
}
__device__ __forceinline__ void ldsm4t(uint32_t* r, uint32_t a) {
    asm volatile("ldmatrix.sync.aligned.m8n8.x4.trans.shared.b16 {%0,%1,%2,%3}, [%4];"
        : "=r"(r[0]), "=r"(r[1]), "=r"(r[2]), "=r"(r[3]) : "r"(a));
}
__device__ __forceinline__ uint32_t f2h2(float x, float y) {
    __half2 h = __floats2half2_rn(x, y);
    return *reinterpret_cast<uint32_t*>(&h);
}

// ---------------- packed f32x2 helpers ----------------
__device__ __forceinline__ unsigned long long pack2(float lo, float hi) {
    unsigned long long r;
    asm("mov.b64 %0, {%1, %2};" : "=l"(r) : "f"(lo), "f"(hi));
    return r;
}
__device__ __forceinline__ void unpack2(unsigned long long v, float& lo, float& hi) {
    asm("mov.b64 {%0, %1}, %2;" : "=f"(lo), "=f"(hi) : "l"(v));
}
__device__ __forceinline__ void fma2(unsigned long long& d, unsigned long long a, unsigned long long b) {
    asm("fma.rn.f32x2 %0, %1, %2, %0;" : "+l"(d) : "l"(a), "l"(b));
}

// ---------------- scratch ----------------
__device__ float g_Wq[CH*CH], g_WqT[CH*CH], g_Wk[CH*CH], g_Wv[CH*CH], g_Wp2[CH*CH], g_bp2[CH];
__device__ float g_Spart[NB*KSPLIT1*CH*CH];
__device__ float g_S[NB*CH*CH], g_K2[NB*CH*CH];
__device__ float g_attn[NB*CH*CH];
__device__ float g_nk2[NB*CH], g_nq2[NB*CH];
__device__ __half g_A2h[NB*CH*CH];         // A2 * A2SCALE, fp16
__device__ __half g_Xf[(size_t)NB*CH*HW];  // X in fp16 (written by xxt_mma)

// Upper-band 16x48 tiles
__constant__ int cTI[30] = {0,0,0,0, 1,1,1,1, 2,2,2,2, 3,3,3, 4,4,4, 5,5,5, 6,6, 7,7, 8,8, 9, 10, 11};
__constant__ int cTJ[30] = {0,1,2,3, 0,1,2,3, 0,1,2,3, 1,2,3, 1,2,3, 1,2,3, 2,3, 2,3, 2,3, 3, 3, 3};

// ============ GEMM1: S_p[b] = Xf Xf^T upper band only, split-K ============
__global__ __launch_bounds__(512) void xxt_mma(const float* __restrict__ xin) {
    extern __shared__ char smem[];
    const int tid = threadIdx.x, wid = tid >> 5, lane = tid & 31;
    const int split = blockIdx.x, b = blockIdx.y;
    const float* Xb = xin + (size_t)b * CH * HW;
    const int kbase = split * (HW / KSPLIT1);
    const uint32_t sb = smem_u32(smem);

    const int i0a = cTI[wid] * 16, j0a = cTJ[wid] * 48;
    const bool has2 = (wid < 14);
    const int i0b = has2 ? cTI[wid + 16] * 16 : 0;
    const int j0b = has2 ? cTJ[wid + 16] * 48 : 0;

    float dA[6][4], dB[6][4];
    #pragma unroll
    for (int j = 0; j < 6; ++j)
        #pragma unroll
        for (int q = 0; q < 4; ++q) { dA[j][q] = 0.f; dB[j][q] = 0.f; }

    auto ldx = [&](float4* v, int kb) {
        #pragma unroll
        for (int i = 0; i < 6; ++i) {
            int u = tid + (i << 9);
            int r = u >> 4, k4 = (u & 15) << 2;
            v[i] = *(const float4*)&Xb[(size_t)r * HW + kb + k4];
        }
    };
    auto stx = [&](const float4* v, int buf, int kb) {
        char* XF = smem + buf * 24576;
        #pragma unroll
        for (int i = 0; i < 6; ++i) {
            int u = tid + (i << 9);
            int r = u >> 4, k4 = (u & 15) << 2;
            uint2 hw = make_uint2(f2h2(v[i].x, v[i].y), f2h2(v[i].z, v[i].w));
            int sw = r * 128 + (((u & 15) << 3) ^ ((r & 7) << 4));
            *(uint2*)(XF + sw) = hw;
            *(uint2*)&g_Xf[((size_t)b * CH + r) * HW + kb + k4] = hw;
        }
    };

    const int xorv = (lane & 7) << 4;
    const int mat = lane >> 3;
    const int halfA = (lane >> 4) << 4;
    const int halfB = (mat & 1) << 4;
    const int rA15 = lane & 15;
    const int rB = ((mat >> 1) << 3) + (lane & 7);

    auto stage_compute = [&](int buf) {
        uint32_t base = sb + buf * 24576;
        #pragma unroll 1
        for (int kk = 0; kk < 4; ++kk) {
            int colA = ((kk << 5) + halfA) ^ xorv;
            int colB = ((kk << 5) + halfB) ^ xorv;
            uint32_t ah[4], bh[3][4];
            ldsm4(ah, base + (i0a + rA15) * 128 + colA);
            #pragma unroll
            for (int jj = 0; jj < 3; ++jj)
                ldsm4(bh[jj], base + (j0a + jj*16 + rB) * 128 + colB);
            #pragma unroll
            for (int jj = 0; jj < 3; ++jj) {
                hmma16(dA[2*jj],     ah, &bh[jj][0]);
                hmma16(dA[2*jj + 1], ah, &bh[jj][2]);
            }
            if (has2) {
                uint32_t ah2[4], bh2[3][4];
                ldsm4(ah2, base + (i0b + rA15) * 128 + colA);
                #pragma unroll
                for (int jj = 0; jj < 3; ++jj)
                    ldsm4(bh2[jj], base + (j0b + jj*16 + rB) * 128 + colB);
                #pragma unroll
                for (int jj = 0; jj < 3; ++jj) {
                    hmma16(dB[2*jj],     ah2, &bh2[jj][0]);
                    hmma16(dB[2*jj + 1], ah2, &bh2[jj][2]);
                }
            }
        }
    };

    {
        float4 v0[6];
        ldx(v0, kbase);
        stx(v0, 0, kbase);
    }
    __syncthreads();
    for (int c = 0; c < 16; ++c) {
        float4 vn[6];
        if (c < 15) ldx(vn, kbase + (c + 1) * 64);
        stage_compute(c & 1);
        if (c < 15) stx(vn, (c + 1) & 1, kbase + (c + 1) * 64);
        __syncthreads();
    }

    float* Sp = g_Spart + (size_t)(b * KSPLIT1 + split) * CH * CH;
    int lr = lane >> 2, lc2 = (lane & 3) * 2;
    #pragma unroll
    for (int nj = 0; nj < 6; ++nj) {
        int r = i0a + lr, cc = j0a + 8*nj + lc2;
        *(float2*)&Sp[r * CH + cc]       = make_float2(dA[nj][0], dA[nj][1]);
        *(float2*)&Sp[(r + 8) * CH + cc] = make_float2(dA[nj][2], dA[nj][3]);
    }
    if (has2) {
        #pragma unroll
        for (int nj = 0; nj < 6; ++nj) {
            int r = i0b + lr, cc = j0b + 8*nj + lc2;
            *(float2*)&Sp[r * CH + cc]       = make_float2(dB[nj][0], dB[nj][1]);
            *(float2*)&Sp[(r + 8) * CH + cc] = make_float2(dB[nj][2], dB[nj][3]);
        }
    }
}

__device__ __forceinline__ bool s_cov(int r, int c) {
    return (48 * (c / 48) + 47) >= (16 * (r / 16));
}

// S = sum_p S_p with symmetrization. grid (6,6,NB), 256 thr.
__global__ __launch_bounds__(256) void s_reduce() {
    __shared__ float tb[32][33];
    const int b = blockIdx.z, I0 = blockIdx.x * 32, J0 = blockIdx.y * 32;
    const int c = threadIdx.x & 31, ty = threadIdx.x >> 5;
    const float* Sp = g_Spart + (size_t)b * KSPLIT1 * CH * CH;

    const int ibmin = I0 >> 4, ibmax = (I0 + 31) >> 4;
    const int jbmin = J0 / 48, jbmax = (J0 + 31) / 48;
    const bool fullCov = (48 * jbmin + 47) >= (16 * ibmax);
    const bool fullUnc = (48 * jbmax + 47) < (16 * ibmin);

    float dsum[4];
    if (!fullUnc) {
        #pragma unroll
        for (int q = 0; q < 4; ++q) {
            int r = I0 + ty + 8*q;
            float s = 0.f;
            #pragma unroll
            for (int p = 0; p < KSPLIT1; ++p)
                s += Sp[(size_t)p*CH*CH + r*CH + J0 + c];
            dsum[q] = s;
        }
    }
    if (!fullCov) {
        #pragma unroll
        for (int q = 0; q < 4; ++q) {
            int rr = J0 + ty + 8*q;
            float s = 0.f;
            #pragma unroll
            for (int p = 0; p < KSPLIT1; ++p)
                s += Sp[(size_t)p*CH*CH + rr*CH + I0 + c];
            tb[ty + 8*q][c] = s;
        }
        __syncthreads();
    }
    float* Sb = g_S + (size_t)b * CH * CH;
    #pragma unroll
    for (int q = 0; q < 4; ++q) {
        int r = I0 + ty + 8*q, cc = J0 + c;
        float v;
        if (fullCov)      v = dsum[q];
        else if (fullUnc) v = tb[c][ty + 8*q];
        else              v = s_cov(r, cc) ? dsum[q] : tb[c][ty + 8*q];
        Sb[r * CH + cc] = v;
    }
}

// ============ GEMM2: out[b] = A2f·Xf * A2INV + bp2 ============
__global__ __launch_bounds__(512) void out_mma(float* __restrict__ out) {
    extern __shared__ char smem[];
    const int tid = threadIdx.x, wid = tid >> 5, lane = tid & 31;
    const int p0 = blockIdx.x * 128, b = blockIdx.y;
    const uint32_t sb = smem_u32(smem);
    const int m0 = (wid >> 2) * 48, n0p = (wid & 3) * 32;

    float d[3][4][4];
    #pragma unroll
    for (int i = 0; i < 3; ++i)
        #pragma unroll
        for (int j = 0; j < 4; ++j)
            #pragma unroll
            for (int q = 0; q < 4; ++q) d[i][j][q] = 0.f;

    auto ldstage = [&](uint4* va, uint4* vx, int c0) {
        #pragma unroll
        for (int i = 0; i < 3; ++i) {
            int u = tid + (i << 9);
            int r = u >> 3, sg = u & 7;
            va[i] = *(const uint4*)&g_A2h[((size_t)b * CH + r) * CH + c0 + sg * 8];
        }
        #pragma unroll
        for (int i = 0; i < 2; ++i) {
            int u = tid + (i << 9);
            int r = u >> 4, c8 = (u & 15) << 3;
            vx[i] = *(const uint4*)&g_Xf[((size_t)b * CH + c0 + r) * HW + p0 + c8];
        }
    };
    auto ststage = [&](const uint4* va, const uint4* vx, int buf) {
        char* A2F = smem + buf * 40960;
        char* XF  = A2F + 24576;
        #pragma unroll
        for (int i = 0; i < 3; ++i) {
            int u = tid + (i << 9);
            int r = u >> 3, sg = u & 7;
            int sw = r * 128 + ((sg << 4) ^ ((r & 7) << 4));
            *(uint4*)(A2F + sw) = va[i];
        }
        #pragma unroll
        for (int i = 0; i < 2; ++i) {
            int u = tid + (i << 9);
            int r = u >> 4;
            int sw = r * 256 + ((((u & 15)) << 4) ^ ((r & 7) << 4));
            *(uint4*)(XF + sw) = vx[i];
        }
    };

    const int xorv = (lane & 7) << 4;
    const int mat = lane >> 3;
    const int halfA = (lane >> 4) << 4;
    const int rA15 = lane & 15;
    const int rbX = ((mat & 1) << 3) + (lane & 7);
    const int cbX = (n0p + ((mat >> 1) << 3)) * 2;

    auto stage_compute = [&](int buf) {
        uint32_t baseAF = sb + buf * 40960;
        uint32_t baseXF = baseAF + 24576;
        #pragma unroll 1
        for (int kk = 0; kk < 4; ++kk) {
            int colA = ((kk << 5) + halfA) ^ xorv;
            int xrow = (kk * 16 + rbX) * 256;
            uint32_t ah[3][4], bt[2][4];
            #pragma unroll
            for (int mi = 0; mi < 3; ++mi)
                ldsm4(ah[mi], baseAF + (m0 + 16*mi + rA15) * 128 + colA);
            #pragma unroll
            for (int jj = 0; jj < 2; ++jj)
                ldsm4t(bt[jj], baseXF + xrow + ((cbX + jj*32) ^ xorv));
            #pragma unroll
            for (int mi = 0; mi < 3; ++mi)
                #pragma unroll
                for (int jj = 0; jj < 2; ++jj) {
                    hmma16(d[mi][2*jj],     ah[mi], &bt[jj][0]);
                    hmma16(d[mi][2*jj + 1], ah[mi], &bt[jj][2]);
                }
        }
    };

    {
        uint4 va0[3], vx0[2];
        ldstage(va0, vx0, 0);
        ststage(va0, vx0, 0);
    }
    __syncthreads();
    for (int c = 0; c < 3; ++c) {
        uint4 va[3], vx[2];
        if (c < 2) ldstage(va, vx, (c + 1) * 64);
        stage_compute(c & 1);
        if (c < 2) ststage(va, vx, (c + 1) & 1);
        __syncthreads();
    }

    float* so = (float*)smem;
    int lr = lane >> 2, lc2 = (lane & 3) * 2;
    #pragma unroll
    for (int mi = 0; mi < 3; ++mi)
        #pragma unroll
        for (int nj = 0; nj < 4; ++nj) {
            int r = m0 + 16*mi + lr, cc = n0p + 8*nj + lc2;
            *(float2*)&so[r * 132 + cc]       = make_float2(d[mi][nj][0], d[mi][nj][1]);
            *(float2*)&so[(r + 8) * 132 + cc] = make_float2(d[mi][nj][2], d[mi][nj][3]);
        }
    __syncthreads();
    #pragma unroll
    for (int u = tid; u < 6144; u += 512) {
        int co = u >> 5, p4 = (u & 31) << 2;
        float4 v = *(const float4*)&so[co * 132 + p4];
        float bias = g_bp2[co];
        v.x = v.x * A2INV + bias;
        v.y = v.y * A2INV + bias;
        v.z = v.z * A2INV + bias;
        v.w = v.w * A2INV + bias;
        *(float4*)&out[((size_t)b * CH + co) * HW + p0 + p4] = v;
    }
}

// ---------------- small 192x192 GEMM core (optionally also writes C^T) ----------------
__device__ __forceinline__ void gemm_tile32(const float* __restrict__ Ab,
                                            const float* __restrict__ Bb,
                                            float* __restrict__ Cb,
                                            float* __restrict__ CbT,
                                            int i0, int j0) {
    __shared__ float As[16][34], Bs[16][34];
    int t = threadIdx.x;
    int tx = t & 15, ty = t >> 4;
    int li = t & 31, lkq = t >> 5;
    int lkb = t >> 4, lj2 = (t & 15) * 2;

    unsigned long long acc0 = 0ull, acc1 = 0ull;

    for (int kk = 0; kk < CH; kk += 16) {
        float2 av = *(const float2*)&Ab[(i0 + li) * CH + kk + lkq * 2];
        float2 bv = *(const float2*)&Bb[(kk + lkb) * CH + j0 + lj2];
        __syncthreads();
        As[lkq*2 + 0][li] = av.x;
        As[lkq*2 + 1][li] = av.y;
        *(float2*)&Bs[lkb][lj2] = bv;
        __syncthreads();
        #pragma unroll
        for (int k = 0; k < 16; ++k) {
            float2 a2 = *(const float2*)&As[k][ty * 2];
            unsigned long long b2 = *(const unsigned long long*)&Bs[k][tx * 2];
            fma2(acc0, pack2(a2.x, a2.x), b2);
            fma2(acc1, pack2(a2.y, a2.y), b2);
        }
    }
    float o00, o01, o10, o11;
    unpack2(acc0, o00, o01);
    unpack2(acc1, o10, o11);
    *(float2*)&Cb[(i0 + ty*2 + 0) * CH + j0 + tx*2] = make_float2(o00, o01);
    *(float2*)&Cb[(i0 + ty*2 + 1) * CH + j0 + tx*2] = make_float2(o10, o11);
    if (CbT) {
        *(float2*)&CbT[(j0 + tx*2 + 0) * CH + i0 + ty*2] = make_float2(o00, o10);
        *(float2*)&CbT[(j0 + tx*2 + 1) * CH + i0 + ty*2] = make_float2(o01, o11);
    }
}

// z=0..3: weight-combine GEMMs (z=0 also emits Wq'^T); z=4 block(0,0): bp2
__global__ __launch_bounds__(256) void prep_weights(const float* __restrict__ wq,
                                                    const float* __restrict__ wk,
                                                    const float* __restrict__ wv,
                                                    const float* __restrict__ wout,
                                                    const float* __restrict__ wsplit,
                                                    const float* __restrict__ wproj,
                                                    const float* __restrict__ bproj) {
    if (blockIdx.z == 4) {
        if (blockIdx.x == 0 && blockIdx.y == 0) {
            int f = threadIdx.x;
            if (f < CH) {
                float s = 0.f;
                for (int o = 0; o < CH; ++o) s += wout[f*CH+o] * bproj[o];
                g_bp2[f] = s;
            }
        }
        return;
    }
    const float *A, *B; float *C, *CT = nullptr;
    switch (blockIdx.z) {
        case 0:  A = wq;   B = wsplit; C = g_Wq;  CT = g_WqT; break;
        case 1:  A = wk;   B = wsplit; C = g_Wk;  break;
        case 2:  A = wv;   B = wsplit; C = g_Wv;  break;
        default: A = wout; B = wproj;  C = g_Wp2; break;
    }
    gemm_tile32(A, B, C, CT, blockIdx.x * 32, blockIdx.y * 32);
}

// ============ pk_gemm: P=Wq'·S (nq2 only) / K2=Wk'·S (stored + nk2) ============
// grid (6, 2, NB), 256 thr. Row-tile 32x192, fused diag-norm epilogue.
__global__ __launch_bounds__(256) void pk_gemm() {
    __shared__ float As[16][33];
    __shared__ float Bs[16][196];
    const int i0 = blockIdx.x * 32, which = blockIdx.y, b = blockIdx.z;
    const float* W = which ? g_Wk : g_Wq;
    const float* Sb = g_S + (size_t)b * CH * CH;
    const int tid = threadIdx.x;
    const int tx = tid & 31, ty = tid >> 5;

    unsigned long long acc[4][3];
    #pragma unroll
    for (int q = 0; q < 4; ++q)
        #pragma unroll
        for (int s = 0; s < 3; ++s) acc[q][s] = 0ull;

    for (int kk = 0; kk < CH; kk += 16) {
        {
            int r = tid >> 3, k2 = (tid & 7) * 2;
            float2 w = *(const float2*)&W[(i0 + r) * CH + kk + k2];
            As[k2][r] = w.x;
            As[k2 + 1][r] = w.y;
        }
        #pragma unroll
        for (int s = 0; s < 3; ++s) {
            int lin = s * 256 + tid;
            int kr = lin / 48, c4 = (lin % 48) * 4;
            *(float4*)&Bs[kr][c4] = *(const float4*)&Sb[(kk + kr) * CH + c4];
        }
        __syncthreads();
        #pragma unroll
        for (int k = 0; k < 16; ++k) {
            float a0 = As[k][ty], a1 = As[k][ty + 8], a2 = As[k][ty + 16], a3 = As[k][ty + 24];
            unsigned long long b0 = *(const unsigned long long*)&Bs[k][tx * 2];
            unsigned long long b1 = *(const unsigned long long*)&Bs[k][tx * 2 + 64];
            unsigned long long b2 = *(const unsigned long long*)&Bs[k][tx * 2 + 128];
            fma2(acc[0][0], pack2(a0, a0), b0); fma2(acc[0][1], pack2(a0, a0), b1); fma2(acc[0][2], pack2(a0, a0), b2);
            fma2(acc[1][0], pack2(a1, a1), b0); fma2(acc[1][1], pack2(a1, a1), b1); fma2(acc[1][2], pack2(a1, a1), b2);
            fma2(acc[2][0], pack2(a2, a2), b0); fma2(acc[2][1], pack2(a2, a2), b1); fma2(acc[2][2], pack2(a2, a2), b2);
            fma2(acc[3][0], pack2(a3, a3), b0); fma2(acc[3][1], pack2(a3, a3), b1); fma2(acc[3][2], pack2(a3, a3), b2);
        }
        __syncthreads();
    }

    // epilogue: optional K2 store + diag norm dot(row, W[row])
    float part[4] = {0.f, 0.f, 0.f, 0.f};
    #pragma unroll
    for (int q = 0; q < 4; ++q) {
        int row = i0 + ty + 8*q;
        #pragma unroll
        for (int s = 0; s < 3; ++s) {
            float lo, hi;
            unpack2(acc[q][s], lo, hi);
            int col = tx * 2 + s * 64;
            if (which)
                *(float2*)&g_K2[((size_t)b * CH + row) * CH + col] = make_float2(lo, hi);
            float2 wv = *(const float2*)&W[row * CH + col];
            part[q] += lo * wv.x + hi * wv.y;
        }
    }
    #pragma unroll
    for (int q = 0; q < 4; ++q) {
        #pragma unroll
        for (int o = 16; o > 0; o >>= 1)
            part[q] += __shfl_xor_sync(0xffffffffu, part[q], o);
        if (tx == 0)
            (which ? g_nk2 : g_nq2)[b * CH + i0 + ty + 8*q] = part[q];
    }
}

// ============ Fused: G = K2·Wq'^T (32x192 rows) + softmax -> attn. grid (6, NB) ============
__global__ __launch_bounds__(256) void g_softmax() {
    __shared__ float As[16][33];
    __shared__ float Bs[16][196];
    __shared__ float Gs[32][196];
    __shared__ float sdq[CH];
    const int b = blockIdx.y, i0 = blockIdx.x * 32;
    const int tid = threadIdx.x;
    const int tx = tid & 31, ty = tid >> 5;
    const float* K2b = g_K2 + (size_t)b * CH * CH;

    unsigned long long acc[4][3];
    #pragma unroll
    for (int q = 0; q < 4; ++q)
        #pragma unroll
        for (int s = 0; s < 3; ++s) acc[q][s] = 0ull;

    for (int kk = 0; kk < CH; kk += 16) {
        {
            int r = tid >> 3, k2 = (tid & 7) * 2;
            float2 w = *(const float2*)&K2b[(i0 + r) * CH + kk + k2];
            As[k2][r] = w.x;
            As[k2 + 1][r] = w.y;
        }
        #pragma unroll
        for (int s = 0; s < 3; ++s) {
            int lin = s * 256 + tid;
            int kr = lin / 48, c4 = (lin % 48) * 4;
            *(float4*)&Bs[kr][c4] = *(const float4*)&g_WqT[(kk + kr) * CH + c4];
        }
        __syncthreads();
        #pragma unroll
        for (int k = 0; k < 16; ++k) {
            float a0 = As[k][ty], a1 = As[k][ty + 8], a2 = As[k][ty + 16], a3 = As[k][ty + 24];
            unsigned long long b0 = *(const unsigned long long*)&Bs[k][tx * 2];
            unsigned long long b1 = *(const unsigned long long*)&Bs[k][tx * 2 + 64];
            unsigned long long b2 = *(const unsigned long long*)&Bs[k][tx * 2 + 128];
            fma2(acc[0][0], pack2(a0, a0), b0); fma2(acc[0][1], pack2(a0, a0), b1); fma2(acc[0][2], pack2(a0, a0), b2);
            fma2(acc[1][0], pack2(a1, a1), b0); fma2(acc[1][1], pack2(a1, a1), b1); fma2(acc[1][2], pack2(a1, a1), b2);
            fma2(acc[2][0], pack2(a2, a2), b0); fma2(acc[2][1], pack2(a2, a2), b1); fma2(acc[2][2], pack2(a2, a2), b2);
            fma2(acc[3][0], pack2(a3, a3), b0); fma2(acc[3][1], pack2(a3, a3), b1); fma2(acc[3][2], pack2(a3, a3), b2);
        }
        __syncthreads();
    }
    #pragma unroll
    for (int q = 0; q < 4; ++q)
        #pragma unroll
        for (int s = 0; s < 3; ++s) {
            float lo, hi;
            unpack2(acc[q][s], lo, hi);
            Gs[ty + 8*q][tx * 2 + s * 64]     = lo;
            Gs[ty + 8*q][tx * 2 + s * 64 + 1] = hi;
        }
    if (tid < CH) sdq[tid] = fmaxf(sqrtf(g_nq2[b * CH + tid]), EPSN);
    __syncthreads();

    const int w = tid >> 5, lane = tid & 31;
    #pragma unroll
    for (int rr = 0; rr < 4; ++rr) {
        int row = w * 4 + rr;
        float dk = fmaxf(sqrtf(g_nk2[b * CH + i0 + row]), EPSN);
        float L[6];
        #pragma unroll
        for (int t = 0; t < 6; ++t)
            L[t] = Gs[row][lane + 32 * t] / (dk * sdq[lane + 32 * t]);
        float m = L[0];
        #pragma unroll
        for (int t = 1; t < 6; ++t) m = fmaxf(m, L[t]);
        #pragma unroll
        for (int o = 16; o > 0; o >>= 1) m = fmaxf(m, __shfl_xor_sync(0xffffffffu, m, o));
        float e[6], sum = 0.f;
        #pragma unroll
        for (int t = 0; t < 6; ++t) { e[t] = expf(L[t] - m); sum += e[t]; }
        #pragma unroll
        for (int o = 16; o > 0; o >>= 1) sum += __shfl_xor_sync(0xffffffffu, sum, o);
        float inv = 1.f / sum;
        #pragma unroll
        for (int t = 0; t < 6; ++t)
            g_attn[((size_t)b * CH + i0 + row) * CH + lane + 32 * t] = e[t] * inv;
    }
}

// ============ Fused: A2 = (Wp2·attn)·Wv', scaled fp16 out. grid (6, NB) ============
__global__ __launch_bounds__(256) void a12_gemm() {
    __shared__ float As[16][33];
    __shared__ float Bs[16][196];
    __shared__ float A1t[192][33];
    const int b = blockIdx.y, i0 = blockIdx.x * 32;
    const int tid = threadIdx.x;
    const int tx = tid & 31, ty = tid >> 5;
    const float* attnb = g_attn + (size_t)b * CH * CH;

    unsigned long long acc[4][3];
    #pragma unroll
    for (int q = 0; q < 4; ++q)
        #pragma unroll
        for (int s = 0; s < 3; ++s) acc[q][s] = 0ull;

    for (int kk = 0; kk < CH; kk += 16) {
        {
            int r = tid >> 3, k2 = (tid & 7) * 2;
            float2 w = *(const float2*)&g_Wp2[(i0 + r) * CH + kk + k2];
            As[k2][r] = w.x;
            As[k2 + 1][r] = w.y;
        }
        #pragma unroll
        for (int s = 0; s < 3; ++s) {
            int lin = s * 256 + tid;
            int kr = lin / 48, c4 = (lin % 48) * 4;
            *(float4*)&Bs[kr][c4] = *(const float4*)&attnb[(kk + kr) * CH + c4];
        }
        __syncthreads();
        #pragma unroll
        for (int k = 0; k < 16; ++k) {
            float a0 = As[k][ty], a1 = As[k][ty + 8], a2 = As[k][ty + 16], a3 = As[k][ty + 24];
            unsigned long long b0 = *(const unsigned long long*)&Bs[k][tx * 2];
            unsigned long long b1 = *(const unsigned long long*)&Bs[k][tx * 2 + 64];
            unsigned long long b2 = *(const unsigned long long*)&Bs[k][tx * 2 + 128];
            fma2(acc[0][0], pack2(a0, a0), b0); fma2(acc[0][1], pack2(a0, a0), b1); fma2(acc[0][2], pack2(a0, a0), b2);
            fma2(acc[1][0], pack2(a1, a1), b0); fma2(acc[1][1], pack2(a1, a1), b1); fma2(acc[1][2], pack2(a1, a1), b2);
            fma2(acc[2][0], pack2(a2, a2), b0); fma2(acc[2][1], pack2(a2, a2), b1); fma2(acc[2][2], pack2(a2, a2), b2);
            fma2(acc[3][0], pack2(a3, a3), b0); fma2(acc[3][1], pack2(a3, a3), b1); fma2(acc[3][2], pack2(a3, a3), b2);
        }
        __syncthreads();
    }
    #pragma unroll
    for (int q = 0; q < 4; ++q)
        #pragma unroll
        for (int s = 0; s < 3; ++s) {
            float lo, hi;
            unpack2(acc[q][s], lo, hi);
            A1t[tx * 2 + s * 64][ty + 8*q]     = lo;
            A1t[tx * 2 + s * 64 + 1][ty + 8*q] = hi;
        }
    __syncthreads();

    unsigned long long acc2[4][3];
    #pragma unroll
    for (int q = 0; q < 4; ++q)
        #pragma unroll
        for (int s = 0; s < 3; ++s) acc2[q][s] = 0ull;

    for (int kk = 0; kk < CH; kk += 16) {
        #pragma unroll
        for (int s = 0; s < 3; ++s) {
            int lin = s * 256 + tid;
            int kr = lin / 48, c4 = (lin % 48) * 4;
            *(float4*)&Bs[kr][c4] = *(const float4*)&g_Wv[(kk + kr) * CH + c4];
        }
        __syncthreads();
        #pragma unroll
        for (int k = 0; k < 16; ++k) {
            float a0 = A1t[kk + k][ty], a1 = A1t[kk + k][ty + 8],
                  a2 = A1t[kk + k][ty + 16], a3 = A1t[kk + k][ty + 24];
            unsigned long long b0 = *(const unsigned long long*)&Bs[k][tx * 2];
            unsigned long long b1 = *(const unsigned long long*)&Bs[k][tx * 2 + 64];
            unsigned long long b2 = *(const unsigned long long*)&Bs[k][tx * 2 + 128];
            fma2(acc2[0][0], pack2(a0, a0), b0); fma2(acc2[0][1], pack2(a0, a0), b1); fma2(acc2[0][2], pack2(a0, a0), b2);
            fma2(acc2[1][0], pack2(a1, a1), b0); fma2(acc2[1][1], pack2(a1, a1), b1); fma2(acc2[1][2], pack2(a1, a1), b2);
            fma2(acc2[2][0], pack2(a2, a2), b0); fma2(acc2[2][1], pack2(a2, a2), b1); fma2(acc2[2][2], pack2(a2, a2), b2);
            fma2(acc2[3][0], pack2(a3, a3), b0); fma2(acc2[3][1], pack2(a3, a3), b1); fma2(acc2[3][2], pack2(a3, a3), b2);
        }
        __syncthreads();
    }
    #pragma unroll
    for (int q = 0; q < 4; ++q)
        #pragma unroll
        for (int s = 0; s < 3; ++s) {
            float lo, hi;
            unpack2(acc2[q][s], lo, hi);
            __half2 hv = __floats2half2_rn(lo * A2SCALE, hi * A2SCALE);
            *(__half2*)&g_A2h[((size_t)b * CH + i0 + ty + 8*q) * CH + tx * 2 + s * 64] = hv;
        }
}

// ---------------- launch ----------------
extern "C" void kernel_launch(void* const* d_in, const int* in_sizes, int n_in,
                              void* d_out, int out_size) {
    const float* x_in   = (const float*)d_in[0];
    const float* w_split= (const float*)d_in[1];
    const float* w_q    = (const float*)d_in[2];
    const float* w_k    = (const float*)d_in[3];
    const float* w_v    = (const float*)d_in[4];
    const float* w_proj = (const float*)d_in[5];
    const float* b_proj = (const float*)d_in[6];
    const float* w_out  = (const float*)d_in[7];
    float* out = (float*)d_out;

    cudaFuncSetAttribute(xxt_mma, cudaFuncAttributeMaxDynamicSharedMemorySize, 49152);
    cudaFuncSetAttribute(out_mma, cudaFuncAttributeMaxDynamicSharedMemorySize, 101376);

    // S partials (upper band, fp16 single-term); also emits g_Xf
    xxt_mma<<<dim3(KSPLIT1, NB), 512, 49152>>>(x_in);

    // combined channel maps (+Wq'^T) + bias (one launch)
    prep_weights<<<dim3(6,6,5), 256>>>(w_q, w_k, w_v, w_out, w_split, w_proj, b_proj);

    // S = sum_p S_p with symmetrization
    s_reduce<<<dim3(6,6,NB), 256>>>();

    // P/K2 + fused diag norms (replaces t12_gemm + diag_norms)
    pk_gemm<<<dim3(6,2,NB), 256>>>();

    // G = K2·Wq'^T + softmax fused -> attn
    g_softmax<<<dim3(6,NB), 256>>>();

    // A2 = (Wp2·attn)·Wv', fp16
    a12_gemm<<<dim3(6,NB), 256>>>();

    // out = A2f Xf + bp2
    out_mma<<<dim3(HW/128, NB), 512, 101376>>>(out);
}

// round 17
// speedup vs baseline: 3.8701x; 1.0533x over previous
#include <cuda_runtime.h>
#include <cuda_fp16.h>
#include <cstdint>

#define CH 192
#define NB 8
#define HW 16384
#define KSPLIT1 16
#define EPSN 1e-12f
#define A2SCALE 4096.0f
#define A2INV   (1.0f/4096.0f)

// ---------------- mma.sync / ldmatrix helpers ----------------
__device__ __forceinline__ uint32_t smem_u32(const void* p) {
    uint32_t a;
    asm("{ .reg .u64 t; cvta.to.shared.u64 t, %1; cvt.u32.u64 %0, t; }" : "=r"(a) : "l"(p));
    return a;
}
__device__ __forceinline__ void hmma16(float* d, const uint32_t* a, const uint32_t* b) {
    asm volatile("mma.sync.aligned.m16n8k16.row.col.f32.f16.f16.f32 "
        "{%0,%1,%2,%3}, {%4,%5,%6,%7}, {%8,%9}, {%0,%1,%2,%3};"
        : "+f"(d[0]), "+f"(d[1]), "+f"(d[2]), "+f"(d[3])
        : "r"(a[0]), "r"(a[1]), "r"(a[2]), "r"(a[3]), "r"(b[0]), "r"(b[1]));
}
__device__ __forceinline__ void ldsm4(uint32_t* r, uint32_t a) {
    asm volatile("ldmatrix.sync.aligned.m8n8.x4.shared.b16 {%0,%1,%2,%3}, [%4];"
        : "=r"(r[0]), "=r"(r[1]), "=r"(r[2]), "=r"(r[3]) : "r"(a));
}
__device__ __forceinline__ void ldsm4t(uint32_t* r, uint32_t a) {
    asm volatile("ldmatrix.sync.aligned.m8n8.x4.trans.shared.b16 {%0,%1,%2,%3}, [%4];"
        : "=r"(r[0]), "=r"(r[1]), "=r"(r[2]), "=r"(r[3]) : "r"(a));
}
__device__ __forceinline__ uint32_t f2h2(float x, float y) {
    __half2 h = __floats2half2_rn(x, y);
    return *reinterpret_cast<uint32_t*>(&h);
}

// ---------------- packed f32x2 helpers ----------------
__device__ __forceinline__ unsigned long long pack2(float lo, float hi) {
    unsigned long long r;
    asm("mov.b64 %0, {%1, %2};" : "=l"(r) : "f"(lo), "f"(hi));
    return r;
}
__device__ __forceinline__ void unpack2(unsigned long long v, float& lo, float& hi) {
    asm("mov.b64 {%0, %1}, %2;" : "=f"(lo), "=f"(hi) : "l"(v));
}
__device__ __forceinline__ void fma2(unsigned long long& d, unsigned long long a, unsigned long long b) {
    asm("fma.rn.f32x2 %0, %1, %2, %0;" : "+l"(d) : "l"(a), "l"(b));
}

// ---------------- scratch ----------------
__device__ float g_Wq[CH*CH], g_WqT[CH*CH], g_Wk[CH*CH], g_Wv[CH*CH], g_Wp2[CH*CH], g_bp2[CH];
__device__ float g_Spart[NB*KSPLIT1*CH*CH];
__device__ float g_S[NB*CH*CH], g_K2[NB*CH*CH];
__device__ float g_attn[NB*CH*CH];
__device__ float g_nk2[NB*CH], g_nq2[NB*CH];
__device__ __half g_A2h[NB*CH*CH];
__device__ __half g_Xf[(size_t)NB*CH*HW];

// Upper-band 16x48 tiles
__constant__ int cTI[30] = {0,0,0,0, 1,1,1,1, 2,2,2,2, 3,3,3, 4,4,4, 5,5,5, 6,6, 7,7, 8,8, 9, 10, 11};
__constant__ int cTJ[30] = {0,1,2,3, 0,1,2,3, 0,1,2,3, 1,2,3, 1,2,3, 1,2,3, 2,3, 2,3, 2,3, 3, 3, 3};

// ============ GEMM1: S_p[b] = Xf Xf^T upper band only, split-K ============
__global__ __launch_bounds__(512) void xxt_mma(const float* __restrict__ xin) {
    extern __shared__ char smem[];
    const int tid = threadIdx.x, wid = tid >> 5, lane = tid & 31;
    const int split = blockIdx.x, b = blockIdx.y;
    const float* Xb = xin + (size_t)b * CH * HW;
    const int kbase = split * (HW / KSPLIT1);
    const uint32_t sb = smem_u32(smem);

    const int i0a = cTI[wid] * 16, j0a = cTJ[wid] * 48;
    const bool has2 = (wid < 14);
    const int i0b = has2 ? cTI[wid + 16] * 16 : 0;
    const int j0b = has2 ? cTJ[wid + 16] * 48 : 0;

    float dA[6][4], dB[6][4];
    #pragma unroll
    for (int j = 0; j < 6; ++j)
        #pragma unroll
        for (int q = 0; q < 4; ++q) { dA[j][q] = 0.f; dB[j][q] = 0.f; }

    auto ldx = [&](float4* v, int kb) {
        #pragma unroll
        for (int i = 0; i < 6; ++i) {
            int u = tid + (i << 9);
            int r = u >> 4, k4 = (u & 15) << 2;
            v[i] = *(const float4*)&Xb[(size_t)r * HW + kb + k4];
        }
    };
    auto stx = [&](const float4* v, int buf, int kb) {
        char* XF = smem + buf * 24576;
        #pragma unroll
        for (int i = 0; i < 6; ++i) {
            int u = tid + (i << 9);
            int r = u >> 4, k4 = (u & 15) << 2;
            uint2 hw = make_uint2(f2h2(v[i].x, v[i].y), f2h2(v[i].z, v[i].w));
            int sw = r * 128 + (((u & 15) << 3) ^ ((r & 7) << 4));
            *(uint2*)(XF + sw) = hw;
            *(uint2*)&g_Xf[((size_t)b * CH + r) * HW + kb + k4] = hw;
        }
    };

    const int xorv = (lane & 7) << 4;
    const int mat = lane >> 3;
    const int halfA = (lane >> 4) << 4;
    const int halfB = (mat & 1) << 4;
    const int rA15 = lane & 15;
    const int rB = ((mat >> 1) << 3) + (lane & 7);

    auto stage_compute = [&](int buf) {
        uint32_t base = sb + buf * 24576;
        #pragma unroll 1
        for (int kk = 0; kk < 4; ++kk) {
            int colA = ((kk << 5) + halfA) ^ xorv;
            int colB = ((kk << 5) + halfB) ^ xorv;
            uint32_t ah[4], bh[3][4];
            ldsm4(ah, base + (i0a + rA15) * 128 + colA);
            #pragma unroll
            for (int jj = 0; jj < 3; ++jj)
                ldsm4(bh[jj], base + (j0a + jj*16 + rB) * 128 + colB);
            #pragma unroll
            for (int jj = 0; jj < 3; ++jj) {
                hmma16(dA[2*jj],     ah, &bh[jj][0]);
                hmma16(dA[2*jj + 1], ah, &bh[jj][2]);
            }
            if (has2) {
                uint32_t ah2[4], bh2[3][4];
                ldsm4(ah2, base + (i0b + rA15) * 128 + colA);
                #pragma unroll
                for (int jj = 0; jj < 3; ++jj)
                    ldsm4(bh2[jj], base + (j0b + jj*16 + rB) * 128 + colB);
                #pragma unroll
                for (int jj = 0; jj < 3; ++jj) {
                    hmma16(dB[2*jj],     ah2, &bh2[jj][0]);
                    hmma16(dB[2*jj + 1], ah2, &bh2[jj][2]);
                }
            }
        }
    };

    {
        float4 v0[6];
        ldx(v0, kbase);
        stx(v0, 0, kbase);
    }
    __syncthreads();
    for (int c = 0; c < 16; ++c) {
        float4 vn[6];
        if (c < 15) ldx(vn, kbase + (c + 1) * 64);
        stage_compute(c & 1);
        if (c < 15) stx(vn, (c + 1) & 1, kbase + (c + 1) * 64);
        __syncthreads();
    }

    float* Sp = g_Spart + (size_t)(b * KSPLIT1 + split) * CH * CH;
    int lr = lane >> 2, lc2 = (lane & 3) * 2;
    #pragma unroll
    for (int nj = 0; nj < 6; ++nj) {
        int r = i0a + lr, cc = j0a + 8*nj + lc2;
        *(float2*)&Sp[r * CH + cc]       = make_float2(dA[nj][0], dA[nj][1]);
        *(float2*)&Sp[(r + 8) * CH + cc] = make_float2(dA[nj][2], dA[nj][3]);
    }
    if (has2) {
        #pragma unroll
        for (int nj = 0; nj < 6; ++nj) {
            int r = i0b + lr, cc = j0b + 8*nj + lc2;
            *(float2*)&Sp[r * CH + cc]       = make_float2(dB[nj][0], dB[nj][1]);
            *(float2*)&Sp[(r + 8) * CH + cc] = make_float2(dB[nj][2], dB[nj][3]);
        }
    }
}

__device__ __forceinline__ bool s_cov(int r, int c) {
    return (48 * (c / 48) + 47) >= (16 * (r / 16));
}

// S = sum_p S_p with symmetrization. grid (6,6,NB), 256 thr.
__global__ __launch_bounds__(256) void s_reduce() {
    __shared__ float tb[32][33];
    const int b = blockIdx.z, I0 = blockIdx.x * 32, J0 = blockIdx.y * 32;
    const int c = threadIdx.x & 31, ty = threadIdx.x >> 5;
    const float* Sp = g_Spart + (size_t)b * KSPLIT1 * CH * CH;

    const int ibmin = I0 >> 4, ibmax = (I0 + 31) >> 4;
    const int jbmin = J0 / 48, jbmax = (J0 + 31) / 48;
    const bool fullCov = (48 * jbmin + 47) >= (16 * ibmax);
    const bool fullUnc = (48 * jbmax + 47) < (16 * ibmin);

    float dsum[4];
    if (!fullUnc) {
        #pragma unroll
        for (int q = 0; q < 4; ++q) {
            int r = I0 + ty + 8*q;
            float s = 0.f;
            #pragma unroll
            for (int p = 0; p < KSPLIT1; ++p)
                s += Sp[(size_t)p*CH*CH + r*CH + J0 + c];
            dsum[q] = s;
        }
    }
    if (!fullCov) {
        #pragma unroll
        for (int q = 0; q < 4; ++q) {
            int rr = J0 + ty + 8*q;
            float s = 0.f;
            #pragma unroll
            for (int p = 0; p < KSPLIT1; ++p)
                s += Sp[(size_t)p*CH*CH + rr*CH + I0 + c];
            tb[ty + 8*q][c] = s;
        }
        __syncthreads();
    }
    float* Sb = g_S + (size_t)b * CH * CH;
    #pragma unroll
    for (int q = 0; q < 4; ++q) {
        int r = I0 + ty + 8*q, cc = J0 + c;
        float v;
        if (fullCov)      v = dsum[q];
        else if (fullUnc) v = tb[c][ty + 8*q];
        else              v = s_cov(r, cc) ? dsum[q] : tb[c][ty + 8*q];
        Sb[r * CH + cc] = v;
    }
}

// ============ GEMM2: out[b] = A2f·Xf * A2INV + bp2 ============
__global__ __launch_bounds__(512) void out_mma(float* __restrict__ out) {
    extern __shared__ char smem[];
    const int tid = threadIdx.x, wid = tid >> 5, lane = tid & 31;
    const int p0 = blockIdx.x * 128, b = blockIdx.y;
    const uint32_t sb = smem_u32(smem);
    const int m0 = (wid >> 2) * 48, n0p = (wid & 3) * 32;

    float d[3][4][4];
    #pragma unroll
    for (int i = 0; i < 3; ++i)
        #pragma unroll
        for (int j = 0; j < 4; ++j)
            #pragma unroll
            for (int q = 0; q < 4; ++q) d[i][j][q] = 0.f;

    auto ldstage = [&](uint4* va, uint4* vx, int c0) {
        #pragma unroll
        for (int i = 0; i < 3; ++i) {
            int u = tid + (i << 9);
            int r = u >> 3, sg = u & 7;
            va[i] = *(const uint4*)&g_A2h[((size_t)b * CH + r) * CH + c0 + sg * 8];
        }
        #pragma unroll
        for (int i = 0; i < 2; ++i) {
            int u = tid + (i << 9);
            int r = u >> 4, c8 = (u & 15) << 3;
            vx[i] = *(const uint4*)&g_Xf[((size_t)b * CH + c0 + r) * HW + p0 + c8];
        }
    };
    auto ststage = [&](const uint4* va, const uint4* vx, int buf) {
        char* A2F = smem + buf * 40960;
        char* XF  = A2F + 24576;
        #pragma unroll
        for (int i = 0; i < 3; ++i) {
            int u = tid + (i << 9);
            int r = u >> 3, sg = u & 7;
            int sw = r * 128 + ((sg << 4) ^ ((r & 7) << 4));
            *(uint4*)(A2F + sw) = va[i];
        }
        #pragma unroll
        for (int i = 0; i < 2; ++i) {
            int u = tid + (i << 9);
            int r = u >> 4;
            int sw = r * 256 + ((((u & 15)) << 4) ^ ((r & 7) << 4));
            *(uint4*)(XF + sw) = vx[i];
        }
    };

    const int xorv = (lane & 7) << 4;
    const int mat = lane >> 3;
    const int halfA = (lane >> 4) << 4;
    const int rA15 = lane & 15;
    const int rbX = ((mat & 1) << 3) + (lane & 7);
    const int cbX = (n0p + ((mat >> 1) << 3)) * 2;

    auto stage_compute = [&](int buf) {
        uint32_t baseAF = sb + buf * 40960;
        uint32_t baseXF = baseAF + 24576;
        #pragma unroll 1
        for (int kk = 0; kk < 4; ++kk) {
            int colA = ((kk << 5) + halfA) ^ xorv;
            int xrow = (kk * 16 + rbX) * 256;
            uint32_t ah[3][4], bt[2][4];
            #pragma unroll
            for (int mi = 0; mi < 3; ++mi)
                ldsm4(ah[mi], baseAF + (m0 + 16*mi + rA15) * 128 + colA);
            #pragma unroll
            for (int jj = 0; jj < 2; ++jj)
                ldsm4t(bt[jj], baseXF + xrow + ((cbX + jj*32) ^ xorv));
            #pragma unroll
            for (int mi = 0; mi < 3; ++mi)
                #pragma unroll
                for (int jj = 0; jj < 2; ++jj) {
                    hmma16(d[mi][2*jj],     ah[mi], &bt[jj][0]);
                    hmma16(d[mi][2*jj + 1], ah[mi], &bt[jj][2]);
                }
        }
    };

    {
        uint4 va0[3], vx0[2];
        ldstage(va0, vx0, 0);
        ststage(va0, vx0, 0);
    }
    __syncthreads();
    for (int c = 0; c < 3; ++c) {
        uint4 va[3], vx[2];
        if (c < 2) ldstage(va, vx, (c + 1) * 64);
        stage_compute(c & 1);
        if (c < 2) ststage(va, vx, (c + 1) & 1);
        __syncthreads();
    }

    float* so = (float*)smem;
    int lr = lane >> 2, lc2 = (lane & 3) * 2;
    #pragma unroll
    for (int mi = 0; mi < 3; ++mi)
        #pragma unroll
        for (int nj = 0; nj < 4; ++nj) {
            int r = m0 + 16*mi + lr, cc = n0p + 8*nj + lc2;
            *(float2*)&so[r * 132 + cc]       = make_float2(d[mi][nj][0], d[mi][nj][1]);
            *(float2*)&so[(r + 8) * 132 + cc] = make_float2(d[mi][nj][2], d[mi][nj][3]);
        }
    __syncthreads();
    #pragma unroll
    for (int u = tid; u < 6144; u += 512) {
        int co = u >> 5, p4 = (u & 31) << 2;
        float4 v = *(const float4*)&so[co * 132 + p4];
        float bias = g_bp2[co];
        v.x = v.x * A2INV + bias;
        v.y = v.y * A2INV + bias;
        v.z = v.z * A2INV + bias;
        v.w = v.w * A2INV + bias;
        *(float4*)&out[((size_t)b * CH + co) * HW + p0 + p4] = v;
    }
}

// ---------------- small 192x192 GEMM core (optionally also writes C^T) ----------------
__device__ __forceinline__ void gemm_tile32(const float* __restrict__ Ab,
                                            const float* __restrict__ Bb,
                                            float* __restrict__ Cb,
                                            float* __restrict__ CbT,
                                            int i0, int j0) {
    __shared__ float As[16][34], Bs[16][34];
    int t = threadIdx.x;
    int tx = t & 15, ty = t >> 4;
    int li = t & 31, lkq = t >> 5;
    int lkb = t >> 4, lj2 = (t & 15) * 2;

    unsigned long long acc0 = 0ull, acc1 = 0ull;

    for (int kk = 0; kk < CH; kk += 16) {
        float2 av = *(const float2*)&Ab[(i0 + li) * CH + kk + lkq * 2];
        float2 bv = *(const float2*)&Bb[(kk + lkb) * CH + j0 + lj2];
        __syncthreads();
        As[lkq*2 + 0][li] = av.x;
        As[lkq*2 + 1][li] = av.y;
        *(float2*)&Bs[lkb][lj2] = bv;
        __syncthreads();
        #pragma unroll
        for (int k = 0; k < 16; ++k) {
            float2 a2 = *(const float2*)&As[k][ty * 2];
            unsigned long long b2 = *(const unsigned long long*)&Bs[k][tx * 2];
            fma2(acc0, pack2(a2.x, a2.x), b2);
            fma2(acc1, pack2(a2.y, a2.y), b2);
        }
    }
    float o00, o01, o10, o11;
    unpack2(acc0, o00, o01);
    unpack2(acc1, o10, o11);
    *(float2*)&Cb[(i0 + ty*2 + 0) * CH + j0 + tx*2] = make_float2(o00, o01);
    *(float2*)&Cb[(i0 + ty*2 + 1) * CH + j0 + tx*2] = make_float2(o10, o11);
    if (CbT) {
        *(float2*)&CbT[(j0 + tx*2 + 0) * CH + i0 + ty*2] = make_float2(o00, o10);
        *(float2*)&CbT[(j0 + tx*2 + 1) * CH + i0 + ty*2] = make_float2(o01, o11);
    }
}

// z=0..3: weight-combine GEMMs (z=0 also emits Wq'^T); z=4 block(0,0): bp2
__global__ __launch_bounds__(256) void prep_weights(const float* __restrict__ wq,
                                                    const float* __restrict__ wk,
                                                    const float* __restrict__ wv,
                                                    const float* __restrict__ wout,
                                                    const float* __restrict__ wsplit,
                                                    const float* __restrict__ wproj,
                                                    const float* __restrict__ bproj) {
    if (blockIdx.z == 4) {
        if (blockIdx.x == 0 && blockIdx.y == 0) {
            int f = threadIdx.x;
            if (f < CH) {
                float s = 0.f;
                for (int o = 0; o < CH; ++o) s += wout[f*CH+o] * bproj[o];
                g_bp2[f] = s;
            }
        }
        return;
    }
    const float *A, *B; float *C, *CT = nullptr;
    switch (blockIdx.z) {
        case 0:  A = wq;   B = wsplit; C = g_Wq;  CT = g_WqT; break;
        case 1:  A = wk;   B = wsplit; C = g_Wk;  break;
        case 2:  A = wv;   B = wsplit; C = g_Wv;  break;
        default: A = wout; B = wproj;  C = g_Wp2; break;
    }
    gemm_tile32(A, B, C, CT, blockIdx.x * 32, blockIdx.y * 32);
}

// ============ Row-tile GEMM helpers: A fully resident, B double-buffered ============
// smem layout (floats): Af[192*33] | Bs0[16*196] | Bs1[16*196] | (extra)
#define AF_SZ  (192*33)
#define BS_SZ  (16*196)

// Load one 16x192 B tile (rows kk..kk+15 of Bsrc) into registers
__device__ __forceinline__ void ldB(float4* v, const float* __restrict__ Bsrc, int kk, int tid) {
    #pragma unroll
    for (int s = 0; s < 3; ++s) {
        int lin = s * 256 + tid;
        int kr = lin / 48, c4 = (lin % 48) * 4;
        v[s] = *(const float4*)&Bsrc[(kk + kr) * CH + c4];
    }
}
__device__ __forceinline__ void stB(const float4* v, float* Bsm, int tid) {
    #pragma unroll
    for (int s = 0; s < 3; ++s) {
        int lin = s * 256 + tid;
        int kr = lin / 48, c4 = (lin % 48) * 4;
        *(float4*)&Bsm[kr * 196 + c4] = v[s];
    }
}
// Preload A row-block [32 x 192] into Af as [k][row] (pad 33)
__device__ __forceinline__ void ldA(float* Af, const float* __restrict__ Asrc, int i0, int tid) {
    #pragma unroll
    for (int i = 0; i < 12; ++i) {
        int lin = i * 256 + tid;               // 3072 float2 units
        int r = lin / 96, k2 = (lin % 96) * 2;
        float2 w = *(const float2*)&Asrc[(i0 + r) * CH + k2];
        Af[k2 * 33 + r]       = w.x;
        Af[(k2 + 1) * 33 + r] = w.y;
    }
}
// Mainloop: acc[4][3] += Af-rowblock · Bsrc  (one barrier/iter, B prefetched)
__device__ __forceinline__ void rowtile_loop(unsigned long long acc[4][3],
                                             const float* Af, float* Bs0, float* Bs1,
                                             const float* __restrict__ Bsrc,
                                             int tid, int tx, int ty) {
    {
        float4 v0[3];
        ldB(v0, Bsrc, 0, tid);
        stB(v0, Bs0, tid);
    }
    __syncthreads();
    for (int c = 0; c < 12; ++c) {
        float4 vn[3];
        if (c < 11) ldB(vn, Bsrc, (c + 1) * 16, tid);
        const float* B = (c & 1) ? Bs1 : Bs0;
        const int kk = c * 16;
        #pragma unroll
        for (int k = 0; k < 16; ++k) {
            const float* ar = &Af[(kk + k) * 33];
            float a0 = ar[ty], a1 = ar[ty + 8], a2 = ar[ty + 16], a3 = ar[ty + 24];
            unsigned long long b0 = *(const unsigned long long*)&B[k * 196 + tx * 2];
            unsigned long long b1 = *(const unsigned long long*)&B[k * 196 + tx * 2 + 64];
            unsigned long long b2 = *(const unsigned long long*)&B[k * 196 + tx * 2 + 128];
            fma2(acc[0][0], pack2(a0, a0), b0); fma2(acc[0][1], pack2(a0, a0), b1); fma2(acc[0][2], pack2(a0, a0), b2);
            fma2(acc[1][0], pack2(a1, a1), b0); fma2(acc[1][1], pack2(a1, a1), b1); fma2(acc[1][2], pack2(a1, a1), b2);
            fma2(acc[2][0], pack2(a2, a2), b0); fma2(acc[2][1], pack2(a2, a2), b1); fma2(acc[2][2], pack2(a2, a2), b2);
            fma2(acc[3][0], pack2(a3, a3), b0); fma2(acc[3][1], pack2(a3, a3), b1); fma2(acc[3][2], pack2(a3, a3), b2);
        }
        if (c < 11) stB(vn, (c & 1) ? Bs0 : Bs1, tid);
        __syncthreads();
    }
}

// ============ pk_gemm: P=Wq'·S (nq2 only) / K2=Wk'·S (stored + nk2) ============
// grid (6, 2, NB), 256 thr, dyn smem (AF_SZ + 2*BS_SZ)*4
__global__ __launch_bounds__(256) void pk_gemm() {
    extern __shared__ float sm[];
    float* Af = sm;
    float* Bs0 = sm + AF_SZ;
    float* Bs1 = Bs0 + BS_SZ;
    const int i0 = blockIdx.x * 32, which = blockIdx.y, b = blockIdx.z;
    const float* W = which ? g_Wk : g_Wq;
    const float* Sb = g_S + (size_t)b * CH * CH;
    const int tid = threadIdx.x, tx = tid & 31, ty = tid >> 5;

    unsigned long long acc[4][3];
    #pragma unroll
    for (int q = 0; q < 4; ++q)
        #pragma unroll
        for (int s = 0; s < 3; ++s) acc[q][s] = 0ull;

    ldA(Af, W, i0, tid);
    rowtile_loop(acc, Af, Bs0, Bs1, Sb, tid, tx, ty);

    // epilogue: optional K2 store + diag norm dot(row, W[row])
    float part[4] = {0.f, 0.f, 0.f, 0.f};
    #pragma unroll
    for (int q = 0; q < 4; ++q) {
        int row = i0 + ty + 8*q;
        #pragma unroll
        for (int s = 0; s < 3; ++s) {
            float lo, hi;
            unpack2(acc[q][s], lo, hi);
            int col = tx * 2 + s * 64;
            if (which)
                *(float2*)&g_K2[((size_t)b * CH + row) * CH + col] = make_float2(lo, hi);
            float2 wv = *(const float2*)&W[row * CH + col];
            part[q] += lo * wv.x + hi * wv.y;
        }
    }
    #pragma unroll
    for (int q = 0; q < 4; ++q) {
        #pragma unroll
        for (int o = 16; o > 0; o >>= 1)
            part[q] += __shfl_xor_sync(0xffffffffu, part[q], o);
        if (tx == 0)
            (which ? g_nk2 : g_nq2)[b * CH + i0 + ty + 8*q] = part[q];
    }
}

// ============ Fused: G = K2·Wq'^T (32x192 rows) + softmax -> attn. grid (6, NB) ============
// dyn smem (AF_SZ + 2*BS_SZ + 192)*4 ; Gs aliases Bs0/Bs1 region after mainloop
__global__ __launch_bounds__(256) void g_softmax() {
    extern __shared__ float sm[];
    float* Af = sm;
    float* Bs0 = sm + AF_SZ;
    float* Bs1 = Bs0 + BS_SZ;
    float* sdq = Bs1 + BS_SZ;
    float* Gs = Bs0;                    // 32*196 = 2*BS_SZ exactly
    const int b = blockIdx.y, i0 = blockIdx.x * 32;
    const int tid = threadIdx.x, tx = tid & 31, ty = tid >> 5;
    const float* K2b = g_K2 + (size_t)b * CH * CH;

    unsigned long long acc[4][3];
    #pragma unroll
    for (int q = 0; q < 4; ++q)
        #pragma unroll
        for (int s = 0; s < 3; ++s) acc[q][s] = 0ull;

    ldA(Af, K2b, i0, tid);
    rowtile_loop(acc, Af, Bs0, Bs1, g_WqT, tid, tx, ty);

    #pragma unroll
    for (int q = 0; q < 4; ++q)
        #pragma unroll
        for (int s = 0; s < 3; ++s) {
            float lo, hi;
            unpack2(acc[q][s], lo, hi);
            Gs[(ty + 8*q) * 196 + tx * 2 + s * 64]     = lo;
            Gs[(ty + 8*q) * 196 + tx * 2 + s * 64 + 1] = hi;
        }
    if (tid < CH) sdq[tid] = fmaxf(sqrtf(g_nq2[b * CH + tid]), EPSN);
    __syncthreads();

    const int w = tid >> 5, lane = tid & 31;
    #pragma unroll
    for (int rr = 0; rr < 4; ++rr) {
        int row = w * 4 + rr;
        float dk = fmaxf(sqrtf(g_nk2[b * CH + i0 + row]), EPSN);
        float L[6];
        #pragma unroll
        for (int t = 0; t < 6; ++t)
            L[t] = Gs[row * 196 + lane + 32 * t] / (dk * sdq[lane + 32 * t]);
        float m = L[0];
        #pragma unroll
        for (int t = 1; t < 6; ++t) m = fmaxf(m, L[t]);
        #pragma unroll
        for (int o = 16; o > 0; o >>= 1) m = fmaxf(m, __shfl_xor_sync(0xffffffffu, m, o));
        float e[6], sum = 0.f;
        #pragma unroll
        for (int t = 0; t < 6; ++t) { e[t] = expf(L[t] - m); sum += e[t]; }
        #pragma unroll
        for (int o = 16; o > 0; o >>= 1) sum += __shfl_xor_sync(0xffffffffu, sum, o);
        float inv = 1.f / sum;
        #pragma unroll
        for (int t = 0; t < 6; ++t)
            g_attn[((size_t)b * CH + i0 + row) * CH + lane + 32 * t] = e[t] * inv;
    }
}

// ============ Fused: A2 = (Wp2·attn)·Wv', scaled fp16 out. grid (6, NB) ============
// dyn smem (AF_SZ + 2*BS_SZ)*4; phase-1 result (A1^T) written into Af for phase 2
__global__ __launch_bounds__(256) void a12_gemm() {
    extern __shared__ float sm[];
    float* Af = sm;
    float* Bs0 = sm + AF_SZ;
    float* Bs1 = Bs0 + BS_SZ;
    const int b = blockIdx.y, i0 = blockIdx.x * 32;
    const int tid = threadIdx.x, tx = tid & 31, ty = tid >> 5;
    const float* attnb = g_attn + (size_t)b * CH * CH;

    unsigned long long acc[4][3];
    #pragma unroll
    for (int q = 0; q < 4; ++q)
        #pragma unroll
        for (int s = 0; s < 3; ++s) acc[q][s] = 0ull;

    // Phase 1: A1blk = Wp2[i0..i0+31, :] · attn_b
    ldA(Af, g_Wp2, i0, tid);
    rowtile_loop(acc, Af, Bs0, Bs1, attnb, tid, tx, ty);

    // write A1^T into Af ([k=col][row] layout, same as ldA produces)
    #pragma unroll
    for (int q = 0; q < 4; ++q)
        #pragma unroll
        for (int s = 0; s < 3; ++s) {
            float lo, hi;
            unpack2(acc[q][s], lo, hi);
            int col = tx * 2 + s * 64;
            Af[col * 33 + ty + 8*q]       = lo;
            Af[(col + 1) * 33 + ty + 8*q] = hi;
        }
    __syncthreads();

    // Phase 2: A2blk = A1blk · Wv'
    unsigned long long acc2[4][3];
    #pragma unroll
    for (int q = 0; q < 4; ++q)
        #pragma unroll
        for (int s = 0; s < 3; ++s) acc2[q][s] = 0ull;

    rowtile_loop(acc2, Af, Bs0, Bs1, g_Wv, tid, tx, ty);

    #pragma unroll
    for (int q = 0; q < 4; ++q)
        #pragma unroll
        for (int s = 0; s < 3; ++s) {
            float lo, hi;
            unpack2(acc2[q][s], lo, hi);
            __half2 hv = __floats2half2_rn(lo * A2SCALE, hi * A2SCALE);
            *(__half2*)&g_A2h[((size_t)b * CH + i0 + ty + 8*q) * CH + tx * 2 + s * 64] = hv;
        }
}

// ---------------- launch ----------------
extern "C" void kernel_launch(void* const* d_in, const int* in_sizes, int n_in,
                              void* d_out, int out_size) {
    const float* x_in   = (const float*)d_in[0];
    const float* w_split= (const float*)d_in[1];
    const float* w_q    = (const float*)d_in[2];
    const float* w_k    = (const float*)d_in[3];
    const float* w_v    = (const float*)d_in[4];
    const float* w_proj = (const float*)d_in[5];
    const float* b_proj = (const float*)d_in[6];
    const float* w_out  = (const float*)d_in[7];
    float* out = (float*)d_out;

    const int smA = (AF_SZ + 2 * BS_SZ) * 4;        // 50432
    const int smG = (AF_SZ + 2 * BS_SZ + 192) * 4;  // 51200

    cudaFuncSetAttribute(xxt_mma, cudaFuncAttributeMaxDynamicSharedMemorySize, 49152);
    cudaFuncSetAttribute(out_mma, cudaFuncAttributeMaxDynamicSharedMemorySize, 101376);
    cudaFuncSetAttribute(pk_gemm, cudaFuncAttributeMaxDynamicSharedMemorySize, smA);
    cudaFuncSetAttribute(g_softmax, cudaFuncAttributeMaxDynamicSharedMemorySize, smG);
    cudaFuncSetAttribute(a12_gemm, cudaFuncAttributeMaxDynamicSharedMemorySize, smA);

    // S partials (upper band, fp16 single-term); also emits g_Xf
    xxt_mma<<<dim3(KSPLIT1, NB), 512, 49152>>>(x_in);

    // combined channel maps (+Wq'^T) + bias (one launch)
    prep_weights<<<dim3(6,6,5), 256>>>(w_q, w_k, w_v, w_out, w_split, w_proj, b_proj);

    // S = sum_p S_p with symmetrization
    s_reduce<<<dim3(6,6,NB), 256>>>();

    // P/K2 + fused diag norms
    pk_gemm<<<dim3(6,2,NB), 256, smA>>>();

    // G = K2·Wq'^T + softmax fused -> attn
    g_softmax<<<dim3(6,NB), 256, smG>>>();

    // A2 = (Wp2·attn)·Wv', fp16
    a12_gemm<<<dim3(6,NB), 256, smA>>>();

    // out = A2f Xf + bp2
    out_mma<<<dim3(HW/128, NB), 512, 101376>>>(out);
}